// round 9
// baseline (speedup 1.0000x reference)
#include <cuda_runtime.h>
#include <math.h>

// Net_ASAP fused pipeline, round 9.
// - 256 threads/CTA, 2 CTAs/SM (smem ~107KB).
// - Weight GEMMs: cp.async panel-staged smem W (16k x 128 panels, double
//   buffered), both conv matrices accumulated into one register tile.
// - Bitmask adjacency; in-place A; warp-parallel small stages (as round 7).

#define THREADS 256
#define G_TOT 512
#define SLOPE 0.2f
#define LDA 132
#define LDS_ 68
#define LDP 17

typedef unsigned long long u64;

__device__ float g_WT[12 * 128 * 128];   // pre-transposed weights W^T[k][h]

__device__ __forceinline__ u64 bcast2(float v) {
  unsigned r = __float_as_uint(v);
  u64 d; asm("mov.b64 %0, {%1, %1};" : "=l"(d) : "r"(r));
  return d;
}
__device__ __forceinline__ u64 ffma2(u64 a, u64 b, u64 c) {
  u64 d; asm("fma.rn.f32x2 %0, %1, %2, %3;" : "=l"(d) : "l"(a), "l"(b), "l"(c));
  return d;
}
__device__ __forceinline__ u64 fadd2(u64 a, u64 b) {
  u64 d; asm("add.rn.f32x2 %0, %1, %2;" : "=l"(d) : "l"(a), "l"(b));
  return d;
}
__device__ __forceinline__ u64 fmul2(u64 a, u64 b) {
  u64 d; asm("mul.rn.f32x2 %0, %1, %2;" : "=l"(d) : "l"(a), "l"(b));
  return d;
}

union V4 { float4 f; u64 p[2]; float s[4]; };

struct Smem {
  float A[64 * LDA];        // features (in-place)
  float B[64 * LDA];        // agg / xq / xc scratch
  float Wpan[2 * 16 * 128]; // double-buffered weight panels (16k x 128)
  float S[64 * LDS_];       // attention matrix
  u64   masks[64];          // binary adjacency, N=64 phase
  float adjP[16 * LDP];     // pooled float adjacency, N<=16
  float part[256];
  float degw[64], s1[64], s2[64], fit[64];
  float av[64], bv[64], cv[64], vals[64];
  int   perm[64];
  float xsum[640];
  float zz[128], yy[16], lse;
};

// ---------------------------------------------------------------------------
// cp.async panel machinery: one 8KB panel (16 k-rows x 128 cols), 32B/thread
// ---------------------------------------------------------------------------
__device__ __forceinline__ void panel_load(float* dst, const float* src, int tid) {
  unsigned sa = (unsigned)__cvta_generic_to_shared(dst) + tid * 32;
  const char* g = (const char*)src + tid * 32;
  asm volatile("cp.async.cg.shared.global [%0], [%1], 16;" :: "r"(sa), "l"(g));
  asm volatile("cp.async.cg.shared.global [%0], [%1], 16;" :: "r"(sa + 16), "l"(g + 16));
  asm volatile("cp.async.commit_group;");
}

// ---------------------------------------------------------------------------
// Panel-staged GEMM: acc[r][0..3] += L[(i0+r)][k] * W[k][c0..c0+7], K=128.
// W streamed from global into smem panels; all threads load, `active` compute.
// Ends with __syncthreads() (safe to write L/base buffers after return).
// ---------------------------------------------------------------------------
template<int RPT>
__device__ void gemm_panels(u64 (&acc)[RPT][4],
    const float* __restrict__ L, const float* __restrict__ Wg,
    float* Wpan, int i0, int c0, bool active, int tid)
{
  panel_load(Wpan, Wg, tid);                 // panel 0 -> buf 0
  const float* Lbase = L + i0 * LDA;
#pragma unroll 1
  for (int p = 0; p < 8; p++) {
    if (p + 1 < 8) {
      panel_load(Wpan + ((p + 1) & 1) * 2048, Wg + (p + 1) * 2048, tid);
      asm volatile("cp.async.wait_group 1;" ::: "memory");
    } else {
      asm volatile("cp.async.wait_group 0;" ::: "memory");
    }
    __syncthreads();
    if (active) {
      const float* Wp = Wpan + (p & 1) * 2048 + c0;
      const float* Lk = Lbase + p * 16;
#pragma unroll
      for (int kq = 0; kq < 4; kq++) {
        V4 lv[RPT];
#pragma unroll
        for (int r = 0; r < RPT; r++)
          lv[r].f = *reinterpret_cast<const float4*>(Lk + r * LDA + kq * 4);
#pragma unroll
        for (int q = 0; q < 4; q++) {
          V4 wa, wb;
          wa.f = *reinterpret_cast<const float4*>(Wp + (kq * 4 + q) * 128);
          wb.f = *reinterpret_cast<const float4*>(Wp + (kq * 4 + q) * 128 + 4);
#pragma unroll
          for (int r = 0; r < RPT; r++) {
            u64 lp_ = bcast2(lv[r].s[q]);
            acc[r][0] = ffma2(lp_, wa.p[0], acc[r][0]);
            acc[r][1] = ffma2(lp_, wa.p[1], acc[r][1]);
            acc[r][2] = ffma2(lp_, wb.p[0], acc[r][2]);
            acc[r][3] = ffma2(lp_, wb.p[1], acc[r][3]);
          }
        }
      }
    }
    __syncthreads();
  }
}

template<int RPT, bool RELU>
__device__ __forceinline__ void epi_store(const u64 (&acc)[RPT][4],
    float* __restrict__ O, int i0, int c0, const float* __restrict__ bias)
{
  float4 b1 = *reinterpret_cast<const float4*>(bias + c0);
  float4 b2 = *reinterpret_cast<const float4*>(bias + c0 + 4);
#pragma unroll
  for (int r = 0; r < RPT; r++) {
    V4 a, b;
    a.p[0] = acc[r][0]; a.p[1] = acc[r][1];
    b.p[0] = acc[r][2]; b.p[1] = acc[r][3];
    a.f.x += b1.x; a.f.y += b1.y; a.f.z += b1.z; a.f.w += b1.w;
    b.f.x += b2.x; b.f.y += b2.y; b.f.z += b2.z; b.f.w += b2.w;
    if (RELU) {
      a.f.x = fmaxf(a.f.x, 0.f); a.f.y = fmaxf(a.f.y, 0.f);
      a.f.z = fmaxf(a.f.z, 0.f); a.f.w = fmaxf(a.f.w, 0.f);
      b.f.x = fmaxf(b.f.x, 0.f); b.f.y = fmaxf(b.f.y, 0.f);
      b.f.z = fmaxf(b.f.z, 0.f); b.f.w = fmaxf(b.f.w, 0.f);
    }
    *reinterpret_cast<float4*>(O + (i0 + r) * LDA + c0)     = a.f;
    *reinterpret_cast<float4*>(O + (i0 + r) * LDA + c0 + 4) = b.f;
  }
}

__device__ __forceinline__ float warp_red_sum(float v) {
#pragma unroll
  for (int o = 16; o; o >>= 1) v += __shfl_xor_sync(0xffffffffu, v, o);
  return v;
}

// ---------------------------------------------------------------------------
// conv, N=64: A = relu( (adj@A)/cnt @ Wr + A@Wroot + br )
// ---------------------------------------------------------------------------
__device__ void conv64(Smem* s, const float* __restrict__ wr_t,
    const float* __restrict__ wroot_t, const float* __restrict__ br)
{
  const int tid = threadIdx.x;
  // agg = (masks @ A)/cnt -> B : 4 rows x 8 cols per thread (bit iteration)
  {
    const int i0 = (tid >> 4) * 4, c0 = (tid & 15) * 4;
    u64 m0 = s->masks[i0], m1 = s->masks[i0+1], m2 = s->masks[i0+2], m3 = s->masks[i0+3];
    u64 a[4][4];
#pragma unroll
    for (int r = 0; r < 4; r++)
#pragma unroll
      for (int j = 0; j < 4; j++) a[r][j] = 0ull;
    u64 mm = m0 | m1 | m2 | m3;
    const float* Ap = s->A + c0;
    while (mm) {
      int j = __ffsll((long long)mm) - 1;
      mm &= mm - 1;
      V4 ra, rb;
      ra.f = *reinterpret_cast<const float4*>(Ap + j * LDA);
      rb.f = *reinterpret_cast<const float4*>(Ap + j * LDA + 64);
      if ((m0 >> j) & 1) { a[0][0]=fadd2(a[0][0],ra.p[0]); a[0][1]=fadd2(a[0][1],ra.p[1]);
                           a[0][2]=fadd2(a[0][2],rb.p[0]); a[0][3]=fadd2(a[0][3],rb.p[1]); }
      if ((m1 >> j) & 1) { a[1][0]=fadd2(a[1][0],ra.p[0]); a[1][1]=fadd2(a[1][1],ra.p[1]);
                           a[1][2]=fadd2(a[1][2],rb.p[0]); a[1][3]=fadd2(a[1][3],rb.p[1]); }
      if ((m2 >> j) & 1) { a[2][0]=fadd2(a[2][0],ra.p[0]); a[2][1]=fadd2(a[2][1],ra.p[1]);
                           a[2][2]=fadd2(a[2][2],rb.p[0]); a[2][3]=fadd2(a[2][3],rb.p[1]); }
      if ((m3 >> j) & 1) { a[3][0]=fadd2(a[3][0],ra.p[0]); a[3][1]=fadd2(a[3][1],ra.p[1]);
                           a[3][2]=fadd2(a[3][2],rb.p[0]); a[3][3]=fadd2(a[3][3],rb.p[1]); }
    }
    u64 msk[4] = {m0, m1, m2, m3};
#pragma unroll
    for (int r = 0; r < 4; r++) {
      u64 rc = bcast2(1.f / fmaxf((float)__popcll(msk[r]), 1.f));
      V4 o;
      o.p[0] = fmul2(a[r][0], rc); o.p[1] = fmul2(a[r][1], rc);
      *reinterpret_cast<float4*>(s->B + (i0 + r) * LDA + c0) = o.f;
      o.p[0] = fmul2(a[r][2], rc); o.p[1] = fmul2(a[r][3], rc);
      *reinterpret_cast<float4*>(s->B + (i0 + r) * LDA + c0 + 64) = o.f;
    }
  }
  __syncthreads();

  // acc = agg@Wr + X@Wroot (4x8 tiles, panel-staged)
  const int i0 = (tid >> 4) * 4, c0 = (tid & 15) * 8;
  u64 acc[4][4];
#pragma unroll
  for (int r = 0; r < 4; r++)
#pragma unroll
    for (int j = 0; j < 4; j++) acc[r][j] = 0ull;
  gemm_panels<4>(acc, s->B, wr_t,    s->Wpan, i0, c0, true, tid);
  gemm_panels<4>(acc, s->A, wroot_t, s->Wpan, i0, c0, true, tid);
  epi_store<4, true>(acc, s->A, i0, c0, br);
  __syncthreads();
}

// ---------------------------------------------------------------------------
// conv, N<=16 (float adjP)
// ---------------------------------------------------------------------------
template<int NI>
__device__ void conv_small(Smem* s, const float* __restrict__ wr_t,
    const float* __restrict__ wroot_t, const float* __restrict__ br)
{
  const int tid = threadIdx.x;
  if (tid < NI * 16) {
    int row = tid >> 4, c0 = (tid & 15) * 4;
    float a[8] = {0,0,0,0,0,0,0,0};
    int cnt = 0;
    for (int j = 0; j < NI; j++) {
      float v = s->adjP[row * LDP + j];
      if (v != 0.f) {
        cnt++;
        V4 ra, rb;
        ra.f = *reinterpret_cast<const float4*>(s->A + j * LDA + c0);
        rb.f = *reinterpret_cast<const float4*>(s->A + j * LDA + c0 + 64);
        a[0]=fmaf(v,ra.s[0],a[0]); a[1]=fmaf(v,ra.s[1],a[1]);
        a[2]=fmaf(v,ra.s[2],a[2]); a[3]=fmaf(v,ra.s[3],a[3]);
        a[4]=fmaf(v,rb.s[0],a[4]); a[5]=fmaf(v,rb.s[1],a[5]);
        a[6]=fmaf(v,rb.s[2],a[6]); a[7]=fmaf(v,rb.s[3],a[7]);
      }
    }
    float rc = 1.f / fmaxf((float)cnt, 1.f);
    *reinterpret_cast<float4*>(s->B + row * LDA + c0) =
        make_float4(a[0]*rc, a[1]*rc, a[2]*rc, a[3]*rc);
    *reinterpret_cast<float4*>(s->B + row * LDA + c0 + 64) =
        make_float4(a[4]*rc, a[5]*rc, a[6]*rc, a[7]*rc);
  }
  __syncthreads();

  const int i0 = tid >> 4, c0 = (tid & 15) * 8;
  const bool act = i0 < NI;
  u64 acc[1][4];
  acc[0][0] = acc[0][1] = acc[0][2] = acc[0][3] = 0ull;
  gemm_panels<1>(acc, s->B, wr_t,    s->Wpan, i0, c0, act, tid);
  gemm_panels<1>(acc, s->A, wroot_t, s->Wpan, i0, c0, act, tid);
  if (act) epi_store<1, true>(acc, s->A, i0, c0, br);
  __syncthreads();
}

// ---------------------------------------------------------------------------
// mean pool of A rows -> xsum[stage]
// ---------------------------------------------------------------------------
__device__ void mean_pool(Smem* s, int NI, int stage) {
  const int tid = threadIdx.x;
  int q = tid >> 7, h = tid & 127;
  float a = 0.f;
  for (int r = q; r < NI; r += 2) a += s->A[r * LDA + h];
  s->part[q * 128 + h] = a;
  __syncthreads();
  if (tid < 128)
    s->xsum[stage * 128 + tid] = (s->part[tid] + s->part[128 + tid]) * (1.f / (float)NI);
  __syncthreads();
}

// ---------------------------------------------------------------------------
// top-k (warp 0)
// ---------------------------------------------------------------------------
template<int KK>
__device__ void topk(Smem* s, int NI) {
  if (threadIdx.x < 32) {
    int lane = threadIdx.x;
    float v0 = (lane < NI) ? s->fit[lane] : -2.f;
    float v1 = (lane + 32 < NI) ? s->fit[lane + 32] : -2.f;
#pragma unroll 1
    for (int t = 0; t < KK; t++) {
      float bv; int bi;
      if (v0 >= v1) { bv = v0; bi = lane; } else { bv = v1; bi = lane + 32; }
#pragma unroll
      for (int o = 16; o; o >>= 1) {
        float ov = __shfl_xor_sync(0xffffffffu, bv, o);
        int   oi = __shfl_xor_sync(0xffffffffu, bi, o);
        if (ov > bv || (ov == bv && oi < bi)) { bv = ov; bi = oi; }
      }
      if (lane == 0) { s->perm[t] = bi; s->vals[t] = bv; }
      if (bi == lane) v0 = -2.f;
      if (bi == lane + 32) v1 = -2.f;
    }
  }
}

// ---------------------------------------------------------------------------
// ASAP pool 1 (N=64 -> 16, bitmask adjacency)
// ---------------------------------------------------------------------------
__device__ void pool1(Smem* s, const float* __restrict__ lw_t,
    const float* __restrict__ lb, const float* __restrict__ aw, float ab,
    const float* __restrict__ l1w, float l1b,
    const float* __restrict__ l2w,
    const float* __restrict__ l3w, float l3b)
{
  const int tid = threadIdx.x;
  const int w = tid >> 5, lane = tid & 31;

  if (tid < 64) s->masks[tid] |= (1ull << tid);
  __syncthreads();
  if (tid < 64) s->degw[tid] = (float)__popcll(s->masks[tid]);

  // masked max-agg -> B : 4 rows x 8 cols
  {
    const int i0 = (tid >> 4) * 4, c0 = (tid & 15) * 4;
    u64 msk[4] = {s->masks[i0], s->masks[i0+1], s->masks[i0+2], s->masks[i0+3]};
    float a[4][8];
#pragma unroll
    for (int r = 0; r < 4; r++)
#pragma unroll
      for (int c = 0; c < 8; c++) a[r][c] = -1e30f;
    u64 mm = msk[0] | msk[1] | msk[2] | msk[3];
    const float* Ap = s->A + c0;
    while (mm) {
      int j = __ffsll((long long)mm) - 1;
      mm &= mm - 1;
      V4 ra, rb;
      ra.f = *reinterpret_cast<const float4*>(Ap + j * LDA);
      rb.f = *reinterpret_cast<const float4*>(Ap + j * LDA + 64);
#pragma unroll
      for (int r = 0; r < 4; r++) {
        if ((msk[r] >> j) & 1) {
          a[r][0]=fmaxf(a[r][0],ra.s[0]); a[r][1]=fmaxf(a[r][1],ra.s[1]);
          a[r][2]=fmaxf(a[r][2],ra.s[2]); a[r][3]=fmaxf(a[r][3],ra.s[3]);
          a[r][4]=fmaxf(a[r][4],rb.s[0]); a[r][5]=fmaxf(a[r][5],rb.s[1]);
          a[r][6]=fmaxf(a[r][6],rb.s[2]); a[r][7]=fmaxf(a[r][7],rb.s[3]);
        }
      }
    }
#pragma unroll
    for (int r = 0; r < 4; r++) {
      *reinterpret_cast<float4*>(s->B + (i0+r)*LDA + c0) =
          make_float4(a[r][0], a[r][1], a[r][2], a[r][3]);
      *reinterpret_cast<float4*>(s->B + (i0+r)*LDA + c0 + 64) =
          make_float4(a[r][4], a[r][5], a[r][6], a[r][7]);
    }
  }
  __syncthreads();

  // XQ = B @ lw^T + lb -> B (panel-staged, in place)
  {
    const int i0 = (tid >> 4) * 4, c0 = (tid & 15) * 8;
    u64 acc[4][4];
#pragma unroll
    for (int r = 0; r < 4; r++)
#pragma unroll
      for (int j = 0; j < 4; j++) acc[r][j] = 0ull;
    gemm_panels<4>(acc, s->B, lw_t, s->Wpan, i0, c0, true, tid);
    epi_store<4, false>(acc, s->B, i0, c0, lb);
  }
  __syncthreads();

  // s1 = XQ.aw[:128] (B), s2 = X.aw[128:] (A)
  for (int d = w; d < 128; d += 8) {
    const float* row = (d < 64) ? (s->B + d * LDA) : (s->A + (d - 64) * LDA);
    const float* wv = (d < 64) ? aw : (aw + 128);
    float4 a = reinterpret_cast<const float4*>(row)[lane];
    float4 b = reinterpret_cast<const float4*>(wv)[lane];
    float dot = warp_red_sum(a.x*b.x + a.y*b.y + a.z*b.z + a.w*b.w);
    if (lane == 0) { if (d < 64) s->s1[d] = dot; else s->s2[d - 64] = dot; }
  }
  __syncthreads();

  // masked softmax -> S
  for (int i = w; i < 64; i += 8) {
    u64 mi = s->masks[i];
    float s1i = s->s1[i];
    bool vA = (mi >> lane) & 1, vB = (mi >> (lane + 32)) & 1;
    float e0 = s1i + s->s2[lane] + ab;       e0 = (e0 > 0.f) ? e0 : SLOPE * e0;
    float e1 = s1i + s->s2[lane + 32] + ab;  e1 = (e1 > 0.f) ? e1 : SLOPE * e1;
    float ev0 = vA ? e0 : -1e30f, ev1 = vB ? e1 : -1e30f;
    float mx = fmaxf(ev0, ev1);
#pragma unroll
    for (int o = 16; o; o >>= 1) mx = fmaxf(mx, __shfl_xor_sync(0xffffffffu, mx, o));
    float ex0 = vA ? __expf(ev0 - mx) : 0.f;
    float ex1 = vB ? __expf(ev1 - mx) : 0.f;
    float sum = warp_red_sum(ex0 + ex1);
    float inv = 1.f / sum;
    s->S[i * LDS_ + lane]      = ex0 * inv;
    s->S[i * LDS_ + lane + 32] = ex1 * inv;
  }
  __syncthreads();

  // XC = S @ X -> B : 4 rows x 8 cols, zero-skip
  {
    const int i0 = (tid >> 4) * 4, c0 = (tid & 15) * 4;
    u64 a[4][4];
#pragma unroll
    for (int r = 0; r < 4; r++)
#pragma unroll
      for (int j = 0; j < 4; j++) a[r][j] = 0ull;
    for (int k = 0; k < 64; k++) {
      float l0 = s->S[i0*LDS_ + k], l1 = s->S[(i0+1)*LDS_ + k];
      float l2 = s->S[(i0+2)*LDS_ + k], l3 = s->S[(i0+3)*LDS_ + k];
      if (l0 == 0.f && l1 == 0.f && l2 == 0.f && l3 == 0.f) continue;
      V4 ra, rb;
      ra.f = *reinterpret_cast<const float4*>(s->A + k * LDA + c0);
      rb.f = *reinterpret_cast<const float4*>(s->A + k * LDA + c0 + 64);
      float lv[4] = {l0, l1, l2, l3};
#pragma unroll
      for (int r = 0; r < 4; r++) {
        if (lv[r] != 0.f) {
          u64 lp = bcast2(lv[r]);
          a[r][0]=ffma2(lp,ra.p[0],a[r][0]); a[r][1]=ffma2(lp,ra.p[1],a[r][1]);
          a[r][2]=ffma2(lp,rb.p[0],a[r][2]); a[r][3]=ffma2(lp,rb.p[1],a[r][3]);
        }
      }
    }
#pragma unroll
    for (int r = 0; r < 4; r++) {
      V4 o;
      o.p[0]=a[r][0]; o.p[1]=a[r][1];
      *reinterpret_cast<float4*>(s->B + (i0+r)*LDA + c0) = o.f;
      o.p[0]=a[r][2]; o.p[1]=a[r][3];
      *reinterpret_cast<float4*>(s->B + (i0+r)*LDA + c0 + 64) = o.f;
    }
  }
  __syncthreads();

  // av/bv/cv dots
  for (int d = w; d < 192; d += 8) {
    int grp = d >> 6, i = d & 63;
    const float* wv = (grp == 0) ? l1w : (grp == 1) ? l2w : l3w;
    float4 a = reinterpret_cast<const float4*>(s->B + i * LDA)[lane];
    float4 b = reinterpret_cast<const float4*>(wv)[lane];
    float dot = warp_red_sum(a.x*b.x + a.y*b.y + a.z*b.z + a.w*b.w);
    if (lane == 0) {
      if (grp == 0)      s->av[i] = dot + l1b;
      else if (grp == 1) s->bv[i] = dot;
      else               s->cv[i] = dot + l3b;
    }
  }
  __syncthreads();

  if (tid < 64) {
    u64 mm = s->masks[tid];
    float a = 0.f;
    while (mm) {
      int j = __ffsll((long long)mm) - 1;
      mm &= mm - 1;
      a += s->av[j];
    }
    float f = a - s->bv[tid] * s->degw[tid] + s->cv[tid];
    s->fit[tid] = 1.f / (1.f + expf(-f));
  }
  __syncthreads();
  topk<16>(s, 64);
  __syncthreads();

  // XN = XC[perm]*vals -> A rows 0..15 ; T = S[perm]@adj1 -> A rows 16..31
  for (int idx = tid; idx < 16 * 128; idx += THREADS) {
    int t2 = idx >> 7, h = idx & 127;
    s->A[t2 * LDA + h] = s->B[s->perm[t2] * LDA + h] * s->vals[t2];
  }
  for (int idx = tid; idx < 16 * 64; idx += THREADS) {
    int t2 = idx >> 6, m = idx & 63;
    const float* srow = s->S + s->perm[t2] * LDS_;
    float a = 0.f;
    for (int n = 0; n < 64; n++) {
      float sv = srow[n];
      if (sv != 0.f && ((s->masks[n] >> m) & 1)) a += sv;
    }
    s->A[(16 + t2) * LDA + m] = a;
  }
  __syncthreads();

  // adjn = T @ S[perm]^T, zero diag -> adjP
  {
    int t2 = tid >> 4, l = tid & 15;
    const float* sl = s->S + s->perm[l] * LDS_;
    const float* tr = s->A + (16 + t2) * LDA;
    float a = 0.f;
    for (int m = 0; m < 64; m++) a += tr[m] * sl[m];
    s->adjP[t2 * LDP + l] = (t2 == l) ? 0.f : a;
  }
  __syncthreads();
}

// ---------------------------------------------------------------------------
// ASAP pool 2 (N=16 -> 4, float adjP)
// ---------------------------------------------------------------------------
__device__ void pool2(Smem* s, const float* __restrict__ lw_t,
    const float* __restrict__ lb, const float* __restrict__ aw, float ab,
    const float* __restrict__ l1w, float l1b,
    const float* __restrict__ l2w,
    const float* __restrict__ l3w, float l3b)
{
  const int tid = threadIdx.x;
  const int w = tid >> 5, lane = tid & 31;

  if (tid < 16) {
    float d = s->adjP[tid * LDP + tid];
    if (d == 0.f) s->adjP[tid * LDP + tid] = 1.f;
  }
  __syncthreads();
  if (tid < 16) {
    float sum = 0.f;
    for (int j = 0; j < 16; j++) sum += s->adjP[tid * LDP + j];
    s->degw[tid] = sum;
  }

  // masked max-agg -> B
  {
    int row = tid >> 4, c0 = (tid & 15) * 4;
    float a[8];
#pragma unroll
    for (int c = 0; c < 8; c++) a[c] = -1e30f;
    for (int j = 0; j < 16; j++) {
      if (s->adjP[row * LDP + j] != 0.f) {
        V4 ra, rb;
        ra.f = *reinterpret_cast<const float4*>(s->A + j * LDA + c0);
        rb.f = *reinterpret_cast<const float4*>(s->A + j * LDA + c0 + 64);
        a[0]=fmaxf(a[0],ra.s[0]); a[1]=fmaxf(a[1],ra.s[1]);
        a[2]=fmaxf(a[2],ra.s[2]); a[3]=fmaxf(a[3],ra.s[3]);
        a[4]=fmaxf(a[4],rb.s[0]); a[5]=fmaxf(a[5],rb.s[1]);
        a[6]=fmaxf(a[6],rb.s[2]); a[7]=fmaxf(a[7],rb.s[3]);
      }
    }
    *reinterpret_cast<float4*>(s->B + row*LDA + c0) = make_float4(a[0],a[1],a[2],a[3]);
    *reinterpret_cast<float4*>(s->B + row*LDA + c0 + 64) = make_float4(a[4],a[5],a[6],a[7]);
  }
  __syncthreads();

  // XQ = B @ lw^T + lb -> B (panel-staged, 16 rows)
  {
    const int i0 = tid >> 4, c0 = (tid & 15) * 8;
    u64 acc[1][4];
    acc[0][0] = acc[0][1] = acc[0][2] = acc[0][3] = 0ull;
    gemm_panels<1>(acc, s->B, lw_t, s->Wpan, i0, c0, true, tid);
    epi_store<1, false>(acc, s->B, i0, c0, lb);
  }
  __syncthreads();

  // s1/s2
  for (int d = w; d < 32; d += 8) {
    const float* row = (d < 16) ? (s->B + d * LDA) : (s->A + (d - 16) * LDA);
    const float* wv = (d < 16) ? aw : (aw + 128);
    float4 a = reinterpret_cast<const float4*>(row)[lane];
    float4 b = reinterpret_cast<const float4*>(wv)[lane];
    float dot = warp_red_sum(a.x*b.x + a.y*b.y + a.z*b.z + a.w*b.w);
    if (lane == 0) { if (d < 16) s->s1[d] = dot; else s->s2[d - 16] = dot; }
  }
  __syncthreads();

  // attention (warp per row, rows 0..15)
  for (int i = w; i < 16; i += 8) {
    float adjv = (lane < 16) ? s->adjP[i * LDP + lane] : 0.f;
    float e = s->s1[i] + ((lane < 16) ? s->s2[lane] : 0.f) + ab;
    e = (e > 0.f) ? e : SLOPE * e;
    float ev = (adjv != 0.f) ? e : -1e30f;
    float mx = ev;
#pragma unroll
    for (int o = 16; o; o >>= 1) mx = fmaxf(mx, __shfl_xor_sync(0xffffffffu, mx, o));
    float ex = (adjv != 0.f) ? __expf(ev - mx) : 0.f;
    float sum = warp_red_sum(ex);
    if (lane < 16) s->S[i * LDS_ + lane] = ex / sum;
  }
  __syncthreads();

  // XC = S @ X -> B
  {
    int row = tid >> 4, c0 = (tid & 15) * 4;
    float a[8] = {0,0,0,0,0,0,0,0};
    for (int j = 0; j < 16; j++) {
      float sv = s->S[row * LDS_ + j];
      if (sv != 0.f) {
        V4 ra, rb;
        ra.f = *reinterpret_cast<const float4*>(s->A + j * LDA + c0);
        rb.f = *reinterpret_cast<const float4*>(s->A + j * LDA + c0 + 64);
        a[0]=fmaf(sv,ra.s[0],a[0]); a[1]=fmaf(sv,ra.s[1],a[1]);
        a[2]=fmaf(sv,ra.s[2],a[2]); a[3]=fmaf(sv,ra.s[3],a[3]);
        a[4]=fmaf(sv,rb.s[0],a[4]); a[5]=fmaf(sv,rb.s[1],a[5]);
        a[6]=fmaf(sv,rb.s[2],a[6]); a[7]=fmaf(sv,rb.s[3],a[7]);
      }
    }
    *reinterpret_cast<float4*>(s->B + row*LDA + c0) = make_float4(a[0],a[1],a[2],a[3]);
    *reinterpret_cast<float4*>(s->B + row*LDA + c0 + 64) = make_float4(a[4],a[5],a[6],a[7]);
  }
  __syncthreads();

  // av/bv/cv
  for (int d = w; d < 48; d += 8) {
    int grp = d >> 4, i = d & 15;
    const float* wv = (grp == 0) ? l1w : (grp == 1) ? l2w : l3w;
    float4 a = reinterpret_cast<const float4*>(s->B + i * LDA)[lane];
    float4 b = reinterpret_cast<const float4*>(wv)[lane];
    float dot = warp_red_sum(a.x*b.x + a.y*b.y + a.z*b.z + a.w*b.w);
    if (lane == 0) {
      if (grp == 0)      s->av[i] = dot + l1b;
      else if (grp == 1) s->bv[i] = dot;
      else               s->cv[i] = dot + l3b;
    }
  }
  __syncthreads();

  if (tid < 16) {
    float a = 0.f;
    for (int j = 0; j < 16; j++) a += s->adjP[tid * LDP + j] * s->av[j];
    float f = a - s->bv[tid] * s->degw[tid] + s->cv[tid];
    s->fit[tid] = 1.f / (1.f + expf(-f));
  }
  __syncthreads();
  topk<4>(s, 16);
  __syncthreads();

  // XN = XC[perm]*vals -> A rows 0..3
  for (int idx = tid; idx < 4 * 128; idx += THREADS) {
    int t2 = idx >> 7, h = idx & 127;
    s->A[t2 * LDA + h] = s->B[s->perm[t2] * LDA + h] * s->vals[t2];
  }
  // T = S[perm] @ adjP -> A rows 16..19
  if (tid < 64) {
    int t2 = tid >> 4, m = tid & 15;
    const float* srow = s->S + s->perm[t2] * LDS_;
    float a = 0.f;
    for (int n = 0; n < 16; n++) a += srow[n] * s->adjP[n * LDP + m];
    s->A[(16 + t2) * LDA + m] = a;
  }
  __syncthreads();
  if (tid < 16) {
    int t2 = tid >> 2, l = tid & 3;
    const float* sl = s->S + s->perm[l] * LDS_;
    const float* tr = s->A + (16 + t2) * LDA;
    float a = 0.f;
    for (int m = 0; m < 16; m++) a += tr[m] * sl[m];
    s->adjP[t2 * LDP + l] = (t2 == l) ? 0.f : a;
  }
  __syncthreads();
}

// ---------------------------------------------------------------------------
// main kernel
// ---------------------------------------------------------------------------
__global__ void __launch_bounds__(THREADS, 2) asap_kernel(
    const float* __restrict__ x,          const float* __restrict__ adj,
    const float* __restrict__ conv1_br,
    const float* __restrict__ convs_br,
    const float* __restrict__ pool_lin_b,
    const float* __restrict__ pool_att_w, const float* __restrict__ pool_att_b,
    const float* __restrict__ pool_le1_w, const float* __restrict__ pool_le1_b,
    const float* __restrict__ pool_le2_w,
    const float* __restrict__ pool_le3_w, const float* __restrict__ pool_le3_b,
    const float* __restrict__ lin1_w,     const float* __restrict__ lin1_b,
    const float* __restrict__ lin2_w,     const float* __restrict__ lin2_b,
    float* __restrict__ out)
{
  extern __shared__ unsigned char smraw[];
  Smem* s = reinterpret_cast<Smem*>(smraw);
  const int g = blockIdx.x, tid = threadIdx.x;
  const int w = tid >> 5, lane = tid & 31;

  // load features + binary adjacency -> masks
  {
    const float4* xs = reinterpret_cast<const float4*>(x + (size_t)g * 8192);
#pragma unroll
    for (int i = 0; i < 8; i++) {
      int idx = tid + i * 256;
      int row = idx >> 5, c = (idx & 31) * 4;
      *reinterpret_cast<float4*>(s->A + row * LDA + c) = xs[idx];
    }
    if (tid < 64) {
      const float4* ar = reinterpret_cast<const float4*>(adj + (size_t)g * 4096 + tid * 64);
      u64 m = 0;
#pragma unroll
      for (int c = 0; c < 16; c++) {
        float4 v = __ldg(ar + c);
        if (v.x != 0.f) m |= 1ull << (c * 4 + 0);
        if (v.y != 0.f) m |= 1ull << (c * 4 + 1);
        if (v.z != 0.f) m |= 1ull << (c * 4 + 2);
        if (v.w != 0.f) m |= 1ull << (c * 4 + 3);
      }
      s->masks[tid] = m;
    }
  }
  __syncthreads();

  const float* W = g_WT;
  conv64(s, W + 0*16384, W + 1*16384, conv1_br);
  mean_pool(s, 64, 0);

  conv64(s, W + 2*16384, W + 6*16384, convs_br);
  mean_pool(s, 64, 1);

  pool1(s, W + 10*16384, pool_lin_b, pool_att_w, pool_att_b[0],
        pool_le1_w, pool_le1_b[0], pool_le2_w, pool_le3_w, pool_le3_b[0]);

  conv_small<16>(s, W + 3*16384, W + 7*16384, convs_br + 128);
  mean_pool(s, 16, 2);

  conv_small<16>(s, W + 4*16384, W + 8*16384, convs_br + 256);
  mean_pool(s, 16, 3);

  pool2(s, W + 11*16384, pool_lin_b + 128, pool_att_w + 256, pool_att_b[1],
        pool_le1_w + 128, pool_le1_b[1], pool_le2_w + 128,
        pool_le3_w + 128, pool_le3_b[1]);

  conv_small<4>(s, W + 5*16384, W + 9*16384, convs_br + 384);
  mean_pool(s, 4, 4);

  // MLP head
  for (int d = w; d < 128; d += 8) {
    const float4* zr = reinterpret_cast<const float4*>(s->xsum);
    const float4* wr = reinterpret_cast<const float4*>(lin1_w + d * 640);
    float a = 0.f;
#pragma unroll
    for (int c = 0; c < 5; c++) {
      float4 zc = zr[lane + 32 * c];
      float4 wc = __ldg(wr + lane + 32 * c);
      a += zc.x*wc.x + zc.y*wc.y + zc.z*wc.z + zc.w*wc.w;
    }
    a = warp_red_sum(a);
    if (lane == 0) s->zz[d] = fmaxf(a + lin1_b[d], 0.f);
  }
  __syncthreads();
  for (int d = w; d < 10; d += 8) {
    float4 zc = reinterpret_cast<const float4*>(s->zz)[lane];
    float4 wc = __ldg(reinterpret_cast<const float4*>(lin2_w + d * 128) + lane);
    float a = warp_red_sum(zc.x*wc.x + zc.y*wc.y + zc.z*wc.z + zc.w*wc.w);
    if (lane == 0) s->yy[d] = a + lin2_b[d];
  }
  __syncthreads();
  if (tid == 0) {
    float mx = -1e30f;
    for (int c = 0; c < 10; c++) mx = fmaxf(mx, s->yy[c]);
    float sum = 0.f;
    for (int c = 0; c < 10; c++) sum += expf(s->yy[c] - mx);
    s->lse = mx + logf(sum);
  }
  __syncthreads();
  if (tid < 10) out[g * 10 + tid] = s->yy[tid] - s->lse;
}

// ---------------------------------------------------------------------------
// prologue: transpose the 12 [128x128] weight matrices into g_WT
// ---------------------------------------------------------------------------
__global__ void transpose_k(
    const float* __restrict__ conv1_wr, const float* __restrict__ conv1_wroot,
    const float* __restrict__ convs_wr, const float* __restrict__ convs_wroot,
    const float* __restrict__ pool_lin_w)
{
  __shared__ float t[32][33];
  int mat = blockIdx.y;
  int tile = blockIdx.x;
  int tx = tile & 3, ty = tile >> 2;
  const float* src =
      (mat == 0) ? conv1_wr :
      (mat == 1) ? conv1_wroot :
      (mat < 6)  ? convs_wr + (mat - 2) * 16384 :
      (mat < 10) ? convs_wroot + (mat - 6) * 16384 :
                   pool_lin_w + (mat - 10) * 16384;
#pragma unroll
  for (int r = threadIdx.y; r < 32; r += 8)
    t[r][threadIdx.x] = src[(ty * 32 + r) * 128 + tx * 32 + threadIdx.x];
  __syncthreads();
#pragma unroll
  for (int r = threadIdx.y; r < 32; r += 8)
    g_WT[mat * 16384 + (tx * 32 + r) * 128 + ty * 32 + threadIdx.x] = t[threadIdx.x][r];
}

// ---------------------------------------------------------------------------
// launch
// ---------------------------------------------------------------------------
extern "C" void kernel_launch(void* const* d_in, const int* in_sizes, int n_in,
                              void* d_out, int out_size)
{
  const float* x           = (const float*)d_in[0];
  const float* adj         = (const float*)d_in[1];
  const float* conv1_wr    = (const float*)d_in[2];
  const float* conv1_br    = (const float*)d_in[3];
  const float* conv1_wroot = (const float*)d_in[4];
  const float* convs_wr    = (const float*)d_in[5];
  const float* convs_br    = (const float*)d_in[6];
  const float* convs_wroot = (const float*)d_in[7];
  const float* pool_lin_w  = (const float*)d_in[8];
  const float* pool_lin_b  = (const float*)d_in[9];
  const float* pool_att_w  = (const float*)d_in[10];
  const float* pool_att_b  = (const float*)d_in[11];
  const float* pool_le1_w  = (const float*)d_in[12];
  const float* pool_le1_b  = (const float*)d_in[13];
  const float* pool_le2_w  = (const float*)d_in[14];
  const float* pool_le3_w  = (const float*)d_in[15];
  const float* pool_le3_b  = (const float*)d_in[16];
  const float* lin1_w      = (const float*)d_in[17];
  const float* lin1_b      = (const float*)d_in[18];
  const float* lin2_w      = (const float*)d_in[19];
  const float* lin2_b      = (const float*)d_in[20];
  float* out = (float*)d_out;

  transpose_k<<<dim3(16, 12), dim3(32, 8)>>>(
      conv1_wr, conv1_wroot, convs_wr, convs_wroot, pool_lin_w);

  cudaFuncSetAttribute(asap_kernel, cudaFuncAttributeMaxDynamicSharedMemorySize,
                       (int)sizeof(Smem));
  asap_kernel<<<G_TOT, THREADS, sizeof(Smem)>>>(
      x, adj, conv1_br, convs_br,
      pool_lin_b, pool_att_w, pool_att_b,
      pool_le1_w, pool_le1_b, pool_le2_w, pool_le3_w, pool_le3_b,
      lin1_w, lin1_b, lin2_w, lin2_b, out);
}

// round 10
// speedup vs baseline: 1.1347x; 1.1347x over previous
#include <cuda_runtime.h>
#include <math.h>

// Net_ASAP fused pipeline, round 10 (= round 7 + fused dual-matrix conv GEMMs
// + full-thread small-N mappings; removes ~7 barriers + smem round trips).
// - 256 threads/CTA, 2 CTAs/SM; W read from global (L1-resident).
// - Bitmask adjacency; in-place A; warp-parallel small stages.

#define THREADS 256
#define G_TOT 512
#define SLOPE 0.2f
#define LDA 132
#define LDS_ 68
#define LDP 17

typedef unsigned long long u64;

__device__ float g_WT[12 * 128 * 128];   // pre-transposed weights W^T[k][h]

__device__ __forceinline__ u64 bcast2(float v) {
  unsigned r = __float_as_uint(v);
  u64 d; asm("mov.b64 %0, {%1, %1};" : "=l"(d) : "r"(r));
  return d;
}
__device__ __forceinline__ u64 ffma2(u64 a, u64 b, u64 c) {
  u64 d; asm("fma.rn.f32x2 %0, %1, %2, %3;" : "=l"(d) : "l"(a), "l"(b), "l"(c));
  return d;
}
__device__ __forceinline__ u64 fadd2(u64 a, u64 b) {
  u64 d; asm("add.rn.f32x2 %0, %1, %2;" : "=l"(d) : "l"(a), "l"(b));
  return d;
}
__device__ __forceinline__ u64 fmul2(u64 a, u64 b) {
  u64 d; asm("mul.rn.f32x2 %0, %1, %2;" : "=l"(d) : "l"(a), "l"(b));
  return d;
}

union V4 { float4 f; u64 p[2]; float s[4]; };

struct Smem {
  float A[64 * LDA];        // features (in-place)
  float B[64 * LDA];        // agg / xq / xc scratch
  float S[64 * LDS_];       // attention matrix
  u64   masks[64];          // binary adjacency, N=64 phase
  float adjP[16 * LDP];     // pooled float adjacency, N<=16
  float part[256];
  float degw[64], s1[64], s2[64], fit[64];
  float av[64], bv[64], cv[64], vals[64];
  int   perm[64];
  float xsum[640];
  float zz[128], yy[16], lse;
};

// ---------------------------------------------------------------------------
// RPT-row x 8-col GEMM core: acc[r][0..3] += L[(i0+r)][k] * W[k][c0..c0+7]
// W in GLOBAL (L1-resident). Same inner structure as round 7's mm48g.
// ---------------------------------------------------------------------------
template<int RPT>
__device__ __forceinline__ void mmg(u64 (&acc)[RPT][4],
    const float* __restrict__ L, const float* __restrict__ W,
    int i0, int c0, int k0, int K)
{
  const float* Lp = L + i0 * LDA + k0;
  const float* Wp = W + k0 * 128 + c0;
#pragma unroll 1
  for (int k = 0; k < K; k += 4) {
    V4 wv[4][2];
#pragma unroll
    for (int q = 0; q < 4; q++) {
      wv[q][0].f = __ldg(reinterpret_cast<const float4*>(Wp + (k + q) * 128));
      wv[q][1].f = __ldg(reinterpret_cast<const float4*>(Wp + (k + q) * 128 + 4));
    }
#pragma unroll
    for (int r = 0; r < RPT; r++) {
      V4 lv; lv.f = *reinterpret_cast<const float4*>(Lp + r * LDA + k);
#pragma unroll
      for (int q = 0; q < 4; q++) {
        u64 lp = bcast2(lv.s[q]);
        acc[r][0] = ffma2(lp, wv[q][0].p[0], acc[r][0]);
        acc[r][1] = ffma2(lp, wv[q][0].p[1], acc[r][1]);
        acc[r][2] = ffma2(lp, wv[q][1].p[0], acc[r][2]);
        acc[r][3] = ffma2(lp, wv[q][1].p[1], acc[r][3]);
      }
    }
  }
}

template<int RPT>
__device__ __forceinline__ void acc_zero(u64 (&acc)[RPT][4]) {
#pragma unroll
  for (int r = 0; r < RPT; r++)
#pragma unroll
    for (int j = 0; j < 4; j++) acc[r][j] = 0ull;
}

template<int RPT, bool RELU>
__device__ __forceinline__ void epi_store(const u64 (&acc)[RPT][4],
    float* __restrict__ O, int i0, int c0, const float* __restrict__ bias)
{
  float4 b1 = *reinterpret_cast<const float4*>(bias + c0);
  float4 b2 = *reinterpret_cast<const float4*>(bias + c0 + 4);
#pragma unroll
  for (int r = 0; r < RPT; r++) {
    V4 a, b;
    a.p[0] = acc[r][0]; a.p[1] = acc[r][1];
    b.p[0] = acc[r][2]; b.p[1] = acc[r][3];
    a.f.x += b1.x; a.f.y += b1.y; a.f.z += b1.z; a.f.w += b1.w;
    b.f.x += b2.x; b.f.y += b2.y; b.f.z += b2.z; b.f.w += b2.w;
    if (RELU) {
      a.f.x = fmaxf(a.f.x, 0.f); a.f.y = fmaxf(a.f.y, 0.f);
      a.f.z = fmaxf(a.f.z, 0.f); a.f.w = fmaxf(a.f.w, 0.f);
      b.f.x = fmaxf(b.f.x, 0.f); b.f.y = fmaxf(b.f.y, 0.f);
      b.f.z = fmaxf(b.f.z, 0.f); b.f.w = fmaxf(b.f.w, 0.f);
    }
    *reinterpret_cast<float4*>(O + (i0 + r) * LDA + c0)     = a.f;
    *reinterpret_cast<float4*>(O + (i0 + r) * LDA + c0 + 4) = b.f;
  }
}

__device__ __forceinline__ float warp_red_sum(float v) {
#pragma unroll
  for (int o = 16; o; o >>= 1) v += __shfl_xor_sync(0xffffffffu, v, o);
  return v;
}

// ---------------------------------------------------------------------------
// conv, N=64: A = relu( (adj@A)/cnt @ Wr + A@Wroot + br )
// Fused: all 256 threads, 4x8 tiles, both matrices into one accumulator.
// ---------------------------------------------------------------------------
__device__ void conv64(Smem* s, const float* __restrict__ wr_t,
    const float* __restrict__ wroot_t, const float* __restrict__ br)
{
  const int tid = threadIdx.x;
  // agg = (masks @ A)/cnt -> B : 4 rows x 8 cols per thread (bit iteration)
  {
    const int i0 = (tid >> 4) * 4, c0 = (tid & 15) * 4;
    u64 m0 = s->masks[i0], m1 = s->masks[i0+1], m2 = s->masks[i0+2], m3 = s->masks[i0+3];
    u64 a[4][4];
#pragma unroll
    for (int r = 0; r < 4; r++)
#pragma unroll
      for (int j = 0; j < 4; j++) a[r][j] = 0ull;
    u64 mm = m0 | m1 | m2 | m3;
    const float* Ap = s->A + c0;
    while (mm) {
      int j = __ffsll((long long)mm) - 1;
      mm &= mm - 1;
      V4 ra, rb;
      ra.f = *reinterpret_cast<const float4*>(Ap + j * LDA);
      rb.f = *reinterpret_cast<const float4*>(Ap + j * LDA + 64);
      if ((m0 >> j) & 1) { a[0][0]=fadd2(a[0][0],ra.p[0]); a[0][1]=fadd2(a[0][1],ra.p[1]);
                           a[0][2]=fadd2(a[0][2],rb.p[0]); a[0][3]=fadd2(a[0][3],rb.p[1]); }
      if ((m1 >> j) & 1) { a[1][0]=fadd2(a[1][0],ra.p[0]); a[1][1]=fadd2(a[1][1],ra.p[1]);
                           a[1][2]=fadd2(a[1][2],rb.p[0]); a[1][3]=fadd2(a[1][3],rb.p[1]); }
      if ((m2 >> j) & 1) { a[2][0]=fadd2(a[2][0],ra.p[0]); a[2][1]=fadd2(a[2][1],ra.p[1]);
                           a[2][2]=fadd2(a[2][2],rb.p[0]); a[2][3]=fadd2(a[2][3],rb.p[1]); }
      if ((m3 >> j) & 1) { a[3][0]=fadd2(a[3][0],ra.p[0]); a[3][1]=fadd2(a[3][1],ra.p[1]);
                           a[3][2]=fadd2(a[3][2],rb.p[0]); a[3][3]=fadd2(a[3][3],rb.p[1]); }
    }
    u64 msk[4] = {m0, m1, m2, m3};
#pragma unroll
    for (int r = 0; r < 4; r++) {
      u64 rc = bcast2(1.f / fmaxf((float)__popcll(msk[r]), 1.f));
      V4 o;
      o.p[0] = fmul2(a[r][0], rc); o.p[1] = fmul2(a[r][1], rc);
      *reinterpret_cast<float4*>(s->B + (i0 + r) * LDA + c0) = o.f;
      o.p[0] = fmul2(a[r][2], rc); o.p[1] = fmul2(a[r][3], rc);
      *reinterpret_cast<float4*>(s->B + (i0 + r) * LDA + c0 + 64) = o.f;
    }
  }
  __syncthreads();

  const int i0 = (tid >> 4) * 4, c0 = (tid & 15) * 8;
  u64 acc[4][4];
  acc_zero<4>(acc);
  mmg<4>(acc, s->B, wr_t,    i0, c0, 0, 128);
  mmg<4>(acc, s->A, wroot_t, i0, c0, 0, 128);
  __syncthreads();
  epi_store<4, true>(acc, s->A, i0, c0, br);
  __syncthreads();
}

// ---------------------------------------------------------------------------
// conv, N<=16 (float adjP). RPT rows per thread, fused dual GEMM.
// ---------------------------------------------------------------------------
template<int NI>
__device__ void conv_small(Smem* s, const float* __restrict__ wr_t,
    const float* __restrict__ wroot_t, const float* __restrict__ br)
{
  const int tid = threadIdx.x;
  if (tid < NI * 16) {
    int row = tid >> 4, c0 = (tid & 15) * 4;
    float a[8] = {0,0,0,0,0,0,0,0};
    int cnt = 0;
    for (int j = 0; j < NI; j++) {
      float v = s->adjP[row * LDP + j];
      if (v != 0.f) {
        cnt++;
        V4 ra, rb;
        ra.f = *reinterpret_cast<const float4*>(s->A + j * LDA + c0);
        rb.f = *reinterpret_cast<const float4*>(s->A + j * LDA + c0 + 64);
        a[0]=fmaf(v,ra.s[0],a[0]); a[1]=fmaf(v,ra.s[1],a[1]);
        a[2]=fmaf(v,ra.s[2],a[2]); a[3]=fmaf(v,ra.s[3],a[3]);
        a[4]=fmaf(v,rb.s[0],a[4]); a[5]=fmaf(v,rb.s[1],a[5]);
        a[6]=fmaf(v,rb.s[2],a[6]); a[7]=fmaf(v,rb.s[3],a[7]);
      }
    }
    float rc = 1.f / fmaxf((float)cnt, 1.f);
    *reinterpret_cast<float4*>(s->B + row * LDA + c0) =
        make_float4(a[0]*rc, a[1]*rc, a[2]*rc, a[3]*rc);
    *reinterpret_cast<float4*>(s->B + row * LDA + c0 + 64) =
        make_float4(a[4]*rc, a[5]*rc, a[6]*rc, a[7]*rc);
  }
  __syncthreads();

  constexpr int RPT = (NI == 16) ? 2 : 1;
  const int i0 = (tid >> 4) * RPT, c0 = (tid & 15) * 8;
  const bool act = i0 < NI;
  u64 acc[RPT][4];
  acc_zero<RPT>(acc);
  if (act) {
    mmg<RPT>(acc, s->B, wr_t,    i0, c0, 0, 128);
    mmg<RPT>(acc, s->A, wroot_t, i0, c0, 0, 128);
  }
  __syncthreads();
  if (act) epi_store<RPT, true>(acc, s->A, i0, c0, br);
  __syncthreads();
}

// ---------------------------------------------------------------------------
// mean pool of A rows -> xsum[stage]
// ---------------------------------------------------------------------------
__device__ void mean_pool(Smem* s, int NI, int stage) {
  const int tid = threadIdx.x;
  int q = tid >> 7, h = tid & 127;
  float a = 0.f;
  for (int r = q; r < NI; r += 2) a += s->A[r * LDA + h];
  s->part[q * 128 + h] = a;
  __syncthreads();
  if (tid < 128)
    s->xsum[stage * 128 + tid] = (s->part[tid] + s->part[128 + tid]) * (1.f / (float)NI);
  __syncthreads();
}

// ---------------------------------------------------------------------------
// top-k (warp 0)
// ---------------------------------------------------------------------------
template<int KK>
__device__ void topk(Smem* s, int NI) {
  if (threadIdx.x < 32) {
    int lane = threadIdx.x;
    float v0 = (lane < NI) ? s->fit[lane] : -2.f;
    float v1 = (lane + 32 < NI) ? s->fit[lane + 32] : -2.f;
#pragma unroll 1
    for (int t = 0; t < KK; t++) {
      float bv; int bi;
      if (v0 >= v1) { bv = v0; bi = lane; } else { bv = v1; bi = lane + 32; }
#pragma unroll
      for (int o = 16; o; o >>= 1) {
        float ov = __shfl_xor_sync(0xffffffffu, bv, o);
        int   oi = __shfl_xor_sync(0xffffffffu, bi, o);
        if (ov > bv || (ov == bv && oi < bi)) { bv = ov; bi = oi; }
      }
      if (lane == 0) { s->perm[t] = bi; s->vals[t] = bv; }
      if (bi == lane) v0 = -2.f;
      if (bi == lane + 32) v1 = -2.f;
    }
  }
}

// ---------------------------------------------------------------------------
// ASAP pool 1 (N=64 -> 16, bitmask adjacency)
// ---------------------------------------------------------------------------
__device__ void pool1(Smem* s, const float* __restrict__ lw_t,
    const float* __restrict__ lb, const float* __restrict__ aw, float ab,
    const float* __restrict__ l1w, float l1b,
    const float* __restrict__ l2w,
    const float* __restrict__ l3w, float l3b)
{
  const int tid = threadIdx.x;
  const int w = tid >> 5, lane = tid & 31;

  if (tid < 64) s->masks[tid] |= (1ull << tid);
  __syncthreads();
  if (tid < 64) s->degw[tid] = (float)__popcll(s->masks[tid]);

  // masked max-agg -> B : 4 rows x 8 cols
  {
    const int i0 = (tid >> 4) * 4, c0 = (tid & 15) * 4;
    u64 msk[4] = {s->masks[i0], s->masks[i0+1], s->masks[i0+2], s->masks[i0+3]};
    float a[4][8];
#pragma unroll
    for (int r = 0; r < 4; r++)
#pragma unroll
      for (int c = 0; c < 8; c++) a[r][c] = -1e30f;
    u64 mm = msk[0] | msk[1] | msk[2] | msk[3];
    const float* Ap = s->A + c0;
    while (mm) {
      int j = __ffsll((long long)mm) - 1;
      mm &= mm - 1;
      V4 ra, rb;
      ra.f = *reinterpret_cast<const float4*>(Ap + j * LDA);
      rb.f = *reinterpret_cast<const float4*>(Ap + j * LDA + 64);
#pragma unroll
      for (int r = 0; r < 4; r++) {
        if ((msk[r] >> j) & 1) {
          a[r][0]=fmaxf(a[r][0],ra.s[0]); a[r][1]=fmaxf(a[r][1],ra.s[1]);
          a[r][2]=fmaxf(a[r][2],ra.s[2]); a[r][3]=fmaxf(a[r][3],ra.s[3]);
          a[r][4]=fmaxf(a[r][4],rb.s[0]); a[r][5]=fmaxf(a[r][5],rb.s[1]);
          a[r][6]=fmaxf(a[r][6],rb.s[2]); a[r][7]=fmaxf(a[r][7],rb.s[3]);
        }
      }
    }
#pragma unroll
    for (int r = 0; r < 4; r++) {
      *reinterpret_cast<float4*>(s->B + (i0+r)*LDA + c0) =
          make_float4(a[r][0], a[r][1], a[r][2], a[r][3]);
      *reinterpret_cast<float4*>(s->B + (i0+r)*LDA + c0 + 64) =
          make_float4(a[r][4], a[r][5], a[r][6], a[r][7]);
    }
  }
  __syncthreads();

  // XQ = B @ lw^T + lb -> B (full-K, in place; barrier before epilogue)
  {
    const int i0 = (tid >> 4) * 4, c0 = (tid & 15) * 8;
    u64 acc[4][4];
    acc_zero<4>(acc);
    mmg<4>(acc, s->B, lw_t, i0, c0, 0, 128);
    __syncthreads();
    epi_store<4, false>(acc, s->B, i0, c0, lb);
  }
  __syncthreads();

  // s1 = XQ.aw[:128] (B), s2 = X.aw[128:] (A)
  for (int d = w; d < 128; d += 8) {
    const float* row = (d < 64) ? (s->B + d * LDA) : (s->A + (d - 64) * LDA);
    const float* wv = (d < 64) ? aw : (aw + 128);
    float4 a = reinterpret_cast<const float4*>(row)[lane];
    float4 b = reinterpret_cast<const float4*>(wv)[lane];
    float dot = warp_red_sum(a.x*b.x + a.y*b.y + a.z*b.z + a.w*b.w);
    if (lane == 0) { if (d < 64) s->s1[d] = dot; else s->s2[d - 64] = dot; }
  }
  __syncthreads();

  // masked softmax -> S
  for (int i = w; i < 64; i += 8) {
    u64 mi = s->masks[i];
    float s1i = s->s1[i];
    bool vA = (mi >> lane) & 1, vB = (mi >> (lane + 32)) & 1;
    float e0 = s1i + s->s2[lane] + ab;       e0 = (e0 > 0.f) ? e0 : SLOPE * e0;
    float e1 = s1i + s->s2[lane + 32] + ab;  e1 = (e1 > 0.f) ? e1 : SLOPE * e1;
    float ev0 = vA ? e0 : -1e30f, ev1 = vB ? e1 : -1e30f;
    float mx = fmaxf(ev0, ev1);
#pragma unroll
    for (int o = 16; o; o >>= 1) mx = fmaxf(mx, __shfl_xor_sync(0xffffffffu, mx, o));
    float ex0 = vA ? __expf(ev0 - mx) : 0.f;
    float ex1 = vB ? __expf(ev1 - mx) : 0.f;
    float sum = warp_red_sum(ex0 + ex1);
    float inv = 1.f / sum;
    s->S[i * LDS_ + lane]      = ex0 * inv;
    s->S[i * LDS_ + lane + 32] = ex1 * inv;
  }
  __syncthreads();

  // XC = S @ X -> B : 4 rows x 8 cols, zero-skip
  {
    const int i0 = (tid >> 4) * 4, c0 = (tid & 15) * 4;
    u64 a[4][4];
#pragma unroll
    for (int r = 0; r < 4; r++)
#pragma unroll
      for (int j = 0; j < 4; j++) a[r][j] = 0ull;
    for (int k = 0; k < 64; k++) {
      float l0 = s->S[i0*LDS_ + k], l1 = s->S[(i0+1)*LDS_ + k];
      float l2 = s->S[(i0+2)*LDS_ + k], l3 = s->S[(i0+3)*LDS_ + k];
      if (l0 == 0.f && l1 == 0.f && l2 == 0.f && l3 == 0.f) continue;
      V4 ra, rb;
      ra.f = *reinterpret_cast<const float4*>(s->A + k * LDA + c0);
      rb.f = *reinterpret_cast<const float4*>(s->A + k * LDA + c0 + 64);
      float lv[4] = {l0, l1, l2, l3};
#pragma unroll
      for (int r = 0; r < 4; r++) {
        if (lv[r] != 0.f) {
          u64 lp = bcast2(lv[r]);
          a[r][0]=ffma2(lp,ra.p[0],a[r][0]); a[r][1]=ffma2(lp,ra.p[1],a[r][1]);
          a[r][2]=ffma2(lp,rb.p[0],a[r][2]); a[r][3]=ffma2(lp,rb.p[1],a[r][3]);
        }
      }
    }
#pragma unroll
    for (int r = 0; r < 4; r++) {
      V4 o;
      o.p[0]=a[r][0]; o.p[1]=a[r][1];
      *reinterpret_cast<float4*>(s->B + (i0+r)*LDA + c0) = o.f;
      o.p[0]=a[r][2]; o.p[1]=a[r][3];
      *reinterpret_cast<float4*>(s->B + (i0+r)*LDA + c0 + 64) = o.f;
    }
  }
  __syncthreads();

  // av/bv/cv dots
  for (int d = w; d < 192; d += 8) {
    int grp = d >> 6, i = d & 63;
    const float* wv = (grp == 0) ? l1w : (grp == 1) ? l2w : l3w;
    float4 a = reinterpret_cast<const float4*>(s->B + i * LDA)[lane];
    float4 b = reinterpret_cast<const float4*>(wv)[lane];
    float dot = warp_red_sum(a.x*b.x + a.y*b.y + a.z*b.z + a.w*b.w);
    if (lane == 0) {
      if (grp == 0)      s->av[i] = dot + l1b;
      else if (grp == 1) s->bv[i] = dot;
      else               s->cv[i] = dot + l3b;
    }
  }
  __syncthreads();

  if (tid < 64) {
    u64 mm = s->masks[tid];
    float a = 0.f;
    while (mm) {
      int j = __ffsll((long long)mm) - 1;
      mm &= mm - 1;
      a += s->av[j];
    }
    float f = a - s->bv[tid] * s->degw[tid] + s->cv[tid];
    s->fit[tid] = 1.f / (1.f + expf(-f));
  }
  __syncthreads();
  topk<16>(s, 64);
  __syncthreads();

  // XN = XC[perm]*vals -> A rows 0..15 ; T = S[perm]@adj1 -> A rows 16..31
  for (int idx = tid; idx < 16 * 128; idx += THREADS) {
    int t2 = idx >> 7, h = idx & 127;
    s->A[t2 * LDA + h] = s->B[s->perm[t2] * LDA + h] * s->vals[t2];
  }
  for (int idx = tid; idx < 16 * 64; idx += THREADS) {
    int t2 = idx >> 6, m = idx & 63;
    const float* srow = s->S + s->perm[t2] * LDS_;
    float a = 0.f;
    for (int n = 0; n < 64; n++) {
      float sv = srow[n];
      if (sv != 0.f && ((s->masks[n] >> m) & 1)) a += sv;
    }
    s->A[(16 + t2) * LDA + m] = a;
  }
  __syncthreads();

  // adjn = T @ S[perm]^T, zero diag -> adjP
  {
    int t2 = tid >> 4, l = tid & 15;
    const float* sl = s->S + s->perm[l] * LDS_;
    const float* tr = s->A + (16 + t2) * LDA;
    float a = 0.f;
    for (int m = 0; m < 64; m++) a += tr[m] * sl[m];
    s->adjP[t2 * LDP + l] = (t2 == l) ? 0.f : a;
  }
  __syncthreads();
}

// ---------------------------------------------------------------------------
// ASAP pool 2 (N=16 -> 4, float adjP)
// ---------------------------------------------------------------------------
__device__ void pool2(Smem* s, const float* __restrict__ lw_t,
    const float* __restrict__ lb, const float* __restrict__ aw, float ab,
    const float* __restrict__ l1w, float l1b,
    const float* __restrict__ l2w,
    const float* __restrict__ l3w, float l3b)
{
  const int tid = threadIdx.x;
  const int w = tid >> 5, lane = tid & 31;

  if (tid < 16) {
    float d = s->adjP[tid * LDP + tid];
    if (d == 0.f) s->adjP[tid * LDP + tid] = 1.f;
  }
  __syncthreads();
  if (tid < 16) {
    float sum = 0.f;
    for (int j = 0; j < 16; j++) sum += s->adjP[tid * LDP + j];
    s->degw[tid] = sum;
  }

  // masked max-agg -> B
  {
    int row = tid >> 4, c0 = (tid & 15) * 4;
    float a[8];
#pragma unroll
    for (int c = 0; c < 8; c++) a[c] = -1e30f;
    for (int j = 0; j < 16; j++) {
      if (s->adjP[row * LDP + j] != 0.f) {
        V4 ra, rb;
        ra.f = *reinterpret_cast<const float4*>(s->A + j * LDA + c0);
        rb.f = *reinterpret_cast<const float4*>(s->A + j * LDA + c0 + 64);
        a[0]=fmaxf(a[0],ra.s[0]); a[1]=fmaxf(a[1],ra.s[1]);
        a[2]=fmaxf(a[2],ra.s[2]); a[3]=fmaxf(a[3],ra.s[3]);
        a[4]=fmaxf(a[4],rb.s[0]); a[5]=fmaxf(a[5],rb.s[1]);
        a[6]=fmaxf(a[6],rb.s[2]); a[7]=fmaxf(a[7],rb.s[3]);
      }
    }
    *reinterpret_cast<float4*>(s->B + row*LDA + c0) = make_float4(a[0],a[1],a[2],a[3]);
    *reinterpret_cast<float4*>(s->B + row*LDA + c0 + 64) = make_float4(a[4],a[5],a[6],a[7]);
  }
  __syncthreads();

  // XQ = B @ lw^T + lb -> B (full-K, 2-row tiles, 128 active threads)
  {
    const int i0 = (tid >> 4) * 2, c0 = (tid & 15) * 8;
    const bool act = i0 < 16;
    u64 acc[2][4];
    acc_zero<2>(acc);
    if (act) mmg<2>(acc, s->B, lw_t, i0, c0, 0, 128);
    __syncthreads();
    if (act) epi_store<2, false>(acc, s->B, i0, c0, lb);
  }
  __syncthreads();

  // s1/s2
  for (int d = w; d < 32; d += 8) {
    const float* row = (d < 16) ? (s->B + d * LDA) : (s->A + (d - 16) * LDA);
    const float* wv = (d < 16) ? aw : (aw + 128);
    float4 a = reinterpret_cast<const float4*>(row)[lane];
    float4 b = reinterpret_cast<const float4*>(wv)[lane];
    float dot = warp_red_sum(a.x*b.x + a.y*b.y + a.z*b.z + a.w*b.w);
    if (lane == 0) { if (d < 16) s->s1[d] = dot; else s->s2[d - 16] = dot; }
  }
  __syncthreads();

  // attention (warp per row, rows 0..15)
  for (int i = w; i < 16; i += 8) {
    float adjv = (lane < 16) ? s->adjP[i * LDP + lane] : 0.f;
    float e = s->s1[i] + ((lane < 16) ? s->s2[lane] : 0.f) + ab;
    e = (e > 0.f) ? e : SLOPE * e;
    float ev = (adjv != 0.f) ? e : -1e30f;
    float mx = ev;
#pragma unroll
    for (int o = 16; o; o >>= 1) mx = fmaxf(mx, __shfl_xor_sync(0xffffffffu, mx, o));
    float ex = (adjv != 0.f) ? __expf(ev - mx) : 0.f;
    float sum = warp_red_sum(ex);
    if (lane < 16) s->S[i * LDS_ + lane] = ex / sum;
  }
  __syncthreads();

  // XC = S @ X -> B
  {
    int row = tid >> 4, c0 = (tid & 15) * 4;
    float a[8] = {0,0,0,0,0,0,0,0};
    for (int j = 0; j < 16; j++) {
      float sv = s->S[row * LDS_ + j];
      if (sv != 0.f) {
        V4 ra, rb;
        ra.f = *reinterpret_cast<const float4*>(s->A + j * LDA + c0);
        rb.f = *reinterpret_cast<const float4*>(s->A + j * LDA + c0 + 64);
        a[0]=fmaf(sv,ra.s[0],a[0]); a[1]=fmaf(sv,ra.s[1],a[1]);
        a[2]=fmaf(sv,ra.s[2],a[2]); a[3]=fmaf(sv,ra.s[3],a[3]);
        a[4]=fmaf(sv,rb.s[0],a[4]); a[5]=fmaf(sv,rb.s[1],a[5]);
        a[6]=fmaf(sv,rb.s[2],a[6]); a[7]=fmaf(sv,rb.s[3],a[7]);
      }
    }
    *reinterpret_cast<float4*>(s->B + row*LDA + c0) = make_float4(a[0],a[1],a[2],a[3]);
    *reinterpret_cast<float4*>(s->B + row*LDA + c0 + 64) = make_float4(a[4],a[5],a[6],a[7]);
  }
  __syncthreads();

  // av/bv/cv
  for (int d = w; d < 48; d += 8) {
    int grp = d >> 4, i = d & 15;
    const float* wv = (grp == 0) ? l1w : (grp == 1) ? l2w : l3w;
    float4 a = reinterpret_cast<const float4*>(s->B + i * LDA)[lane];
    float4 b = reinterpret_cast<const float4*>(wv)[lane];
    float dot = warp_red_sum(a.x*b.x + a.y*b.y + a.z*b.z + a.w*b.w);
    if (lane == 0) {
      if (grp == 0)      s->av[i] = dot + l1b;
      else if (grp == 1) s->bv[i] = dot;
      else               s->cv[i] = dot + l3b;
    }
  }
  __syncthreads();

  if (tid < 16) {
    float a = 0.f;
    for (int j = 0; j < 16; j++) a += s->adjP[tid * LDP + j] * s->av[j];
    float f = a - s->bv[tid] * s->degw[tid] + s->cv[tid];
    s->fit[tid] = 1.f / (1.f + expf(-f));
  }
  __syncthreads();
  topk<4>(s, 16);
  __syncthreads();

  // XN = XC[perm]*vals -> A rows 0..3
  for (int idx = tid; idx < 4 * 128; idx += THREADS) {
    int t2 = idx >> 7, h = idx & 127;
    s->A[t2 * LDA + h] = s->B[s->perm[t2] * LDA + h] * s->vals[t2];
  }
  // T = S[perm] @ adjP -> A rows 16..19
  if (tid < 64) {
    int t2 = tid >> 4, m = tid & 15;
    const float* srow = s->S + s->perm[t2] * LDS_;
    float a = 0.f;
    for (int n = 0; n < 16; n++) a += srow[n] * s->adjP[n * LDP + m];
    s->A[(16 + t2) * LDA + m] = a;
  }
  __syncthreads();
  if (tid < 16) {
    int t2 = tid >> 2, l = tid & 3;
    const float* sl = s->S + s->perm[l] * LDS_;
    const float* tr = s->A + (16 + t2) * LDA;
    float a = 0.f;
    for (int m = 0; m < 16; m++) a += tr[m] * sl[m];
    s->adjP[t2 * LDP + l] = (t2 == l) ? 0.f : a;
  }
  __syncthreads();
}

// ---------------------------------------------------------------------------
// main kernel
// ---------------------------------------------------------------------------
__global__ void __launch_bounds__(THREADS, 2) asap_kernel(
    const float* __restrict__ x,          const float* __restrict__ adj,
    const float* __restrict__ conv1_br,
    const float* __restrict__ convs_br,
    const float* __restrict__ pool_lin_b,
    const float* __restrict__ pool_att_w, const float* __restrict__ pool_att_b,
    const float* __restrict__ pool_le1_w, const float* __restrict__ pool_le1_b,
    const float* __restrict__ pool_le2_w,
    const float* __restrict__ pool_le3_w, const float* __restrict__ pool_le3_b,
    const float* __restrict__ lin1_w,     const float* __restrict__ lin1_b,
    const float* __restrict__ lin2_w,     const float* __restrict__ lin2_b,
    float* __restrict__ out)
{
  extern __shared__ unsigned char smraw[];
  Smem* s = reinterpret_cast<Smem*>(smraw);
  const int g = blockIdx.x, tid = threadIdx.x;
  const int w = tid >> 5, lane = tid & 31;

  // load features + binary adjacency -> masks
  {
    const float4* xs = reinterpret_cast<const float4*>(x + (size_t)g * 8192);
#pragma unroll
    for (int i = 0; i < 8; i++) {
      int idx = tid + i * 256;
      int row = idx >> 5, c = (idx & 31) * 4;
      *reinterpret_cast<float4*>(s->A + row * LDA + c) = xs[idx];
    }
    if (tid < 64) {
      const float4* ar = reinterpret_cast<const float4*>(adj + (size_t)g * 4096 + tid * 64);
      u64 m = 0;
#pragma unroll
      for (int c = 0; c < 16; c++) {
        float4 v = __ldg(ar + c);
        if (v.x != 0.f) m |= 1ull << (c * 4 + 0);
        if (v.y != 0.f) m |= 1ull << (c * 4 + 1);
        if (v.z != 0.f) m |= 1ull << (c * 4 + 2);
        if (v.w != 0.f) m |= 1ull << (c * 4 + 3);
      }
      s->masks[tid] = m;
    }
  }
  __syncthreads();

  const float* W = g_WT;
  conv64(s, W + 0*16384, W + 1*16384, conv1_br);
  mean_pool(s, 64, 0);

  conv64(s, W + 2*16384, W + 6*16384, convs_br);
  mean_pool(s, 64, 1);

  pool1(s, W + 10*16384, pool_lin_b, pool_att_w, pool_att_b[0],
        pool_le1_w, pool_le1_b[0], pool_le2_w, pool_le3_w, pool_le3_b[0]);

  conv_small<16>(s, W + 3*16384, W + 7*16384, convs_br + 128);
  mean_pool(s, 16, 2);

  conv_small<16>(s, W + 4*16384, W + 8*16384, convs_br + 256);
  mean_pool(s, 16, 3);

  pool2(s, W + 11*16384, pool_lin_b + 128, pool_att_w + 256, pool_att_b[1],
        pool_le1_w + 128, pool_le1_b[1], pool_le2_w + 128,
        pool_le3_w + 128, pool_le3_b[1]);

  conv_small<4>(s, W + 5*16384, W + 9*16384, convs_br + 384);
  mean_pool(s, 4, 4);

  // MLP head
  for (int d = w; d < 128; d += 8) {
    const float4* zr = reinterpret_cast<const float4*>(s->xsum);
    const float4* wr = reinterpret_cast<const float4*>(lin1_w + d * 640);
    float a = 0.f;
#pragma unroll
    for (int c = 0; c < 5; c++) {
      float4 zc = zr[lane + 32 * c];
      float4 wc = __ldg(wr + lane + 32 * c);
      a += zc.x*wc.x + zc.y*wc.y + zc.z*wc.z + zc.w*wc.w;
    }
    a = warp_red_sum(a);
    if (lane == 0) s->zz[d] = fmaxf(a + lin1_b[d], 0.f);
  }
  __syncthreads();
  for (int d = w; d < 10; d += 8) {
    float4 zc = reinterpret_cast<const float4*>(s->zz)[lane];
    float4 wc = __ldg(reinterpret_cast<const float4*>(lin2_w + d * 128) + lane);
    float a = warp_red_sum(zc.x*wc.x + zc.y*wc.y + zc.z*wc.z + zc.w*wc.w);
    if (lane == 0) s->yy[d] = a + lin2_b[d];
  }
  __syncthreads();
  if (tid == 0) {
    float mx = -1e30f;
    for (int c = 0; c < 10; c++) mx = fmaxf(mx, s->yy[c]);
    float sum = 0.f;
    for (int c = 0; c < 10; c++) sum += expf(s->yy[c] - mx);
    s->lse = mx + logf(sum);
  }
  __syncthreads();
  if (tid < 10) out[g * 10 + tid] = s->yy[tid] - s->lse;
}

// ---------------------------------------------------------------------------
// prologue: transpose the 12 [128x128] weight matrices into g_WT
// ---------------------------------------------------------------------------
__global__ void transpose_k(
    const float* __restrict__ conv1_wr, const float* __restrict__ conv1_wroot,
    const float* __restrict__ convs_wr, const float* __restrict__ convs_wroot,
    const float* __restrict__ pool_lin_w)
{
  __shared__ float t[32][33];
  int mat = blockIdx.y;
  int tile = blockIdx.x;
  int tx = tile & 3, ty = tile >> 2;
  const float* src =
      (mat == 0) ? conv1_wr :
      (mat == 1) ? conv1_wroot :
      (mat < 6)  ? convs_wr + (mat - 2) * 16384 :
      (mat < 10) ? convs_wroot + (mat - 6) * 16384 :
                   pool_lin_w + (mat - 10) * 16384;
#pragma unroll
  for (int r = threadIdx.y; r < 32; r += 8)
    t[r][threadIdx.x] = src[(ty * 32 + r) * 128 + tx * 32 + threadIdx.x];
  __syncthreads();
#pragma unroll
  for (int r = threadIdx.y; r < 32; r += 8)
    g_WT[mat * 16384 + (tx * 32 + r) * 128 + ty * 32 + threadIdx.x] = t[threadIdx.x][r];
}

// ---------------------------------------------------------------------------
// launch
// ---------------------------------------------------------------------------
extern "C" void kernel_launch(void* const* d_in, const int* in_sizes, int n_in,
                              void* d_out, int out_size)
{
  const float* x           = (const float*)d_in[0];
  const float* adj         = (const float*)d_in[1];
  const float* conv1_wr    = (const float*)d_in[2];
  const float* conv1_br    = (const float*)d_in[3];
  const float* conv1_wroot = (const float*)d_in[4];
  const float* convs_wr    = (const float*)d_in[5];
  const float* convs_br    = (const float*)d_in[6];
  const float* convs_wroot = (const float*)d_in[7];
  const float* pool_lin_w  = (const float*)d_in[8];
  const float* pool_lin_b  = (const float*)d_in[9];
  const float* pool_att_w  = (const float*)d_in[10];
  const float* pool_att_b  = (const float*)d_in[11];
  const float* pool_le1_w  = (const float*)d_in[12];
  const float* pool_le1_b  = (const float*)d_in[13];
  const float* pool_le2_w  = (const float*)d_in[14];
  const float* pool_le3_w  = (const float*)d_in[15];
  const float* pool_le3_b  = (const float*)d_in[16];
  const float* lin1_w      = (const float*)d_in[17];
  const float* lin1_b      = (const float*)d_in[18];
  const float* lin2_w      = (const float*)d_in[19];
  const float* lin2_b      = (const float*)d_in[20];
  float* out = (float*)d_out;

  transpose_k<<<dim3(16, 12), dim3(32, 8)>>>(
      conv1_wr, conv1_wroot, convs_wr, convs_wroot, pool_lin_w);

  cudaFuncSetAttribute(asap_kernel, cudaFuncAttributeMaxDynamicSharedMemorySize,
                       (int)sizeof(Smem));
  asap_kernel<<<G_TOT, THREADS, sizeof(Smem)>>>(
      x, adj, conv1_br, convs_br,
      pool_lin_b, pool_att_w, pool_att_b,
      pool_le1_w, pool_le1_b, pool_le2_w, pool_le3_w, pool_le3_b,
      lin1_w, lin1_b, lin2_w, lin2_b, out);
}

// round 14
// speedup vs baseline: 1.2980x; 1.1439x over previous
#include <cuda_runtime.h>
#include <math.h>

// Net_ASAP fused pipeline, round 14 = round 13 resubmit (infra failure x2).
// Round 7 base (best passing, 416us) + thread-utilization fixes:
//   - conv_small<16>: 2-row tiles, all 128 threads/group active (was 64)
//   - conv_small<4>:  1-row tiles, 64 active/group (was 16)
//   - pool XQ GEMMs: full-K all-thread, direct bias-store (no K-split trip)

#define THREADS 256
#define G_TOT 512
#define SLOPE 0.2f
#define LDA 132
#define LDS_ 68
#define LDP 17

typedef unsigned long long u64;

__device__ float g_WT[12 * 128 * 128];   // pre-transposed weights W^T[k][h]

__device__ __forceinline__ u64 bcast2(float v) {
  unsigned r = __float_as_uint(v);
  u64 d; asm("mov.b64 %0, {%1, %1};" : "=l"(d) : "r"(r));
  return d;
}
__device__ __forceinline__ u64 ffma2(u64 a, u64 b, u64 c) {
  u64 d; asm("fma.rn.f32x2 %0, %1, %2, %3;" : "=l"(d) : "l"(a), "l"(b), "l"(c));
  return d;
}
__device__ __forceinline__ u64 fadd2(u64 a, u64 b) {
  u64 d; asm("add.rn.f32x2 %0, %1, %2;" : "=l"(d) : "l"(a), "l"(b));
  return d;
}
__device__ __forceinline__ u64 fmul2(u64 a, u64 b) {
  u64 d; asm("mul.rn.f32x2 %0, %1, %2;" : "=l"(d) : "l"(a), "l"(b));
  return d;
}

union V4 { float4 f; u64 p[2]; float s[4]; };

struct Smem {
  float A[64 * LDA];        // features (in-place)
  float B[64 * LDA];        // agg / xq / xc scratch
  float S[64 * LDS_];       // attention matrix
  u64   masks[64];          // binary adjacency, N=64 phase
  float adjP[16 * LDP];     // pooled float adjacency, N<=16
  float part[256];
  float degw[64], s1[64], s2[64], fit[64];
  float av[64], bv[64], cv[64], vals[64];
  int   perm[64];
  float xsum[640];
  float zz[128], yy[16], lse;
};

// ---------------------------------------------------------------------------
// 8x8 GEMM core: acc[r][0..3] += L[(i0+r)][k] * W[k][c0..c0+7], W in GLOBAL
// ---------------------------------------------------------------------------
__device__ __forceinline__ void mm88(u64 (&acc)[8][4],
    const float* __restrict__ L, const float* __restrict__ W,
    int i0, int c0, int k0, int K)
{
  const float* Lp = L + i0 * LDA + k0;
  const float* Wp = W + k0 * 128 + c0;
#pragma unroll 1
  for (int k = 0; k < K; k += 4) {
    V4 wv[4][2];
#pragma unroll
    for (int q = 0; q < 4; q++) {
      wv[q][0].f = __ldg(reinterpret_cast<const float4*>(Wp + (k + q) * 128));
      wv[q][1].f = __ldg(reinterpret_cast<const float4*>(Wp + (k + q) * 128 + 4));
    }
#pragma unroll
    for (int r = 0; r < 8; r++) {
      V4 lv; lv.f = *reinterpret_cast<const float4*>(Lp + r * LDA + k);
#pragma unroll
      for (int q = 0; q < 4; q++) {
        u64 lp = bcast2(lv.s[q]);
        acc[r][0] = ffma2(lp, wv[q][0].p[0], acc[r][0]);
        acc[r][1] = ffma2(lp, wv[q][0].p[1], acc[r][1]);
        acc[r][2] = ffma2(lp, wv[q][1].p[0], acc[r][2]);
        acc[r][3] = ffma2(lp, wv[q][1].p[1], acc[r][3]);
      }
    }
  }
}

// RPT-row x 8-col variant for small GEMMs
template<int RPT>
__device__ __forceinline__ void mmg(u64 (&acc)[RPT][4],
    const float* __restrict__ L, const float* __restrict__ W,
    int i0, int c0, int k0, int K)
{
  const float* Lp = L + i0 * LDA + k0;
  const float* Wp = W + k0 * 128 + c0;
#pragma unroll 1
  for (int k = 0; k < K; k += 4) {
    V4 wv[4][2];
#pragma unroll
    for (int q = 0; q < 4; q++) {
      wv[q][0].f = __ldg(reinterpret_cast<const float4*>(Wp + (k + q) * 128));
      wv[q][1].f = __ldg(reinterpret_cast<const float4*>(Wp + (k + q) * 128 + 4));
    }
#pragma unroll
    for (int r = 0; r < RPT; r++) {
      V4 lv; lv.f = *reinterpret_cast<const float4*>(Lp + r * LDA + k);
#pragma unroll
      for (int q = 0; q < 4; q++) {
        u64 lp = bcast2(lv.s[q]);
        acc[r][0] = ffma2(lp, wv[q][0].p[0], acc[r][0]);
        acc[r][1] = ffma2(lp, wv[q][0].p[1], acc[r][1]);
        acc[r][2] = ffma2(lp, wv[q][1].p[0], acc[r][2]);
        acc[r][3] = ffma2(lp, wv[q][1].p[1], acc[r][3]);
      }
    }
  }
}

template<int RI>
__device__ __forceinline__ void acc_zero(u64 (&acc)[RI][4]) {
#pragma unroll
  for (int r = 0; r < RI; r++)
#pragma unroll
    for (int j = 0; j < 4; j++) acc[r][j] = 0ull;
}

template<int RI>
__device__ __forceinline__ void storeT(const u64 (&acc)[RI][4],
    float* O, int i0, int c0)
{
#pragma unroll
  for (int r = 0; r < RI; r++) {
    V4 a, b;
    a.p[0] = acc[r][0]; a.p[1] = acc[r][1];
    b.p[0] = acc[r][2]; b.p[1] = acc[r][3];
    *reinterpret_cast<float4*>(O + (i0 + r) * LDA + c0)     = a.f;
    *reinterpret_cast<float4*>(O + (i0 + r) * LDA + c0 + 4) = b.f;
  }
}

// O_tile = acc + P_tile + bias (optional relu)
template<int RI, bool RELU>
__device__ __forceinline__ void combineT(const u64 (&acc)[RI][4],
    const float* __restrict__ P, float* __restrict__ O,
    int i0, int c0, const float* __restrict__ bias)
{
  float4 b1 = *reinterpret_cast<const float4*>(bias + c0);
  float4 b2 = *reinterpret_cast<const float4*>(bias + c0 + 4);
#pragma unroll
  for (int r = 0; r < RI; r++) {
    V4 a, b, o1, o2;
    a.p[0] = acc[r][0]; a.p[1] = acc[r][1];
    b.p[0] = acc[r][2]; b.p[1] = acc[r][3];
    o1.f = *reinterpret_cast<const float4*>(P + (i0 + r) * LDA + c0);
    o2.f = *reinterpret_cast<const float4*>(P + (i0 + r) * LDA + c0 + 4);
    a.f.x += o1.f.x + b1.x; a.f.y += o1.f.y + b1.y;
    a.f.z += o1.f.z + b1.z; a.f.w += o1.f.w + b1.w;
    b.f.x += o2.f.x + b2.x; b.f.y += o2.f.y + b2.y;
    b.f.z += o2.f.z + b2.z; b.f.w += o2.f.w + b2.w;
    if (RELU) {
      a.f.x = fmaxf(a.f.x, 0.f); a.f.y = fmaxf(a.f.y, 0.f);
      a.f.z = fmaxf(a.f.z, 0.f); a.f.w = fmaxf(a.f.w, 0.f);
      b.f.x = fmaxf(b.f.x, 0.f); b.f.y = fmaxf(b.f.y, 0.f);
      b.f.z = fmaxf(b.f.z, 0.f); b.f.w = fmaxf(b.f.w, 0.f);
    }
    *reinterpret_cast<float4*>(O + (i0 + r) * LDA + c0)     = a.f;
    *reinterpret_cast<float4*>(O + (i0 + r) * LDA + c0 + 4) = b.f;
  }
}

// O_tile = acc + bias (no P), optional relu
template<int RI, bool RELU>
__device__ __forceinline__ void epi_store(const u64 (&acc)[RI][4],
    float* __restrict__ O, int i0, int c0, const float* __restrict__ bias)
{
  float4 b1 = *reinterpret_cast<const float4*>(bias + c0);
  float4 b2 = *reinterpret_cast<const float4*>(bias + c0 + 4);
#pragma unroll
  for (int r = 0; r < RI; r++) {
    V4 a, b;
    a.p[0] = acc[r][0]; a.p[1] = acc[r][1];
    b.p[0] = acc[r][2]; b.p[1] = acc[r][3];
    a.f.x += b1.x; a.f.y += b1.y; a.f.z += b1.z; a.f.w += b1.w;
    b.f.x += b2.x; b.f.y += b2.y; b.f.z += b2.z; b.f.w += b2.w;
    if (RELU) {
      a.f.x = fmaxf(a.f.x, 0.f); a.f.y = fmaxf(a.f.y, 0.f);
      a.f.z = fmaxf(a.f.z, 0.f); a.f.w = fmaxf(a.f.w, 0.f);
      b.f.x = fmaxf(b.f.x, 0.f); b.f.y = fmaxf(b.f.y, 0.f);
      b.f.z = fmaxf(b.f.z, 0.f); b.f.w = fmaxf(b.f.w, 0.f);
    }
    *reinterpret_cast<float4*>(O + (i0 + r) * LDA + c0)     = a.f;
    *reinterpret_cast<float4*>(O + (i0 + r) * LDA + c0 + 4) = b.f;
  }
}

__device__ __forceinline__ float warp_red_sum(float v) {
#pragma unroll
  for (int o = 16; o; o >>= 1) v += __shfl_xor_sync(0xffffffffu, v, o);
  return v;
}

// ---------------------------------------------------------------------------
// conv, N=64 (round 7 verbatim)
// ---------------------------------------------------------------------------
__device__ void conv64(Smem* s, const float* __restrict__ wr_t,
    const float* __restrict__ wroot_t, const float* __restrict__ br)
{
  const int tid = threadIdx.x;
  // agg = (masks @ A)/cnt -> B : 4 rows x 8 cols per thread (bit iteration)
  {
    const int i0 = (tid >> 4) * 4, c0 = (tid & 15) * 4;
    u64 m0 = s->masks[i0], m1 = s->masks[i0+1], m2 = s->masks[i0+2], m3 = s->masks[i0+3];
    u64 a[4][4];
#pragma unroll
    for (int r = 0; r < 4; r++)
#pragma unroll
      for (int j = 0; j < 4; j++) a[r][j] = 0ull;
    u64 mm = m0 | m1 | m2 | m3;
    const float* Ap = s->A + c0;
    while (mm) {
      int j = __ffsll((long long)mm) - 1;
      mm &= mm - 1;
      V4 ra, rb;
      ra.f = *reinterpret_cast<const float4*>(Ap + j * LDA);
      rb.f = *reinterpret_cast<const float4*>(Ap + j * LDA + 64);
      if ((m0 >> j) & 1) { a[0][0]=fadd2(a[0][0],ra.p[0]); a[0][1]=fadd2(a[0][1],ra.p[1]);
                           a[0][2]=fadd2(a[0][2],rb.p[0]); a[0][3]=fadd2(a[0][3],rb.p[1]); }
      if ((m1 >> j) & 1) { a[1][0]=fadd2(a[1][0],ra.p[0]); a[1][1]=fadd2(a[1][1],ra.p[1]);
                           a[1][2]=fadd2(a[1][2],rb.p[0]); a[1][3]=fadd2(a[1][3],rb.p[1]); }
      if ((m2 >> j) & 1) { a[2][0]=fadd2(a[2][0],ra.p[0]); a[2][1]=fadd2(a[2][1],ra.p[1]);
                           a[2][2]=fadd2(a[2][2],rb.p[0]); a[2][3]=fadd2(a[2][3],rb.p[1]); }
      if ((m3 >> j) & 1) { a[3][0]=fadd2(a[3][0],ra.p[0]); a[3][1]=fadd2(a[3][1],ra.p[1]);
                           a[3][2]=fadd2(a[3][2],rb.p[0]); a[3][3]=fadd2(a[3][3],rb.p[1]); }
    }
    u64 msk[4] = {m0, m1, m2, m3};
#pragma unroll
    for (int r = 0; r < 4; r++) {
      u64 rc = bcast2(1.f / fmaxf((float)__popcll(msk[r]), 1.f));
      V4 o;
      o.p[0] = fmul2(a[r][0], rc); o.p[1] = fmul2(a[r][1], rc);
      *reinterpret_cast<float4*>(s->B + (i0 + r) * LDA + c0) = o.f;
      o.p[0] = fmul2(a[r][2], rc); o.p[1] = fmul2(a[r][3], rc);
      *reinterpret_cast<float4*>(s->B + (i0 + r) * LDA + c0 + 64) = o.f;
    }
  }
  __syncthreads();

  const int grp = tid >> 7, t = tid & 127;
  const int i0 = (t >> 4) * 8, c0 = (t & 15) * 8;
  u64 acc[8][4];
  acc_zero<8>(acc);
  if (grp == 0) mm88(acc, s->B, wr_t, i0, c0, 0, 128);
  else          mm88(acc, s->A, wroot_t, i0, c0, 0, 128);
  __syncthreads();
  if (grp == 1) storeT<8>(acc, s->B, i0, c0);
  __syncthreads();
  if (grp == 0) combineT<8, true>(acc, s->B, s->A, i0, c0, br);
  __syncthreads();
}

// ---------------------------------------------------------------------------
// conv, N<=16 (float adjP) — full-thread mapping (RPT rows per thread)
// ---------------------------------------------------------------------------
template<int NI>
__device__ void conv_small(Smem* s, const float* __restrict__ wr_t,
    const float* __restrict__ wroot_t, const float* __restrict__ br)
{
  const int tid = threadIdx.x;
  if (tid < NI * 16) {
    int row = tid >> 4, c0 = (tid & 15) * 4;
    float a[8] = {0,0,0,0,0,0,0,0};
    int cnt = 0;
    for (int j = 0; j < NI; j++) {
      float v = s->adjP[row * LDP + j];
      if (v != 0.f) {
        cnt++;
        V4 ra, rb;
        ra.f = *reinterpret_cast<const float4*>(s->A + j * LDA + c0);
        rb.f = *reinterpret_cast<const float4*>(s->A + j * LDA + c0 + 64);
        a[0]=fmaf(v,ra.s[0],a[0]); a[1]=fmaf(v,ra.s[1],a[1]);
        a[2]=fmaf(v,ra.s[2],a[2]); a[3]=fmaf(v,ra.s[3],a[3]);
        a[4]=fmaf(v,rb.s[0],a[4]); a[5]=fmaf(v,rb.s[1],a[5]);
        a[6]=fmaf(v,rb.s[2],a[6]); a[7]=fmaf(v,rb.s[3],a[7]);
      }
    }
    float rc = 1.f / fmaxf((float)cnt, 1.f);
    *reinterpret_cast<float4*>(s->B + row * LDA + c0) =
        make_float4(a[0]*rc, a[1]*rc, a[2]*rc, a[3]*rc);
    *reinterpret_cast<float4*>(s->B + row * LDA + c0 + 64) =
        make_float4(a[4]*rc, a[5]*rc, a[6]*rc, a[7]*rc);
  }
  __syncthreads();

  constexpr int RPT = (NI == 16) ? 2 : 1;
  const int grp = tid >> 7, t = tid & 127;
  const int i0 = (t >> 4) * RPT, c0 = (t & 15) * 8;
  const bool act = i0 < NI;
  u64 acc[RPT][4];
  acc_zero<RPT>(acc);
  if (act) {
    if (grp == 0) mmg<RPT>(acc, s->B, wr_t, i0, c0, 0, 128);
    else          mmg<RPT>(acc, s->A, wroot_t, i0, c0, 0, 128);
  }
  __syncthreads();
  if (grp == 1 && act) storeT<RPT>(acc, s->B, i0, c0);
  __syncthreads();
  if (grp == 0 && act) combineT<RPT, true>(acc, s->B, s->A, i0, c0, br);
  __syncthreads();
}

// ---------------------------------------------------------------------------
// mean pool of A rows -> xsum[stage]
// ---------------------------------------------------------------------------
__device__ void mean_pool(Smem* s, int NI, int stage) {
  const int tid = threadIdx.x;
  int q = tid >> 7, h = tid & 127;
  float a = 0.f;
  for (int r = q; r < NI; r += 2) a += s->A[r * LDA + h];
  s->part[q * 128 + h] = a;
  __syncthreads();
  if (tid < 128)
    s->xsum[stage * 128 + tid] = (s->part[tid] + s->part[128 + tid]) * (1.f / (float)NI);
  __syncthreads();
}

// ---------------------------------------------------------------------------
// top-k (warp 0)
// ---------------------------------------------------------------------------
template<int KK>
__device__ void topk(Smem* s, int NI) {
  if (threadIdx.x < 32) {
    int lane = threadIdx.x;
    float v0 = (lane < NI) ? s->fit[lane] : -2.f;
    float v1 = (lane + 32 < NI) ? s->fit[lane + 32] : -2.f;
#pragma unroll 1
    for (int t = 0; t < KK; t++) {
      float bv; int bi;
      if (v0 >= v1) { bv = v0; bi = lane; } else { bv = v1; bi = lane + 32; }
#pragma unroll
      for (int o = 16; o; o >>= 1) {
        float ov = __shfl_xor_sync(0xffffffffu, bv, o);
        int   oi = __shfl_xor_sync(0xffffffffu, bi, o);
        if (ov > bv || (ov == bv && oi < bi)) { bv = ov; bi = oi; }
      }
      if (lane == 0) { s->perm[t] = bi; s->vals[t] = bv; }
      if (bi == lane) v0 = -2.f;
      if (bi == lane + 32) v1 = -2.f;
    }
  }
}

// ---------------------------------------------------------------------------
// ASAP pool 1 (N=64 -> 16, bitmask adjacency)
// ---------------------------------------------------------------------------
__device__ void pool1(Smem* s, const float* __restrict__ lw_t,
    const float* __restrict__ lb, const float* __restrict__ aw, float ab,
    const float* __restrict__ l1w, float l1b,
    const float* __restrict__ l2w,
    const float* __restrict__ l3w, float l3b)
{
  const int tid = threadIdx.x;
  const int w = tid >> 5, lane = tid & 31;

  if (tid < 64) s->masks[tid] |= (1ull << tid);
  __syncthreads();
  if (tid < 64) s->degw[tid] = (float)__popcll(s->masks[tid]);

  // masked max-agg -> B : 4 rows x 8 cols
  {
    const int i0 = (tid >> 4) * 4, c0 = (tid & 15) * 4;
    u64 msk[4] = {s->masks[i0], s->masks[i0+1], s->masks[i0+2], s->masks[i0+3]};
    float a[4][8];
#pragma unroll
    for (int r = 0; r < 4; r++)
#pragma unroll
      for (int c = 0; c < 8; c++) a[r][c] = -1e30f;
    u64 mm = msk[0] | msk[1] | msk[2] | msk[3];
    const float* Ap = s->A + c0;
    while (mm) {
      int j = __ffsll((long long)mm) - 1;
      mm &= mm - 1;
      V4 ra, rb;
      ra.f = *reinterpret_cast<const float4*>(Ap + j * LDA);
      rb.f = *reinterpret_cast<const float4*>(Ap + j * LDA + 64);
#pragma unroll
      for (int r = 0; r < 4; r++) {
        if ((msk[r] >> j) & 1) {
          a[r][0]=fmaxf(a[r][0],ra.s[0]); a[r][1]=fmaxf(a[r][1],ra.s[1]);
          a[r][2]=fmaxf(a[r][2],ra.s[2]); a[r][3]=fmaxf(a[r][3],ra.s[3]);
          a[r][4]=fmaxf(a[r][4],rb.s[0]); a[r][5]=fmaxf(a[r][5],rb.s[1]);
          a[r][6]=fmaxf(a[r][6],rb.s[2]); a[r][7]=fmaxf(a[r][7],rb.s[3]);
        }
      }
    }
#pragma unroll
    for (int r = 0; r < 4; r++) {
      *reinterpret_cast<float4*>(s->B + (i0+r)*LDA + c0) =
          make_float4(a[r][0], a[r][1], a[r][2], a[r][3]);
      *reinterpret_cast<float4*>(s->B + (i0+r)*LDA + c0 + 64) =
          make_float4(a[r][4], a[r][5], a[r][6], a[r][7]);
    }
  }
  __syncthreads();

  // XQ = B @ lw^T + lb -> B (full-K, all 256 threads, in place)
  {
    const int i0 = (tid >> 4) * 4, c0 = (tid & 15) * 8;
    u64 acc[4][4];
    acc_zero<4>(acc);
    mmg<4>(acc, s->B, lw_t, i0, c0, 0, 128);
    __syncthreads();
    epi_store<4, false>(acc, s->B, i0, c0, lb);
  }
  __syncthreads();

  // s1 = XQ.aw[:128] (B), s2 = X.aw[128:] (A)
  for (int d = w; d < 128; d += 8) {
    const float* row = (d < 64) ? (s->B + d * LDA) : (s->A + (d - 64) * LDA);
    const float* wv = (d < 64) ? aw : (aw + 128);
    float4 a = reinterpret_cast<const float4*>(row)[lane];
    float4 b = reinterpret_cast<const float4*>(wv)[lane];
    float dot = warp_red_sum(a.x*b.x + a.y*b.y + a.z*b.z + a.w*b.w);
    if (lane == 0) { if (d < 64) s->s1[d] = dot; else s->s2[d - 64] = dot; }
  }
  __syncthreads();

  // masked softmax -> S
  for (int i = w; i < 64; i += 8) {
    u64 mi = s->masks[i];
    float s1i = s->s1[i];
    bool vA = (mi >> lane) & 1, vB = (mi >> (lane + 32)) & 1;
    float e0 = s1i + s->s2[lane] + ab;       e0 = (e0 > 0.f) ? e0 : SLOPE * e0;
    float e1 = s1i + s->s2[lane + 32] + ab;  e1 = (e1 > 0.f) ? e1 : SLOPE * e1;
    float ev0 = vA ? e0 : -1e30f, ev1 = vB ? e1 : -1e30f;
    float mx = fmaxf(ev0, ev1);
#pragma unroll
    for (int o = 16; o; o >>= 1) mx = fmaxf(mx, __shfl_xor_sync(0xffffffffu, mx, o));
    float ex0 = vA ? __expf(ev0 - mx) : 0.f;
    float ex1 = vB ? __expf(ev1 - mx) : 0.f;
    float sum = warp_red_sum(ex0 + ex1);
    float inv = 1.f / sum;
    s->S[i * LDS_ + lane]      = ex0 * inv;
    s->S[i * LDS_ + lane + 32] = ex1 * inv;
  }
  __syncthreads();

  // XC = S @ X -> B : 4 rows x 8 cols, zero-skip
  {
    const int i0 = (tid >> 4) * 4, c0 = (tid & 15) * 4;
    u64 a[4][4];
#pragma unroll
    for (int r = 0; r < 4; r++)
#pragma unroll
      for (int j = 0; j < 4; j++) a[r][j] = 0ull;
    for (int k = 0; k < 64; k++) {
      float l0 = s->S[i0*LDS_ + k], l1 = s->S[(i0+1)*LDS_ + k];
      float l2 = s->S[(i0+2)*LDS_ + k], l3 = s->S[(i0+3)*LDS_ + k];
      if (l0 == 0.f && l1 == 0.f && l2 == 0.f && l3 == 0.f) continue;
      V4 ra, rb;
      ra.f = *reinterpret_cast<const float4*>(s->A + k * LDA + c0);
      rb.f = *reinterpret_cast<const float4*>(s->A + k * LDA + c0 + 64);
      float lv[4] = {l0, l1, l2, l3};
#pragma unroll
      for (int r = 0; r < 4; r++) {
        if (lv[r] != 0.f) {
          u64 lp = bcast2(lv[r]);
          a[r][0]=ffma2(lp,ra.p[0],a[r][0]); a[r][1]=ffma2(lp,ra.p[1],a[r][1]);
          a[r][2]=ffma2(lp,rb.p[0],a[r][2]); a[r][3]=ffma2(lp,rb.p[1],a[r][3]);
        }
      }
    }
#pragma unroll
    for (int r = 0; r < 4; r++) {
      V4 o;
      o.p[0]=a[r][0]; o.p[1]=a[r][1];
      *reinterpret_cast<float4*>(s->B + (i0+r)*LDA + c0) = o.f;
      o.p[0]=a[r][2]; o.p[1]=a[r][3];
      *reinterpret_cast<float4*>(s->B + (i0+r)*LDA + c0 + 64) = o.f;
    }
  }
  __syncthreads();

  // av/bv/cv dots
  for (int d = w; d < 192; d += 8) {
    int grp = d >> 6, i = d & 63;
    const float* wv = (grp == 0) ? l1w : (grp == 1) ? l2w : l3w;
    float4 a = reinterpret_cast<const float4*>(s->B + i * LDA)[lane];
    float4 b = reinterpret_cast<const float4*>(wv)[lane];
    float dot = warp_red_sum(a.x*b.x + a.y*b.y + a.z*b.z + a.w*b.w);
    if (lane == 0) {
      if (grp == 0)      s->av[i] = dot + l1b;
      else if (grp == 1) s->bv[i] = dot;
      else               s->cv[i] = dot + l3b;
    }
  }
  __syncthreads();

  if (tid < 64) {
    u64 mm = s->masks[tid];
    float a = 0.f;
    while (mm) {
      int j = __ffsll((long long)mm) - 1;
      mm &= mm - 1;
      a += s->av[j];
    }
    float f = a - s->bv[tid] * s->degw[tid] + s->cv[tid];
    s->fit[tid] = 1.f / (1.f + expf(-f));
  }
  __syncthreads();
  topk<16>(s, 64);
  __syncthreads();

  // XN = XC[perm]*vals -> A rows 0..15 ; T = S[perm]@adj1 -> A rows 16..31
  for (int idx = tid; idx < 16 * 128; idx += THREADS) {
    int t2 = idx >> 7, h = idx & 127;
    s->A[t2 * LDA + h] = s->B[s->perm[t2] * LDA + h] * s->vals[t2];
  }
  for (int idx = tid; idx < 16 * 64; idx += THREADS) {
    int t2 = idx >> 6, m = idx & 63;
    const float* srow = s->S + s->perm[t2] * LDS_;
    float a = 0.f;
    for (int n = 0; n < 64; n++) {
      float sv = srow[n];
      if (sv != 0.f && ((s->masks[n] >> m) & 1)) a += sv;
    }
    s->A[(16 + t2) * LDA + m] = a;
  }
  __syncthreads();

  // adjn = T @ S[perm]^T, zero diag -> adjP
  {
    int t2 = tid >> 4, l = tid & 15;
    const float* sl = s->S + s->perm[l] * LDS_;
    const float* tr = s->A + (16 + t2) * LDA;
    float a = 0.f;
    for (int m = 0; m < 64; m++) a += tr[m] * sl[m];
    s->adjP[t2 * LDP + l] = (t2 == l) ? 0.f : a;
  }
  __syncthreads();
}

// ---------------------------------------------------------------------------
// ASAP pool 2 (N=16 -> 4, float adjP)
// ---------------------------------------------------------------------------
__device__ void pool2(Smem* s, const float* __restrict__ lw_t,
    const float* __restrict__ lb, const float* __restrict__ aw, float ab,
    const float* __restrict__ l1w, float l1b,
    const float* __restrict__ l2w,
    const float* __restrict__ l3w, float l3b)
{
  const int tid = threadIdx.x;
  const int w = tid >> 5, lane = tid & 31;

  if (tid < 16) {
    float d = s->adjP[tid * LDP + tid];
    if (d == 0.f) s->adjP[tid * LDP + tid] = 1.f;
  }
  __syncthreads();
  if (tid < 16) {
    float sum = 0.f;
    for (int j = 0; j < 16; j++) sum += s->adjP[tid * LDP + j];
    s->degw[tid] = sum;
  }

  // masked max-agg -> B
  {
    int row = tid >> 4, c0 = (tid & 15) * 4;
    float a[8];
#pragma unroll
    for (int c = 0; c < 8; c++) a[c] = -1e30f;
    for (int j = 0; j < 16; j++) {
      if (s->adjP[row * LDP + j] != 0.f) {
        V4 ra, rb;
        ra.f = *reinterpret_cast<const float4*>(s->A + j * LDA + c0);
        rb.f = *reinterpret_cast<const float4*>(s->A + j * LDA + c0 + 64);
        a[0]=fmaxf(a[0],ra.s[0]); a[1]=fmaxf(a[1],ra.s[1]);
        a[2]=fmaxf(a[2],ra.s[2]); a[3]=fmaxf(a[3],ra.s[3]);
        a[4]=fmaxf(a[4],rb.s[0]); a[5]=fmaxf(a[5],rb.s[1]);
        a[6]=fmaxf(a[6],rb.s[2]); a[7]=fmaxf(a[7],rb.s[3]);
      }
    }
    *reinterpret_cast<float4*>(s->B + row*LDA + c0) = make_float4(a[0],a[1],a[2],a[3]);
    *reinterpret_cast<float4*>(s->B + row*LDA + c0 + 64) = make_float4(a[4],a[5],a[6],a[7]);
  }
  __syncthreads();

  // XQ = B @ lw^T + lb -> B (full-K, 1-row tiles, all 256 threads)
  {
    const int i0 = tid >> 4, c0 = (tid & 15) * 8;   // i0 in 0..15
    u64 acc[1][4];
    acc_zero<1>(acc);
    mmg<1>(acc, s->B, lw_t, i0, c0, 0, 128);
    __syncthreads();
    epi_store<1, false>(acc, s->B, i0, c0, lb);
  }
  __syncthreads();

  // s1/s2
  for (int d = w; d < 32; d += 8) {
    const float* row = (d < 16) ? (s->B + d * LDA) : (s->A + (d - 16) * LDA);
    const float* wv = (d < 16) ? aw : (aw + 128);
    float4 a = reinterpret_cast<const float4*>(row)[lane];
    float4 b = reinterpret_cast<const float4*>(wv)[lane];
    float dot = warp_red_sum(a.x*b.x + a.y*b.y + a.z*b.z + a.w*b.w);
    if (lane == 0) { if (d < 16) s->s1[d] = dot; else s->s2[d - 16] = dot; }
  }
  __syncthreads();

  // attention (warp per row, rows 0..15)
  for (int i = w; i < 16; i += 8) {
    float adjv = (lane < 16) ? s->adjP[i * LDP + lane] : 0.f;
    float e = s->s1[i] + ((lane < 16) ? s->s2[lane] : 0.f) + ab;
    e = (e > 0.f) ? e : SLOPE * e;
    float ev = (adjv != 0.f) ? e : -1e30f;
    float mx = ev;
#pragma unroll
    for (int o = 16; o; o >>= 1) mx = fmaxf(mx, __shfl_xor_sync(0xffffffffu, mx, o));
    float ex = (adjv != 0.f) ? __expf(ev - mx) : 0.f;
    float sum = warp_red_sum(ex);
    if (lane < 16) s->S[i * LDS_ + lane] = ex / sum;
  }
  __syncthreads();

  // XC = S @ X -> B
  {
    int row = tid >> 4, c0 = (tid & 15) * 4;
    float a[8] = {0,0,0,0,0,0,0,0};
    for (int j = 0; j < 16; j++) {
      float sv = s->S[row * LDS_ + j];
      if (sv != 0.f) {
        V4 ra, rb;
        ra.f = *reinterpret_cast<const float4*>(s->A + j * LDA + c0);
        rb.f = *reinterpret_cast<const float4*>(s->A + j * LDA + c0 + 64);
        a[0]=fmaf(sv,ra.s[0],a[0]); a[1]=fmaf(sv,ra.s[1],a[1]);
        a[2]=fmaf(sv,ra.s[2],a[2]); a[3]=fmaf(sv,ra.s[3],a[3]);
        a[4]=fmaf(sv,rb.s[0],a[4]); a[5]=fmaf(sv,rb.s[1],a[5]);
        a[6]=fmaf(sv,rb.s[2],a[6]); a[7]=fmaf(sv,rb.s[3],a[7]);
      }
    }
    *reinterpret_cast<float4*>(s->B + row*LDA + c0) = make_float4(a[0],a[1],a[2],a[3]);
    *reinterpret_cast<float4*>(s->B + row*LDA + c0 + 64) = make_float4(a[4],a[5],a[6],a[7]);
  }
  __syncthreads();

  // av/bv/cv
  for (int d = w; d < 48; d += 8) {
    int grp = d >> 4, i = d & 15;
    const float* wv = (grp == 0) ? l1w : (grp == 1) ? l2w : l3w;
    float4 a = reinterpret_cast<const float4*>(s->B + i * LDA)[lane];
    float4 b = reinterpret_cast<const float4*>(wv)[lane];
    float dot = warp_red_sum(a.x*b.x + a.y*b.y + a.z*b.z + a.w*b.w);
    if (lane == 0) {
      if (grp == 0)      s->av[i] = dot + l1b;
      else if (grp == 1) s->bv[i] = dot;
      else               s->cv[i] = dot + l3b;
    }
  }
  __syncthreads();

  if (tid < 16) {
    float a = 0.f;
    for (int j = 0; j < 16; j++) a += s->adjP[tid * LDP + j] * s->av[j];
    float f = a - s->bv[tid] * s->degw[tid] + s->cv[tid];
    s->fit[tid] = 1.f / (1.f + expf(-f));
  }
  __syncthreads();
  topk<4>(s, 16);
  __syncthreads();

  // XN = XC[perm]*vals -> A rows 0..3
  for (int idx = tid; idx < 4 * 128; idx += THREADS) {
    int t2 = idx >> 7, h = idx & 127;
    s->A[t2 * LDA + h] = s->B[s->perm[t2] * LDA + h] * s->vals[t2];
  }
  // T = S[perm] @ adjP -> A rows 16..19
  if (tid < 64) {
    int t2 = tid >> 4, m = tid & 15;
    const float* srow = s->S + s->perm[t2] * LDS_;
    float a = 0.f;
    for (int n = 0; n < 16; n++) a += srow[n] * s->adjP[n * LDP + m];
    s->A[(16 + t2) * LDA + m] = a;
  }
  __syncthreads();
  if (tid < 16) {
    int t2 = tid >> 2, l = tid & 3;
    const float* sl = s->S + s->perm[l] * LDS_;
    const float* tr = s->A + (16 + t2) * LDA;
    float a = 0.f;
    for (int m = 0; m < 16; m++) a += tr[m] * sl[m];
    s->adjP[t2 * LDP + l] = (t2 == l) ? 0.f : a;
  }
  __syncthreads();
}

// ---------------------------------------------------------------------------
// main kernel
// ---------------------------------------------------------------------------
__global__ void __launch_bounds__(THREADS, 2) asap_kernel(
    const float* __restrict__ x,          const float* __restrict__ adj,
    const float* __restrict__ conv1_br,
    const float* __restrict__ convs_br,
    const float* __restrict__ pool_lin_b,
    const float* __restrict__ pool_att_w, const float* __restrict__ pool_att_b,
    const float* __restrict__ pool_le1_w, const float* __restrict__ pool_le1_b,
    const float* __restrict__ pool_le2_w,
    const float* __restrict__ pool_le3_w, const float* __restrict__ pool_le3_b,
    const float* __restrict__ lin1_w,     const float* __restrict__ lin1_b,
    const float* __restrict__ lin2_w,     const float* __restrict__ lin2_b,
    float* __restrict__ out)
{
  extern __shared__ unsigned char smraw[];
  Smem* s = reinterpret_cast<Smem*>(smraw);
  const int g = blockIdx.x, tid = threadIdx.x;
  const int w = tid >> 5, lane = tid & 31;

  // load features + binary adjacency -> masks
  {
    const float4* xs = reinterpret_cast<const float4*>(x + (size_t)g * 8192);
#pragma unroll
    for (int i = 0; i < 8; i++) {
      int idx = tid + i * 256;
      int row = idx >> 5, c = (idx & 31) * 4;
      *reinterpret_cast<float4*>(s->A + row * LDA + c) = xs[idx];
    }
    if (tid < 64) {
      const float4* ar = reinterpret_cast<const float4*>(adj + (size_t)g * 4096 + tid * 64);
      u64 m = 0;
#pragma unroll
      for (int c = 0; c < 16; c++) {
        float4 v = __ldg(ar + c);
        if (v.x != 0.f) m |= 1ull << (c * 4 + 0);
        if (v.y != 0.f) m |= 1ull << (c * 4 + 1);
        if (v.z != 0.f) m |= 1ull << (c * 4 + 2);
        if (v.w != 0.f) m |= 1ull << (c * 4 + 3);
      }
      s->masks[tid] = m;
    }
  }
  __syncthreads();

  const float* W = g_WT;
  conv64(s, W + 0*16384, W + 1*16384, conv1_br);
  mean_pool(s, 64, 0);

  conv64(s, W + 2*16384, W + 6*16384, convs_br);
  mean_pool(s, 64, 1);

  pool1(s, W + 10*16384, pool_lin_b, pool_att_w, pool_att_b[0],
        pool_le1_w, pool_le1_b[0], pool_le2_w, pool_le3_w, pool_le3_b[0]);

  conv_small<16>(s, W + 3*16384, W + 7*16384, convs_br + 128);
  mean_pool(s, 16, 2);

  conv_small<16>(s, W + 4*16384, W + 8*16384, convs_br + 256);
  mean_pool(s, 16, 3);

  pool2(s, W + 11*16384, pool_lin_b + 128, pool_att_w + 256, pool_att_b[1],
        pool_le1_w + 128, pool_le1_b[1], pool_le2_w + 128,
        pool_le3_w + 128, pool_le3_b[1]);

  conv_small<4>(s, W + 5*16384, W + 9*16384, convs_br + 384);
  mean_pool(s, 4, 4);

  // MLP head
  for (int d = w; d < 128; d += 8) {
    const float4* zr = reinterpret_cast<const float4*>(s->xsum);
    const float4* wr = reinterpret_cast<const float4*>(lin1_w + d * 640);
    float a = 0.f;
#pragma unroll
    for (int c = 0; c < 5; c++) {
      float4 zc = zr[lane + 32 * c];
      float4 wc = __ldg(wr + lane + 32 * c);
      a += zc.x*wc.x + zc.y*wc.y + zc.z*wc.z + zc.w*wc.w;
    }
    a = warp_red_sum(a);
    if (lane == 0) s->zz[d] = fmaxf(a + lin1_b[d], 0.f);
  }
  __syncthreads();
  for (int d = w; d < 10; d += 8) {
    float4 zc = reinterpret_cast<const float4*>(s->zz)[lane];
    float4 wc = __ldg(reinterpret_cast<const float4*>(lin2_w + d * 128) + lane);
    float a = warp_red_sum(zc.x*wc.x + zc.y*wc.y + zc.z*wc.z + zc.w*wc.w);
    if (lane == 0) s->yy[d] = a + lin2_b[d];
  }
  __syncthreads();
  if (tid == 0) {
    float mx = -1e30f;
    for (int c = 0; c < 10; c++) mx = fmaxf(mx, s->yy[c]);
    float sum = 0.f;
    for (int c = 0; c < 10; c++) sum += expf(s->yy[c] - mx);
    s->lse = mx + logf(sum);
  }
  __syncthreads();
  if (tid < 10) out[g * 10 + tid] = s->yy[tid] - s->lse;
}

// ---------------------------------------------------------------------------
// prologue: transpose the 12 [128x128] weight matrices into g_WT
// ---------------------------------------------------------------------------
__global__ void transpose_k(
    const float* __restrict__ conv1_wr, const float* __restrict__ conv1_wroot,
    const float* __restrict__ convs_wr, const float* __restrict__ convs_wroot,
    const float* __restrict__ pool_lin_w)
{
  __shared__ float t[32][33];
  int mat = blockIdx.y;
  int tile = blockIdx.x;
  int tx = tile & 3, ty = tile >> 2;
  const float* src =
      (mat == 0) ? conv1_wr :
      (mat == 1) ? conv1_wroot :
      (mat < 6)  ? convs_wr + (mat - 2) * 16384 :
      (mat < 10) ? convs_wroot + (mat - 6) * 16384 :
                   pool_lin_w + (mat - 10) * 16384;
#pragma unroll
  for (int r = threadIdx.y; r < 32; r += 8)
    t[r][threadIdx.x] = src[(ty * 32 + r) * 128 + tx * 32 + threadIdx.x];
  __syncthreads();
#pragma unroll
  for (int r = threadIdx.y; r < 32; r += 8)
    g_WT[mat * 16384 + (tx * 32 + r) * 128 + ty * 32 + threadIdx.x] = t[threadIdx.x][r];
}

// ---------------------------------------------------------------------------
// launch
// ---------------------------------------------------------------------------
extern "C" void kernel_launch(void* const* d_in, const int* in_sizes, int n_in,
                              void* d_out, int out_size)
{
  const float* x           = (const float*)d_in[0];
  const float* adj         = (const float*)d_in[1];
  const float* conv1_wr    = (const float*)d_in[2];
  const float* conv1_br    = (const float*)d_in[3];
  const float* conv1_wroot = (const float*)d_in[4];
  const float* convs_wr    = (const float*)d_in[5];
  const float* convs_br    = (const float*)d_in[6];
  const float* convs_wroot = (const float*)d_in[7];
  const float* pool_lin_w  = (const float*)d_in[8];
  const float* pool_lin_b  = (const float*)d_in[9];
  const float* pool_att_w  = (const float*)d_in[10];
  const float* pool_att_b  = (const float*)d_in[11];
  const float* pool_le1_w  = (const float*)d_in[12];
  const float* pool_le1_b  = (const float*)d_in[13];
  const float* pool_le2_w  = (const float*)d_in[14];
  const float* pool_le3_w  = (const float*)d_in[15];
  const float* pool_le3_b  = (const float*)d_in[16];
  const float* lin1_w      = (const float*)d_in[17];
  const float* lin1_b      = (const float*)d_in[18];
  const float* lin2_w      = (const float*)d_in[19];
  const float* lin2_b      = (const float*)d_in[20];
  float* out = (float*)d_out;

  transpose_k<<<dim3(16, 12), dim3(32, 8)>>>(
      conv1_wr, conv1_wroot, convs_wr, convs_wroot, pool_lin_w);

  cudaFuncSetAttribute(asap_kernel, cudaFuncAttributeMaxDynamicSharedMemorySize,
                       (int)sizeof(Smem));
  asap_kernel<<<G_TOT, THREADS, sizeof(Smem)>>>(
      x, adj, conv1_br, convs_br,
      pool_lin_b, pool_att_w, pool_att_b,
      pool_le1_w, pool_le1_b, pool_le2_w, pool_le3_w, pool_le3_b,
      lin1_w, lin1_b, lin2_w, lin2_b, out);
}

// round 15
// speedup vs baseline: 1.4113x; 1.0872x over previous
#include <cuda_runtime.h>
#include <math.h>

// Net_ASAP fused pipeline, round 15 = round 7 (best passing, 416us) verbatim
// + two ordering-safe micro-opts:
//   - mean_pool: redundant trailing barrier removed (5 fewer barriers)
//   - mm48g: k-loop unroll 2 (better W-load latency overlap, reg-safe)

#define THREADS 256
#define G_TOT 512
#define SLOPE 0.2f
#define LDA 132
#define LDS_ 68
#define LDP 17

typedef unsigned long long u64;

__device__ float g_WT[12 * 128 * 128];   // pre-transposed weights W^T[k][h]

__device__ __forceinline__ u64 bcast2(float v) {
  unsigned r = __float_as_uint(v);
  u64 d; asm("mov.b64 %0, {%1, %1};" : "=l"(d) : "r"(r));
  return d;
}
__device__ __forceinline__ u64 ffma2(u64 a, u64 b, u64 c) {
  u64 d; asm("fma.rn.f32x2 %0, %1, %2, %3;" : "=l"(d) : "l"(a), "l"(b), "l"(c));
  return d;
}
__device__ __forceinline__ u64 fadd2(u64 a, u64 b) {
  u64 d; asm("add.rn.f32x2 %0, %1, %2;" : "=l"(d) : "l"(a), "l"(b));
  return d;
}
__device__ __forceinline__ u64 fmul2(u64 a, u64 b) {
  u64 d; asm("mul.rn.f32x2 %0, %1, %2;" : "=l"(d) : "l"(a), "l"(b));
  return d;
}

union V4 { float4 f; u64 p[2]; float s[4]; };

struct Smem {
  float A[64 * LDA];        // features (in-place)
  float B[64 * LDA];        // agg / xq / xc scratch
  float S[64 * LDS_];       // attention matrix
  u64   masks[64];          // binary adjacency, N=64 phase
  float adjP[16 * LDP];     // pooled float adjacency, N<=16
  float part[256];
  float degw[64], s1[64], s2[64], fit[64];
  float av[64], bv[64], cv[64], vals[64];
  int   perm[64];
  float xsum[640];
  float zz[128], yy[16], lse;
};

// ---------------------------------------------------------------------------
// 8x8 GEMM core: acc[r][0..3] += L[(i0+r)][k] * W[k][c0..c0+7], W in GLOBAL
// ---------------------------------------------------------------------------
__device__ __forceinline__ void mm88(u64 (&acc)[8][4],
    const float* __restrict__ L, const float* __restrict__ W,
    int i0, int c0, int k0, int K)
{
  const float* Lp = L + i0 * LDA + k0;
  const float* Wp = W + k0 * 128 + c0;
#pragma unroll 1
  for (int k = 0; k < K; k += 4) {
    V4 wv[4][2];
#pragma unroll
    for (int q = 0; q < 4; q++) {
      wv[q][0].f = __ldg(reinterpret_cast<const float4*>(Wp + (k + q) * 128));
      wv[q][1].f = __ldg(reinterpret_cast<const float4*>(Wp + (k + q) * 128 + 4));
    }
#pragma unroll
    for (int r = 0; r < 8; r++) {
      V4 lv; lv.f = *reinterpret_cast<const float4*>(Lp + r * LDA + k);
#pragma unroll
      for (int q = 0; q < 4; q++) {
        u64 lp = bcast2(lv.s[q]);
        acc[r][0] = ffma2(lp, wv[q][0].p[0], acc[r][0]);
        acc[r][1] = ffma2(lp, wv[q][0].p[1], acc[r][1]);
        acc[r][2] = ffma2(lp, wv[q][1].p[0], acc[r][2]);
        acc[r][3] = ffma2(lp, wv[q][1].p[1], acc[r][3]);
      }
    }
  }
}

// 4x8 variant for small-N convs / pool XQ (round 7 mapping, unroll 2)
__device__ __forceinline__ void mm48g(u64 (&acc)[4][4],
    const float* __restrict__ L, const float* __restrict__ W,
    int i0, int c0, int k0, int K)
{
  const float* Lp = L + i0 * LDA + k0;
  const float* Wp = W + k0 * 128 + c0;
#pragma unroll 2
  for (int k = 0; k < K; k += 4) {
    V4 wv[4][2];
#pragma unroll
    for (int q = 0; q < 4; q++) {
      wv[q][0].f = __ldg(reinterpret_cast<const float4*>(Wp + (k + q) * 128));
      wv[q][1].f = __ldg(reinterpret_cast<const float4*>(Wp + (k + q) * 128 + 4));
    }
#pragma unroll
    for (int r = 0; r < 4; r++) {
      V4 lv; lv.f = *reinterpret_cast<const float4*>(Lp + r * LDA + k);
#pragma unroll
      for (int q = 0; q < 4; q++) {
        u64 lp = bcast2(lv.s[q]);
        acc[r][0] = ffma2(lp, wv[q][0].p[0], acc[r][0]);
        acc[r][1] = ffma2(lp, wv[q][0].p[1], acc[r][1]);
        acc[r][2] = ffma2(lp, wv[q][1].p[0], acc[r][2]);
        acc[r][3] = ffma2(lp, wv[q][1].p[1], acc[r][3]);
      }
    }
  }
}

template<int RI>
__device__ __forceinline__ void storeT(const u64 (&acc)[RI][4],
    float* O, int i0, int c0)
{
#pragma unroll
  for (int r = 0; r < RI; r++) {
    V4 a, b;
    a.p[0] = acc[r][0]; a.p[1] = acc[r][1];
    b.p[0] = acc[r][2]; b.p[1] = acc[r][3];
    *reinterpret_cast<float4*>(O + (i0 + r) * LDA + c0)     = a.f;
    *reinterpret_cast<float4*>(O + (i0 + r) * LDA + c0 + 4) = b.f;
  }
}

// O_tile = acc + P_tile + bias (optional relu)
template<int RI, bool RELU>
__device__ __forceinline__ void combineT(const u64 (&acc)[RI][4],
    const float* __restrict__ P, float* __restrict__ O,
    int i0, int c0, const float* __restrict__ bias)
{
  float4 b1 = *reinterpret_cast<const float4*>(bias + c0);
  float4 b2 = *reinterpret_cast<const float4*>(bias + c0 + 4);
#pragma unroll
  for (int r = 0; r < RI; r++) {
    V4 a, b, o1, o2;
    a.p[0] = acc[r][0]; a.p[1] = acc[r][1];
    b.p[0] = acc[r][2]; b.p[1] = acc[r][3];
    o1.f = *reinterpret_cast<const float4*>(P + (i0 + r) * LDA + c0);
    o2.f = *reinterpret_cast<const float4*>(P + (i0 + r) * LDA + c0 + 4);
    a.f.x += o1.f.x + b1.x; a.f.y += o1.f.y + b1.y;
    a.f.z += o1.f.z + b1.z; a.f.w += o1.f.w + b1.w;
    b.f.x += o2.f.x + b2.x; b.f.y += o2.f.y + b2.y;
    b.f.z += o2.f.z + b2.z; b.f.w += o2.f.w + b2.w;
    if (RELU) {
      a.f.x = fmaxf(a.f.x, 0.f); a.f.y = fmaxf(a.f.y, 0.f);
      a.f.z = fmaxf(a.f.z, 0.f); a.f.w = fmaxf(a.f.w, 0.f);
      b.f.x = fmaxf(b.f.x, 0.f); b.f.y = fmaxf(b.f.y, 0.f);
      b.f.z = fmaxf(b.f.z, 0.f); b.f.w = fmaxf(b.f.w, 0.f);
    }
    *reinterpret_cast<float4*>(O + (i0 + r) * LDA + c0)     = a.f;
    *reinterpret_cast<float4*>(O + (i0 + r) * LDA + c0 + 4) = b.f;
  }
}

__device__ __forceinline__ float warp_red_sum(float v) {
#pragma unroll
  for (int o = 16; o; o >>= 1) v += __shfl_xor_sync(0xffffffffu, v, o);
  return v;
}

// ---------------------------------------------------------------------------
// conv, N=64 (round 7 verbatim)
// ---------------------------------------------------------------------------
__device__ void conv64(Smem* s, const float* __restrict__ wr_t,
    const float* __restrict__ wroot_t, const float* __restrict__ br)
{
  const int tid = threadIdx.x;
  // agg = (masks @ A)/cnt -> B : 4 rows x 8 cols per thread (bit iteration)
  {
    const int i0 = (tid >> 4) * 4, c0 = (tid & 15) * 4;
    u64 m0 = s->masks[i0], m1 = s->masks[i0+1], m2 = s->masks[i0+2], m3 = s->masks[i0+3];
    u64 a[4][4];
#pragma unroll
    for (int r = 0; r < 4; r++)
#pragma unroll
      for (int j = 0; j < 4; j++) a[r][j] = 0ull;
    u64 mm = m0 | m1 | m2 | m3;
    const float* Ap = s->A + c0;
    while (mm) {
      int j = __ffsll((long long)mm) - 1;
      mm &= mm - 1;
      V4 ra, rb;
      ra.f = *reinterpret_cast<const float4*>(Ap + j * LDA);
      rb.f = *reinterpret_cast<const float4*>(Ap + j * LDA + 64);
      if ((m0 >> j) & 1) { a[0][0]=fadd2(a[0][0],ra.p[0]); a[0][1]=fadd2(a[0][1],ra.p[1]);
                           a[0][2]=fadd2(a[0][2],rb.p[0]); a[0][3]=fadd2(a[0][3],rb.p[1]); }
      if ((m1 >> j) & 1) { a[1][0]=fadd2(a[1][0],ra.p[0]); a[1][1]=fadd2(a[1][1],ra.p[1]);
                           a[1][2]=fadd2(a[1][2],rb.p[0]); a[1][3]=fadd2(a[1][3],rb.p[1]); }
      if ((m2 >> j) & 1) { a[2][0]=fadd2(a[2][0],ra.p[0]); a[2][1]=fadd2(a[2][1],ra.p[1]);
                           a[2][2]=fadd2(a[2][2],rb.p[0]); a[2][3]=fadd2(a[2][3],rb.p[1]); }
      if ((m3 >> j) & 1) { a[3][0]=fadd2(a[3][0],ra.p[0]); a[3][1]=fadd2(a[3][1],ra.p[1]);
                           a[3][2]=fadd2(a[3][2],rb.p[0]); a[3][3]=fadd2(a[3][3],rb.p[1]); }
    }
    u64 msk[4] = {m0, m1, m2, m3};
#pragma unroll
    for (int r = 0; r < 4; r++) {
      u64 rc = bcast2(1.f / fmaxf((float)__popcll(msk[r]), 1.f));
      V4 o;
      o.p[0] = fmul2(a[r][0], rc); o.p[1] = fmul2(a[r][1], rc);
      *reinterpret_cast<float4*>(s->B + (i0 + r) * LDA + c0) = o.f;
      o.p[0] = fmul2(a[r][2], rc); o.p[1] = fmul2(a[r][3], rc);
      *reinterpret_cast<float4*>(s->B + (i0 + r) * LDA + c0 + 64) = o.f;
    }
  }
  __syncthreads();

  const int grp = tid >> 7, t = tid & 127;
  const int i0 = (t >> 4) * 8, c0 = (t & 15) * 8;
  u64 acc[8][4];
#pragma unroll
  for (int r = 0; r < 8; r++)
#pragma unroll
    for (int j = 0; j < 4; j++) acc[r][j] = 0ull;
  if (grp == 0) mm88(acc, s->B, wr_t, i0, c0, 0, 128);
  else          mm88(acc, s->A, wroot_t, i0, c0, 0, 128);
  __syncthreads();
  if (grp == 1) storeT<8>(acc, s->B, i0, c0);
  __syncthreads();
  if (grp == 0) combineT<8, true>(acc, s->B, s->A, i0, c0, br);
  __syncthreads();
}

// ---------------------------------------------------------------------------
// conv, N<=16 (round 7 verbatim)
// ---------------------------------------------------------------------------
template<int NI>
__device__ void conv_small(Smem* s, const float* __restrict__ wr_t,
    const float* __restrict__ wroot_t, const float* __restrict__ br)
{
  const int tid = threadIdx.x;
  if (tid < NI * 16) {
    int row = tid >> 4, c0 = (tid & 15) * 4;
    float a[8] = {0,0,0,0,0,0,0,0};
    int cnt = 0;
    for (int j = 0; j < NI; j++) {
      float v = s->adjP[row * LDP + j];
      if (v != 0.f) {
        cnt++;
        V4 ra, rb;
        ra.f = *reinterpret_cast<const float4*>(s->A + j * LDA + c0);
        rb.f = *reinterpret_cast<const float4*>(s->A + j * LDA + c0 + 64);
        a[0]=fmaf(v,ra.s[0],a[0]); a[1]=fmaf(v,ra.s[1],a[1]);
        a[2]=fmaf(v,ra.s[2],a[2]); a[3]=fmaf(v,ra.s[3],a[3]);
        a[4]=fmaf(v,rb.s[0],a[4]); a[5]=fmaf(v,rb.s[1],a[5]);
        a[6]=fmaf(v,rb.s[2],a[6]); a[7]=fmaf(v,rb.s[3],a[7]);
      }
    }
    float rc = 1.f / fmaxf((float)cnt, 1.f);
    *reinterpret_cast<float4*>(s->B + row * LDA + c0) =
        make_float4(a[0]*rc, a[1]*rc, a[2]*rc, a[3]*rc);
    *reinterpret_cast<float4*>(s->B + row * LDA + c0 + 64) =
        make_float4(a[4]*rc, a[5]*rc, a[6]*rc, a[7]*rc);
  }
  __syncthreads();

  const int grp = tid >> 7, t = tid & 127;
  const int i0 = (t >> 4) * 4, c0 = (t & 15) * 8;
  const bool act = i0 < NI;
  u64 acc[4][4];
#pragma unroll
  for (int r = 0; r < 4; r++)
#pragma unroll
    for (int j = 0; j < 4; j++) acc[r][j] = 0ull;
  if (act) {
    if (grp == 0) mm48g(acc, s->B, wr_t, i0, c0, 0, 128);
    else          mm48g(acc, s->A, wroot_t, i0, c0, 0, 128);
  }
  __syncthreads();
  if (grp == 1 && act) storeT<4>(acc, s->B, i0, c0);
  __syncthreads();
  if (grp == 0 && act) combineT<4, true>(acc, s->B, s->A, i0, c0, br);
  __syncthreads();
}

// ---------------------------------------------------------------------------
// mean pool of A rows -> xsum[stage]
// (trailing barrier removed: part[] reuse and xsum reads are protected by
//  the multiple barriers inside the next conv/pool phase)
// ---------------------------------------------------------------------------
__device__ void mean_pool(Smem* s, int NI, int stage) {
  const int tid = threadIdx.x;
  int q = tid >> 7, h = tid & 127;
  float a = 0.f;
  for (int r = q; r < NI; r += 2) a += s->A[r * LDA + h];
  s->part[q * 128 + h] = a;
  __syncthreads();
  if (tid < 128)
    s->xsum[stage * 128 + tid] = (s->part[tid] + s->part[128 + tid]) * (1.f / (float)NI);
}

// ---------------------------------------------------------------------------
// top-k (warp 0)
// ---------------------------------------------------------------------------
template<int KK>
__device__ void topk(Smem* s, int NI) {
  if (threadIdx.x < 32) {
    int lane = threadIdx.x;
    float v0 = (lane < NI) ? s->fit[lane] : -2.f;
    float v1 = (lane + 32 < NI) ? s->fit[lane + 32] : -2.f;
#pragma unroll 1
    for (int t = 0; t < KK; t++) {
      float bv; int bi;
      if (v0 >= v1) { bv = v0; bi = lane; } else { bv = v1; bi = lane + 32; }
#pragma unroll
      for (int o = 16; o; o >>= 1) {
        float ov = __shfl_xor_sync(0xffffffffu, bv, o);
        int   oi = __shfl_xor_sync(0xffffffffu, bi, o);
        if (ov > bv || (ov == bv && oi < bi)) { bv = ov; bi = oi; }
      }
      if (lane == 0) { s->perm[t] = bi; s->vals[t] = bv; }
      if (bi == lane) v0 = -2.f;
      if (bi == lane + 32) v1 = -2.f;
    }
  }
}

// ---------------------------------------------------------------------------
// ASAP pool 1 (N=64 -> 16, bitmask adjacency) (round 7 verbatim)
// ---------------------------------------------------------------------------
__device__ void pool1(Smem* s, const float* __restrict__ lw_t,
    const float* __restrict__ lb, const float* __restrict__ aw, float ab,
    const float* __restrict__ l1w, float l1b,
    const float* __restrict__ l2w,
    const float* __restrict__ l3w, float l3b)
{
  const int tid = threadIdx.x;
  const int w = tid >> 5, lane = tid & 31;

  if (tid < 64) s->masks[tid] |= (1ull << tid);
  __syncthreads();
  if (tid < 64) s->degw[tid] = (float)__popcll(s->masks[tid]);

  // masked max-agg -> B : 4 rows x 8 cols
  {
    const int i0 = (tid >> 4) * 4, c0 = (tid & 15) * 4;
    u64 msk[4] = {s->masks[i0], s->masks[i0+1], s->masks[i0+2], s->masks[i0+3]};
    float a[4][8];
#pragma unroll
    for (int r = 0; r < 4; r++)
#pragma unroll
      for (int c = 0; c < 8; c++) a[r][c] = -1e30f;
    u64 mm = msk[0] | msk[1] | msk[2] | msk[3];
    const float* Ap = s->A + c0;
    while (mm) {
      int j = __ffsll((long long)mm) - 1;
      mm &= mm - 1;
      V4 ra, rb;
      ra.f = *reinterpret_cast<const float4*>(Ap + j * LDA);
      rb.f = *reinterpret_cast<const float4*>(Ap + j * LDA + 64);
#pragma unroll
      for (int r = 0; r < 4; r++) {
        if ((msk[r] >> j) & 1) {
          a[r][0]=fmaxf(a[r][0],ra.s[0]); a[r][1]=fmaxf(a[r][1],ra.s[1]);
          a[r][2]=fmaxf(a[r][2],ra.s[2]); a[r][3]=fmaxf(a[r][3],ra.s[3]);
          a[r][4]=fmaxf(a[r][4],rb.s[0]); a[r][5]=fmaxf(a[r][5],rb.s[1]);
          a[r][6]=fmaxf(a[r][6],rb.s[2]); a[r][7]=fmaxf(a[r][7],rb.s[3]);
        }
      }
    }
#pragma unroll
    for (int r = 0; r < 4; r++) {
      *reinterpret_cast<float4*>(s->B + (i0+r)*LDA + c0) =
          make_float4(a[r][0], a[r][1], a[r][2], a[r][3]);
      *reinterpret_cast<float4*>(s->B + (i0+r)*LDA + c0 + 64) =
          make_float4(a[r][4], a[r][5], a[r][6], a[r][7]);
    }
  }
  __syncthreads();

  // XQ = B @ lw^T + lb -> B (K-split dual group, round 7)
  {
    const int grp = tid >> 7, t = tid & 127;
    const int i0 = (t >> 4) * 8, c0 = (t & 15) * 8;
    u64 acc[8][4];
#pragma unroll
    for (int r = 0; r < 8; r++)
#pragma unroll
      for (int j = 0; j < 4; j++) acc[r][j] = 0ull;
    mm88(acc, s->B, lw_t, i0, c0, grp ? 64 : 0, 64);
    __syncthreads();
    if (grp == 1) storeT<8>(acc, s->B, i0, c0);
    __syncthreads();
    if (grp == 0) combineT<8, false>(acc, s->B, s->B, i0, c0, lb);
  }
  __syncthreads();

  // s1 = XQ.aw[:128] (B), s2 = X.aw[128:] (A)
  for (int d = w; d < 128; d += 8) {
    const float* row = (d < 64) ? (s->B + d * LDA) : (s->A + (d - 64) * LDA);
    const float* wv = (d < 64) ? aw : (aw + 128);
    float4 a = reinterpret_cast<const float4*>(row)[lane];
    float4 b = reinterpret_cast<const float4*>(wv)[lane];
    float dot = warp_red_sum(a.x*b.x + a.y*b.y + a.z*b.z + a.w*b.w);
    if (lane == 0) { if (d < 64) s->s1[d] = dot; else s->s2[d - 64] = dot; }
  }
  __syncthreads();

  // masked softmax -> S
  for (int i = w; i < 64; i += 8) {
    u64 mi = s->masks[i];
    float s1i = s->s1[i];
    bool vA = (mi >> lane) & 1, vB = (mi >> (lane + 32)) & 1;
    float e0 = s1i + s->s2[lane] + ab;       e0 = (e0 > 0.f) ? e0 : SLOPE * e0;
    float e1 = s1i + s->s2[lane + 32] + ab;  e1 = (e1 > 0.f) ? e1 : SLOPE * e1;
    float ev0 = vA ? e0 : -1e30f, ev1 = vB ? e1 : -1e30f;
    float mx = fmaxf(ev0, ev1);
#pragma unroll
    for (int o = 16; o; o >>= 1) mx = fmaxf(mx, __shfl_xor_sync(0xffffffffu, mx, o));
    float ex0 = vA ? __expf(ev0 - mx) : 0.f;
    float ex1 = vB ? __expf(ev1 - mx) : 0.f;
    float sum = warp_red_sum(ex0 + ex1);
    float inv = 1.f / sum;
    s->S[i * LDS_ + lane]      = ex0 * inv;
    s->S[i * LDS_ + lane + 32] = ex1 * inv;
  }
  __syncthreads();

  // XC = S @ X -> B : 4 rows x 8 cols, zero-skip
  {
    const int i0 = (tid >> 4) * 4, c0 = (tid & 15) * 4;
    u64 a[4][4];
#pragma unroll
    for (int r = 0; r < 4; r++)
#pragma unroll
      for (int j = 0; j < 4; j++) a[r][j] = 0ull;
    for (int k = 0; k < 64; k++) {
      float l0 = s->S[i0*LDS_ + k], l1 = s->S[(i0+1)*LDS_ + k];
      float l2 = s->S[(i0+2)*LDS_ + k], l3 = s->S[(i0+3)*LDS_ + k];
      if (l0 == 0.f && l1 == 0.f && l2 == 0.f && l3 == 0.f) continue;
      V4 ra, rb;
      ra.f = *reinterpret_cast<const float4*>(s->A + k * LDA + c0);
      rb.f = *reinterpret_cast<const float4*>(s->A + k * LDA + c0 + 64);
      float lv[4] = {l0, l1, l2, l3};
#pragma unroll
      for (int r = 0; r < 4; r++) {
        if (lv[r] != 0.f) {
          u64 lp = bcast2(lv[r]);
          a[r][0]=ffma2(lp,ra.p[0],a[r][0]); a[r][1]=ffma2(lp,ra.p[1],a[r][1]);
          a[r][2]=ffma2(lp,rb.p[0],a[r][2]); a[r][3]=ffma2(lp,rb.p[1],a[r][3]);
        }
      }
    }
#pragma unroll
    for (int r = 0; r < 4; r++) {
      V4 o;
      o.p[0]=a[r][0]; o.p[1]=a[r][1];
      *reinterpret_cast<float4*>(s->B + (i0+r)*LDA + c0) = o.f;
      o.p[0]=a[r][2]; o.p[1]=a[r][3];
      *reinterpret_cast<float4*>(s->B + (i0+r)*LDA + c0 + 64) = o.f;
    }
  }
  __syncthreads();

  // av/bv/cv dots
  for (int d = w; d < 192; d += 8) {
    int grp = d >> 6, i = d & 63;
    const float* wv = (grp == 0) ? l1w : (grp == 1) ? l2w : l3w;
    float4 a = reinterpret_cast<const float4*>(s->B + i * LDA)[lane];
    float4 b = reinterpret_cast<const float4*>(wv)[lane];
    float dot = warp_red_sum(a.x*b.x + a.y*b.y + a.z*b.z + a.w*b.w);
    if (lane == 0) {
      if (grp == 0)      s->av[i] = dot + l1b;
      else if (grp == 1) s->bv[i] = dot;
      else               s->cv[i] = dot + l3b;
    }
  }
  __syncthreads();

  if (tid < 64) {
    u64 mm = s->masks[tid];
    float a = 0.f;
    while (mm) {
      int j = __ffsll((long long)mm) - 1;
      mm &= mm - 1;
      a += s->av[j];
    }
    float f = a - s->bv[tid] * s->degw[tid] + s->cv[tid];
    s->fit[tid] = 1.f / (1.f + expf(-f));
  }
  __syncthreads();
  topk<16>(s, 64);
  __syncthreads();

  // XN = XC[perm]*vals -> A rows 0..15 ; T = S[perm]@adj1 -> A rows 16..31
  for (int idx = tid; idx < 16 * 128; idx += THREADS) {
    int t2 = idx >> 7, h = idx & 127;
    s->A[t2 * LDA + h] = s->B[s->perm[t2] * LDA + h] * s->vals[t2];
  }
  for (int idx = tid; idx < 16 * 64; idx += THREADS) {
    int t2 = idx >> 6, m = idx & 63;
    const float* srow = s->S + s->perm[t2] * LDS_;
    float a = 0.f;
    for (int n = 0; n < 64; n++) {
      float sv = srow[n];
      if (sv != 0.f && ((s->masks[n] >> m) & 1)) a += sv;
    }
    s->A[(16 + t2) * LDA + m] = a;
  }
  __syncthreads();

  // adjn = T @ S[perm]^T, zero diag -> adjP
  {
    int t2 = tid >> 4, l = tid & 15;
    const float* sl = s->S + s->perm[l] * LDS_;
    const float* tr = s->A + (16 + t2) * LDA;
    float a = 0.f;
    for (int m = 0; m < 64; m++) a += tr[m] * sl[m];
    s->adjP[t2 * LDP + l] = (t2 == l) ? 0.f : a;
  }
  __syncthreads();
}

// ---------------------------------------------------------------------------
// ASAP pool 2 (N=16 -> 4, float adjP) (round 7 verbatim)
// ---------------------------------------------------------------------------
__device__ void pool2(Smem* s, const float* __restrict__ lw_t,
    const float* __restrict__ lb, const float* __restrict__ aw, float ab,
    const float* __restrict__ l1w, float l1b,
    const float* __restrict__ l2w,
    const float* __restrict__ l3w, float l3b)
{
  const int tid = threadIdx.x;
  const int w = tid >> 5, lane = tid & 31;

  if (tid < 16) {
    float d = s->adjP[tid * LDP + tid];
    if (d == 0.f) s->adjP[tid * LDP + tid] = 1.f;
  }
  __syncthreads();
  if (tid < 16) {
    float sum = 0.f;
    for (int j = 0; j < 16; j++) sum += s->adjP[tid * LDP + j];
    s->degw[tid] = sum;
  }

  // masked max-agg -> B
  {
    int row = tid >> 4, c0 = (tid & 15) * 4;
    float a[8];
#pragma unroll
    for (int c = 0; c < 8; c++) a[c] = -1e30f;
    for (int j = 0; j < 16; j++) {
      if (s->adjP[row * LDP + j] != 0.f) {
        V4 ra, rb;
        ra.f = *reinterpret_cast<const float4*>(s->A + j * LDA + c0);
        rb.f = *reinterpret_cast<const float4*>(s->A + j * LDA + c0 + 64);
        a[0]=fmaxf(a[0],ra.s[0]); a[1]=fmaxf(a[1],ra.s[1]);
        a[2]=fmaxf(a[2],ra.s[2]); a[3]=fmaxf(a[3],ra.s[3]);
        a[4]=fmaxf(a[4],rb.s[0]); a[5]=fmaxf(a[5],rb.s[1]);
        a[6]=fmaxf(a[6],rb.s[2]); a[7]=fmaxf(a[7],rb.s[3]);
      }
    }
    *reinterpret_cast<float4*>(s->B + row*LDA + c0) = make_float4(a[0],a[1],a[2],a[3]);
    *reinterpret_cast<float4*>(s->B + row*LDA + c0 + 64) = make_float4(a[4],a[5],a[6],a[7]);
  }
  __syncthreads();

  // XQ = B @ lw^T + lb -> B (K-split, 16 rows, 4-row tiles, round 7)
  {
    const int grp = tid >> 7, t = tid & 127;
    const int i0 = (t >> 4) * 4, c0 = (t & 15) * 8;
    const bool act = i0 < 16;
    u64 acc[4][4];
#pragma unroll
    for (int r = 0; r < 4; r++)
#pragma unroll
      for (int j = 0; j < 4; j++) acc[r][j] = 0ull;
    if (act) mm48g(acc, s->B, lw_t, i0, c0, grp ? 64 : 0, 64);
    __syncthreads();
    if (grp == 1 && act) storeT<4>(acc, s->B, i0, c0);
    __syncthreads();
    if (grp == 0 && act) combineT<4, false>(acc, s->B, s->B, i0, c0, lb);
  }
  __syncthreads();

  // s1/s2
  for (int d = w; d < 32; d += 8) {
    const float* row = (d < 16) ? (s->B + d * LDA) : (s->A + (d - 16) * LDA);
    const float* wv = (d < 16) ? aw : (aw + 128);
    float4 a = reinterpret_cast<const float4*>(row)[lane];
    float4 b = reinterpret_cast<const float4*>(wv)[lane];
    float dot = warp_red_sum(a.x*b.x + a.y*b.y + a.z*b.z + a.w*b.w);
    if (lane == 0) { if (d < 16) s->s1[d] = dot; else s->s2[d - 16] = dot; }
  }
  __syncthreads();

  // attention (warp per row, rows 0..15)
  for (int i = w; i < 16; i += 8) {
    float adjv = (lane < 16) ? s->adjP[i * LDP + lane] : 0.f;
    float e = s->s1[i] + ((lane < 16) ? s->s2[lane] : 0.f) + ab;
    e = (e > 0.f) ? e : SLOPE * e;
    float ev = (adjv != 0.f) ? e : -1e30f;
    float mx = ev;
#pragma unroll
    for (int o = 16; o; o >>= 1) mx = fmaxf(mx, __shfl_xor_sync(0xffffffffu, mx, o));
    float ex = (adjv != 0.f) ? __expf(ev - mx) : 0.f;
    float sum = warp_red_sum(ex);
    if (lane < 16) s->S[i * LDS_ + lane] = ex / sum;
  }
  __syncthreads();

  // XC = S @ X -> B
  {
    int row = tid >> 4, c0 = (tid & 15) * 4;
    float a[8] = {0,0,0,0,0,0,0,0};
    for (int j = 0; j < 16; j++) {
      float sv = s->S[row * LDS_ + j];
      if (sv != 0.f) {
        V4 ra, rb;
        ra.f = *reinterpret_cast<const float4*>(s->A + j * LDA + c0);
        rb.f = *reinterpret_cast<const float4*>(s->A + j * LDA + c0 + 64);
        a[0]=fmaf(sv,ra.s[0],a[0]); a[1]=fmaf(sv,ra.s[1],a[1]);
        a[2]=fmaf(sv,ra.s[2],a[2]); a[3]=fmaf(sv,ra.s[3],a[3]);
        a[4]=fmaf(sv,rb.s[0],a[4]); a[5]=fmaf(sv,rb.s[1],a[5]);
        a[6]=fmaf(sv,rb.s[2],a[6]); a[7]=fmaf(sv,rb.s[3],a[7]);
      }
    }
    *reinterpret_cast<float4*>(s->B + row*LDA + c0) = make_float4(a[0],a[1],a[2],a[3]);
    *reinterpret_cast<float4*>(s->B + row*LDA + c0 + 64) = make_float4(a[4],a[5],a[6],a[7]);
  }
  __syncthreads();

  // av/bv/cv
  for (int d = w; d < 48; d += 8) {
    int grp = d >> 4, i = d & 15;
    const float* wv = (grp == 0) ? l1w : (grp == 1) ? l2w : l3w;
    float4 a = reinterpret_cast<const float4*>(s->B + i * LDA)[lane];
    float4 b = reinterpret_cast<const float4*>(wv)[lane];
    float dot = warp_red_sum(a.x*b.x + a.y*b.y + a.z*b.z + a.w*b.w);
    if (lane == 0) {
      if (grp == 0)      s->av[i] = dot + l1b;
      else if (grp == 1) s->bv[i] = dot;
      else               s->cv[i] = dot + l3b;
    }
  }
  __syncthreads();

  if (tid < 16) {
    float a = 0.f;
    for (int j = 0; j < 16; j++) a += s->adjP[tid * LDP + j] * s->av[j];
    float f = a - s->bv[tid] * s->degw[tid] + s->cv[tid];
    s->fit[tid] = 1.f / (1.f + expf(-f));
  }
  __syncthreads();
  topk<4>(s, 16);
  __syncthreads();

  // XN = XC[perm]*vals -> A rows 0..3
  for (int idx = tid; idx < 4 * 128; idx += THREADS) {
    int t2 = idx >> 7, h = idx & 127;
    s->A[t2 * LDA + h] = s->B[s->perm[t2] * LDA + h] * s->vals[t2];
  }
  // T = S[perm] @ adjP -> A rows 16..19
  if (tid < 64) {
    int t2 = tid >> 4, m = tid & 15;
    const float* srow = s->S + s->perm[t2] * LDS_;
    float a = 0.f;
    for (int n = 0; n < 16; n++) a += srow[n] * s->adjP[n * LDP + m];
    s->A[(16 + t2) * LDA + m] = a;
  }
  __syncthreads();
  if (tid < 16) {
    int t2 = tid >> 2, l = tid & 3;
    const float* sl = s->S + s->perm[l] * LDS_;
    const float* tr = s->A + (16 + t2) * LDA;
    float a = 0.f;
    for (int m = 0; m < 16; m++) a += tr[m] * sl[m];
    s->adjP[t2 * LDP + l] = (t2 == l) ? 0.f : a;
  }
  __syncthreads();
}

// ---------------------------------------------------------------------------
// main kernel
// ---------------------------------------------------------------------------
__global__ void __launch_bounds__(THREADS, 2) asap_kernel(
    const float* __restrict__ x,          const float* __restrict__ adj,
    const float* __restrict__ conv1_br,
    const float* __restrict__ convs_br,
    const float* __restrict__ pool_lin_b,
    const float* __restrict__ pool_att_w, const float* __restrict__ pool_att_b,
    const float* __restrict__ pool_le1_w, const float* __restrict__ pool_le1_b,
    const float* __restrict__ pool_le2_w,
    const float* __restrict__ pool_le3_w, const float* __restrict__ pool_le3_b,
    const float* __restrict__ lin1_w,     const float* __restrict__ lin1_b,
    const float* __restrict__ lin2_w,     const float* __restrict__ lin2_b,
    float* __restrict__ out)
{
  extern __shared__ unsigned char smraw[];
  Smem* s = reinterpret_cast<Smem*>(smraw);
  const int g = blockIdx.x, tid = threadIdx.x;
  const int w = tid >> 5, lane = tid & 31;

  // load features + binary adjacency -> masks
  {
    const float4* xs = reinterpret_cast<const float4*>(x + (size_t)g * 8192);
#pragma unroll
    for (int i = 0; i < 8; i++) {
      int idx = tid + i * 256;
      int row = idx >> 5, c = (idx & 31) * 4;
      *reinterpret_cast<float4*>(s->A + row * LDA + c) = xs[idx];
    }
    if (tid < 64) {
      const float4* ar = reinterpret_cast<const float4*>(adj + (size_t)g * 4096 + tid * 64);
      u64 m = 0;
#pragma unroll
      for (int c = 0; c < 16; c++) {
        float4 v = __ldg(ar + c);
        if (v.x != 0.f) m |= 1ull << (c * 4 + 0);
        if (v.y != 0.f) m |= 1ull << (c * 4 + 1);
        if (v.z != 0.f) m |= 1ull << (c * 4 + 2);
        if (v.w != 0.f) m |= 1ull << (c * 4 + 3);
      }
      s->masks[tid] = m;
    }
  }
  __syncthreads();

  const float* W = g_WT;
  conv64(s, W + 0*16384, W + 1*16384, conv1_br);
  mean_pool(s, 64, 0);

  conv64(s, W + 2*16384, W + 6*16384, convs_br);
  mean_pool(s, 64, 1);

  pool1(s, W + 10*16384, pool_lin_b, pool_att_w, pool_att_b[0],
        pool_le1_w, pool_le1_b[0], pool_le2_w, pool_le3_w, pool_le3_b[0]);

  conv_small<16>(s, W + 3*16384, W + 7*16384, convs_br + 128);
  mean_pool(s, 16, 2);

  conv_small<16>(s, W + 4*16384, W + 8*16384, convs_br + 256);
  mean_pool(s, 16, 3);

  pool2(s, W + 11*16384, pool_lin_b + 128, pool_att_w + 256, pool_att_b[1],
        pool_le1_w + 128, pool_le1_b[1], pool_le2_w + 128,
        pool_le3_w + 128, pool_le3_b[1]);

  conv_small<4>(s, W + 5*16384, W + 9*16384, convs_br + 384);
  mean_pool(s, 4, 4);
  __syncthreads();   // xsum complete before MLP head reads it

  // MLP head
  for (int d = w; d < 128; d += 8) {
    const float4* zr = reinterpret_cast<const float4*>(s->xsum);
    const float4* wr = reinterpret_cast<const float4*>(lin1_w + d * 640);
    float a = 0.f;
#pragma unroll
    for (int c = 0; c < 5; c++) {
      float4 zc = zr[lane + 32 * c];
      float4 wc = __ldg(wr + lane + 32 * c);
      a += zc.x*wc.x + zc.y*wc.y + zc.z*wc.z + zc.w*wc.w;
    }
    a = warp_red_sum(a);
    if (lane == 0) s->zz[d] = fmaxf(a + lin1_b[d], 0.f);
  }
  __syncthreads();
  for (int d = w; d < 10; d += 8) {
    float4 zc = reinterpret_cast<const float4*>(s->zz)[lane];
    float4 wc = __ldg(reinterpret_cast<const float4*>(lin2_w + d * 128) + lane);
    float a = warp_red_sum(zc.x*wc.x + zc.y*wc.y + zc.z*wc.z + zc.w*wc.w);
    if (lane == 0) s->yy[d] = a + lin2_b[d];
  }
  __syncthreads();
  if (tid == 0) {
    float mx = -1e30f;
    for (int c = 0; c < 10; c++) mx = fmaxf(mx, s->yy[c]);
    float sum = 0.f;
    for (int c = 0; c < 10; c++) sum += expf(s->yy[c] - mx);
    s->lse = mx + logf(sum);
  }
  __syncthreads();
  if (tid < 10) out[g * 10 + tid] = s->yy[tid] - s->lse;
}

// ---------------------------------------------------------------------------
// prologue: transpose the 12 [128x128] weight matrices into g_WT
// ---------------------------------------------------------------------------
__global__ void transpose_k(
    const float* __restrict__ conv1_wr, const float* __restrict__ conv1_wroot,
    const float* __restrict__ convs_wr, const float* __restrict__ convs_wroot,
    const float* __restrict__ pool_lin_w)
{
  __shared__ float t[32][33];
  int mat = blockIdx.y;
  int tile = blockIdx.x;
  int tx = tile & 3, ty = tile >> 2;
  const float* src =
      (mat == 0) ? conv1_wr :
      (mat == 1) ? conv1_wroot :
      (mat < 6)  ? convs_wr + (mat - 2) * 16384 :
      (mat < 10) ? convs_wroot + (mat - 6) * 16384 :
                   pool_lin_w + (mat - 10) * 16384;
#pragma unroll
  for (int r = threadIdx.y; r < 32; r += 8)
    t[r][threadIdx.x] = src[(ty * 32 + r) * 128 + tx * 32 + threadIdx.x];
  __syncthreads();
#pragma unroll
  for (int r = threadIdx.y; r < 32; r += 8)
    g_WT[mat * 16384 + (tx * 32 + r) * 128 + ty * 32 + threadIdx.x] = t[threadIdx.x][r];
}

// ---------------------------------------------------------------------------
// launch
// ---------------------------------------------------------------------------
extern "C" void kernel_launch(void* const* d_in, const int* in_sizes, int n_in,
                              void* d_out, int out_size)
{
  const float* x           = (const float*)d_in[0];
  const float* adj         = (const float*)d_in[1];
  const float* conv1_wr    = (const float*)d_in[2];
  const float* conv1_br    = (const float*)d_in[3];
  const float* conv1_wroot = (const float*)d_in[4];
  const float* convs_wr    = (const float*)d_in[5];
  const float* convs_br    = (const float*)d_in[6];
  const float* convs_wroot = (const float*)d_in[7];
  const float* pool_lin_w  = (const float*)d_in[8];
  const float* pool_lin_b  = (const float*)d_in[9];
  const float* pool_att_w  = (const float*)d_in[10];
  const float* pool_att_b  = (const float*)d_in[11];
  const float* pool_le1_w  = (const float*)d_in[12];
  const float* pool_le1_b  = (const float*)d_in[13];
  const float* pool_le2_w  = (const float*)d_in[14];
  const float* pool_le3_w  = (const float*)d_in[15];
  const float* pool_le3_b  = (const float*)d_in[16];
  const float* lin1_w      = (const float*)d_in[17];
  const float* lin1_b      = (const float*)d_in[18];
  const float* lin2_w      = (const float*)d_in[19];
  const float* lin2_b      = (const float*)d_in[20];
  float* out = (float*)d_out;

  transpose_k<<<dim3(16, 12), dim3(32, 8)>>>(
      conv1_wr, conv1_wroot, convs_wr, convs_wroot, pool_lin_w);

  cudaFuncSetAttribute(asap_kernel, cudaFuncAttributeMaxDynamicSharedMemorySize,
                       (int)sizeof(Smem));
  asap_kernel<<<G_TOT, THREADS, sizeof(Smem)>>>(
      x, adj, conv1_br, convs_br,
      pool_lin_b, pool_att_w, pool_att_b,
      pool_le1_w, pool_le1_b, pool_le2_w, pool_le3_w, pool_le3_b,
      lin1_w, lin1_b, lin2_w, lin2_b, out);
}

// round 16
// speedup vs baseline: 1.4159x; 1.0033x over previous
#include <cuda_runtime.h>
#include <math.h>

// Net_ASAP fused pipeline, round 16 = round 15 (best passing, 407.6us)
// + output-side-safe micro-opts:
//   - mean_pool: float4-vectorized row-slice partials (4x fewer LDS)
//   - MLP-head lse: __expf/__logf (MUFU fast path)

#define THREADS 256
#define G_TOT 512
#define SLOPE 0.2f
#define LDA 132
#define LDS_ 68
#define LDP 17

typedef unsigned long long u64;

__device__ float g_WT[12 * 128 * 128];   // pre-transposed weights W^T[k][h]

__device__ __forceinline__ u64 bcast2(float v) {
  unsigned r = __float_as_uint(v);
  u64 d; asm("mov.b64 %0, {%1, %1};" : "=l"(d) : "r"(r));
  return d;
}
__device__ __forceinline__ u64 ffma2(u64 a, u64 b, u64 c) {
  u64 d; asm("fma.rn.f32x2 %0, %1, %2, %3;" : "=l"(d) : "l"(a), "l"(b), "l"(c));
  return d;
}
__device__ __forceinline__ u64 fadd2(u64 a, u64 b) {
  u64 d; asm("add.rn.f32x2 %0, %1, %2;" : "=l"(d) : "l"(a), "l"(b));
  return d;
}
__device__ __forceinline__ u64 fmul2(u64 a, u64 b) {
  u64 d; asm("mul.rn.f32x2 %0, %1, %2;" : "=l"(d) : "l"(a), "l"(b));
  return d;
}

union V4 { float4 f; u64 p[2]; float s[4]; };

struct Smem {
  float A[64 * LDA];        // features (in-place)
  float B[64 * LDA];        // agg / xq / xc scratch
  float S[64 * LDS_];       // attention matrix
  u64   masks[64];          // binary adjacency, N=64 phase
  float adjP[16 * LDP];     // pooled float adjacency, N<=16
  float part4[8 * 128];     // mean-pool slice partials
  float degw[64], s1[64], s2[64], fit[64];
  float av[64], bv[64], cv[64], vals[64];
  int   perm[64];
  float xsum[640];
  float zz[128], yy[16], lse;
};

// ---------------------------------------------------------------------------
// 8x8 GEMM core: acc[r][0..3] += L[(i0+r)][k] * W[k][c0..c0+7], W in GLOBAL
// ---------------------------------------------------------------------------
__device__ __forceinline__ void mm88(u64 (&acc)[8][4],
    const float* __restrict__ L, const float* __restrict__ W,
    int i0, int c0, int k0, int K)
{
  const float* Lp = L + i0 * LDA + k0;
  const float* Wp = W + k0 * 128 + c0;
#pragma unroll 1
  for (int k = 0; k < K; k += 4) {
    V4 wv[4][2];
#pragma unroll
    for (int q = 0; q < 4; q++) {
      wv[q][0].f = __ldg(reinterpret_cast<const float4*>(Wp + (k + q) * 128));
      wv[q][1].f = __ldg(reinterpret_cast<const float4*>(Wp + (k + q) * 128 + 4));
    }
#pragma unroll
    for (int r = 0; r < 8; r++) {
      V4 lv; lv.f = *reinterpret_cast<const float4*>(Lp + r * LDA + k);
#pragma unroll
      for (int q = 0; q < 4; q++) {
        u64 lp = bcast2(lv.s[q]);
        acc[r][0] = ffma2(lp, wv[q][0].p[0], acc[r][0]);
        acc[r][1] = ffma2(lp, wv[q][0].p[1], acc[r][1]);
        acc[r][2] = ffma2(lp, wv[q][1].p[0], acc[r][2]);
        acc[r][3] = ffma2(lp, wv[q][1].p[1], acc[r][3]);
      }
    }
  }
}

// 4x8 variant for small-N convs / pool XQ (round 7 mapping, unroll 2)
__device__ __forceinline__ void mm48g(u64 (&acc)[4][4],
    const float* __restrict__ L, const float* __restrict__ W,
    int i0, int c0, int k0, int K)
{
  const float* Lp = L + i0 * LDA + k0;
  const float* Wp = W + k0 * 128 + c0;
#pragma unroll 2
  for (int k = 0; k < K; k += 4) {
    V4 wv[4][2];
#pragma unroll
    for (int q = 0; q < 4; q++) {
      wv[q][0].f = __ldg(reinterpret_cast<const float4*>(Wp + (k + q) * 128));
      wv[q][1].f = __ldg(reinterpret_cast<const float4*>(Wp + (k + q) * 128 + 4));
    }
#pragma unroll
    for (int r = 0; r < 4; r++) {
      V4 lv; lv.f = *reinterpret_cast<const float4*>(Lp + r * LDA + k);
#pragma unroll
      for (int q = 0; q < 4; q++) {
        u64 lp = bcast2(lv.s[q]);
        acc[r][0] = ffma2(lp, wv[q][0].p[0], acc[r][0]);
        acc[r][1] = ffma2(lp, wv[q][0].p[1], acc[r][1]);
        acc[r][2] = ffma2(lp, wv[q][1].p[0], acc[r][2]);
        acc[r][3] = ffma2(lp, wv[q][1].p[1], acc[r][3]);
      }
    }
  }
}

template<int RI>
__device__ __forceinline__ void storeT(const u64 (&acc)[RI][4],
    float* O, int i0, int c0)
{
#pragma unroll
  for (int r = 0; r < RI; r++) {
    V4 a, b;
    a.p[0] = acc[r][0]; a.p[1] = acc[r][1];
    b.p[0] = acc[r][2]; b.p[1] = acc[r][3];
    *reinterpret_cast<float4*>(O + (i0 + r) * LDA + c0)     = a.f;
    *reinterpret_cast<float4*>(O + (i0 + r) * LDA + c0 + 4) = b.f;
  }
}

// O_tile = acc + P_tile + bias (optional relu)
template<int RI, bool RELU>
__device__ __forceinline__ void combineT(const u64 (&acc)[RI][4],
    const float* __restrict__ P, float* __restrict__ O,
    int i0, int c0, const float* __restrict__ bias)
{
  float4 b1 = *reinterpret_cast<const float4*>(bias + c0);
  float4 b2 = *reinterpret_cast<const float4*>(bias + c0 + 4);
#pragma unroll
  for (int r = 0; r < RI; r++) {
    V4 a, b, o1, o2;
    a.p[0] = acc[r][0]; a.p[1] = acc[r][1];
    b.p[0] = acc[r][2]; b.p[1] = acc[r][3];
    o1.f = *reinterpret_cast<const float4*>(P + (i0 + r) * LDA + c0);
    o2.f = *reinterpret_cast<const float4*>(P + (i0 + r) * LDA + c0 + 4);
    a.f.x += o1.f.x + b1.x; a.f.y += o1.f.y + b1.y;
    a.f.z += o1.f.z + b1.z; a.f.w += o1.f.w + b1.w;
    b.f.x += o2.f.x + b2.x; b.f.y += o2.f.y + b2.y;
    b.f.z += o2.f.z + b2.z; b.f.w += o2.f.w + b2.w;
    if (RELU) {
      a.f.x = fmaxf(a.f.x, 0.f); a.f.y = fmaxf(a.f.y, 0.f);
      a.f.z = fmaxf(a.f.z, 0.f); a.f.w = fmaxf(a.f.w, 0.f);
      b.f.x = fmaxf(b.f.x, 0.f); b.f.y = fmaxf(b.f.y, 0.f);
      b.f.z = fmaxf(b.f.z, 0.f); b.f.w = fmaxf(b.f.w, 0.f);
    }
    *reinterpret_cast<float4*>(O + (i0 + r) * LDA + c0)     = a.f;
    *reinterpret_cast<float4*>(O + (i0 + r) * LDA + c0 + 4) = b.f;
  }
}

__device__ __forceinline__ float warp_red_sum(float v) {
#pragma unroll
  for (int o = 16; o; o >>= 1) v += __shfl_xor_sync(0xffffffffu, v, o);
  return v;
}

// ---------------------------------------------------------------------------
// conv, N=64 (round 7 verbatim)
// ---------------------------------------------------------------------------
__device__ void conv64(Smem* s, const float* __restrict__ wr_t,
    const float* __restrict__ wroot_t, const float* __restrict__ br)
{
  const int tid = threadIdx.x;
  // agg = (masks @ A)/cnt -> B : 4 rows x 8 cols per thread (bit iteration)
  {
    const int i0 = (tid >> 4) * 4, c0 = (tid & 15) * 4;
    u64 m0 = s->masks[i0], m1 = s->masks[i0+1], m2 = s->masks[i0+2], m3 = s->masks[i0+3];
    u64 a[4][4];
#pragma unroll
    for (int r = 0; r < 4; r++)
#pragma unroll
      for (int j = 0; j < 4; j++) a[r][j] = 0ull;
    u64 mm = m0 | m1 | m2 | m3;
    const float* Ap = s->A + c0;
    while (mm) {
      int j = __ffsll((long long)mm) - 1;
      mm &= mm - 1;
      V4 ra, rb;
      ra.f = *reinterpret_cast<const float4*>(Ap + j * LDA);
      rb.f = *reinterpret_cast<const float4*>(Ap + j * LDA + 64);
      if ((m0 >> j) & 1) { a[0][0]=fadd2(a[0][0],ra.p[0]); a[0][1]=fadd2(a[0][1],ra.p[1]);
                           a[0][2]=fadd2(a[0][2],rb.p[0]); a[0][3]=fadd2(a[0][3],rb.p[1]); }
      if ((m1 >> j) & 1) { a[1][0]=fadd2(a[1][0],ra.p[0]); a[1][1]=fadd2(a[1][1],ra.p[1]);
                           a[1][2]=fadd2(a[1][2],rb.p[0]); a[1][3]=fadd2(a[1][3],rb.p[1]); }
      if ((m2 >> j) & 1) { a[2][0]=fadd2(a[2][0],ra.p[0]); a[2][1]=fadd2(a[2][1],ra.p[1]);
                           a[2][2]=fadd2(a[2][2],rb.p[0]); a[2][3]=fadd2(a[2][3],rb.p[1]); }
      if ((m3 >> j) & 1) { a[3][0]=fadd2(a[3][0],ra.p[0]); a[3][1]=fadd2(a[3][1],ra.p[1]);
                           a[3][2]=fadd2(a[3][2],rb.p[0]); a[3][3]=fadd2(a[3][3],rb.p[1]); }
    }
    u64 msk[4] = {m0, m1, m2, m3};
#pragma unroll
    for (int r = 0; r < 4; r++) {
      u64 rc = bcast2(1.f / fmaxf((float)__popcll(msk[r]), 1.f));
      V4 o;
      o.p[0] = fmul2(a[r][0], rc); o.p[1] = fmul2(a[r][1], rc);
      *reinterpret_cast<float4*>(s->B + (i0 + r) * LDA + c0) = o.f;
      o.p[0] = fmul2(a[r][2], rc); o.p[1] = fmul2(a[r][3], rc);
      *reinterpret_cast<float4*>(s->B + (i0 + r) * LDA + c0 + 64) = o.f;
    }
  }
  __syncthreads();

  const int grp = tid >> 7, t = tid & 127;
  const int i0 = (t >> 4) * 8, c0 = (t & 15) * 8;
  u64 acc[8][4];
#pragma unroll
  for (int r = 0; r < 8; r++)
#pragma unroll
    for (int j = 0; j < 4; j++) acc[r][j] = 0ull;
  if (grp == 0) mm88(acc, s->B, wr_t, i0, c0, 0, 128);
  else          mm88(acc, s->A, wroot_t, i0, c0, 0, 128);
  __syncthreads();
  if (grp == 1) storeT<8>(acc, s->B, i0, c0);
  __syncthreads();
  if (grp == 0) combineT<8, true>(acc, s->B, s->A, i0, c0, br);
  __syncthreads();
}

// ---------------------------------------------------------------------------
// conv, N<=16 (round 7 verbatim)
// ---------------------------------------------------------------------------
template<int NI>
__device__ void conv_small(Smem* s, const float* __restrict__ wr_t,
    const float* __restrict__ wroot_t, const float* __restrict__ br)
{
  const int tid = threadIdx.x;
  if (tid < NI * 16) {
    int row = tid >> 4, c0 = (tid & 15) * 4;
    float a[8] = {0,0,0,0,0,0,0,0};
    int cnt = 0;
    for (int j = 0; j < NI; j++) {
      float v = s->adjP[row * LDP + j];
      if (v != 0.f) {
        cnt++;
        V4 ra, rb;
        ra.f = *reinterpret_cast<const float4*>(s->A + j * LDA + c0);
        rb.f = *reinterpret_cast<const float4*>(s->A + j * LDA + c0 + 64);
        a[0]=fmaf(v,ra.s[0],a[0]); a[1]=fmaf(v,ra.s[1],a[1]);
        a[2]=fmaf(v,ra.s[2],a[2]); a[3]=fmaf(v,ra.s[3],a[3]);
        a[4]=fmaf(v,rb.s[0],a[4]); a[5]=fmaf(v,rb.s[1],a[5]);
        a[6]=fmaf(v,rb.s[2],a[6]); a[7]=fmaf(v,rb.s[3],a[7]);
      }
    }
    float rc = 1.f / fmaxf((float)cnt, 1.f);
    *reinterpret_cast<float4*>(s->B + row * LDA + c0) =
        make_float4(a[0]*rc, a[1]*rc, a[2]*rc, a[3]*rc);
    *reinterpret_cast<float4*>(s->B + row * LDA + c0 + 64) =
        make_float4(a[4]*rc, a[5]*rc, a[6]*rc, a[7]*rc);
  }
  __syncthreads();

  const int grp = tid >> 7, t = tid & 127;
  const int i0 = (t >> 4) * 4, c0 = (t & 15) * 8;
  const bool act = i0 < NI;
  u64 acc[4][4];
#pragma unroll
  for (int r = 0; r < 4; r++)
#pragma unroll
    for (int j = 0; j < 4; j++) acc[r][j] = 0ull;
  if (act) {
    if (grp == 0) mm48g(acc, s->B, wr_t, i0, c0, 0, 128);
    else          mm48g(acc, s->A, wroot_t, i0, c0, 0, 128);
  }
  __syncthreads();
  if (grp == 1 && act) storeT<4>(acc, s->B, i0, c0);
  __syncthreads();
  if (grp == 0 && act) combineT<4, true>(acc, s->B, s->A, i0, c0, br);
  __syncthreads();
}

// ---------------------------------------------------------------------------
// mean pool of A rows -> xsum[stage]  (float4-vectorized slice partials;
// xsum is output-side only, so the changed summation order is safe)
// ---------------------------------------------------------------------------
__device__ void mean_pool(Smem* s, int NI, int stage) {
  const int tid = threadIdx.x;
  const int slice = tid >> 5;       // 0..7
  const int cq = tid & 31;          // 4-col group
  float4 acc = make_float4(0.f, 0.f, 0.f, 0.f);
  for (int r = slice; r < NI; r += 8) {
    float4 v = *reinterpret_cast<const float4*>(s->A + r * LDA + cq * 4);
    acc.x += v.x; acc.y += v.y; acc.z += v.z; acc.w += v.w;
  }
  *reinterpret_cast<float4*>(s->part4 + slice * 128 + cq * 4) = acc;
  __syncthreads();
  if (tid < 128) {
    float a = 0.f;
#pragma unroll
    for (int sl = 0; sl < 8; sl++) a += s->part4[sl * 128 + tid];
    s->xsum[stage * 128 + tid] = a * (1.f / (float)NI);
  }
}

// ---------------------------------------------------------------------------
// top-k (warp 0)
// ---------------------------------------------------------------------------
template<int KK>
__device__ void topk(Smem* s, int NI) {
  if (threadIdx.x < 32) {
    int lane = threadIdx.x;
    float v0 = (lane < NI) ? s->fit[lane] : -2.f;
    float v1 = (lane + 32 < NI) ? s->fit[lane + 32] : -2.f;
#pragma unroll 1
    for (int t = 0; t < KK; t++) {
      float bv; int bi;
      if (v0 >= v1) { bv = v0; bi = lane; } else { bv = v1; bi = lane + 32; }
#pragma unroll
      for (int o = 16; o; o >>= 1) {
        float ov = __shfl_xor_sync(0xffffffffu, bv, o);
        int   oi = __shfl_xor_sync(0xffffffffu, bi, o);
        if (ov > bv || (ov == bv && oi < bi)) { bv = ov; bi = oi; }
      }
      if (lane == 0) { s->perm[t] = bi; s->vals[t] = bv; }
      if (bi == lane) v0 = -2.f;
      if (bi == lane + 32) v1 = -2.f;
    }
  }
}

// ---------------------------------------------------------------------------
// ASAP pool 1 (N=64 -> 16, bitmask adjacency) (round 7 verbatim)
// ---------------------------------------------------------------------------
__device__ void pool1(Smem* s, const float* __restrict__ lw_t,
    const float* __restrict__ lb, const float* __restrict__ aw, float ab,
    const float* __restrict__ l1w, float l1b,
    const float* __restrict__ l2w,
    const float* __restrict__ l3w, float l3b)
{
  const int tid = threadIdx.x;
  const int w = tid >> 5, lane = tid & 31;

  if (tid < 64) s->masks[tid] |= (1ull << tid);
  __syncthreads();
  if (tid < 64) s->degw[tid] = (float)__popcll(s->masks[tid]);

  // masked max-agg -> B : 4 rows x 8 cols
  {
    const int i0 = (tid >> 4) * 4, c0 = (tid & 15) * 4;
    u64 msk[4] = {s->masks[i0], s->masks[i0+1], s->masks[i0+2], s->masks[i0+3]};
    float a[4][8];
#pragma unroll
    for (int r = 0; r < 4; r++)
#pragma unroll
      for (int c = 0; c < 8; c++) a[r][c] = -1e30f;
    u64 mm = msk[0] | msk[1] | msk[2] | msk[3];
    const float* Ap = s->A + c0;
    while (mm) {
      int j = __ffsll((long long)mm) - 1;
      mm &= mm - 1;
      V4 ra, rb;
      ra.f = *reinterpret_cast<const float4*>(Ap + j * LDA);
      rb.f = *reinterpret_cast<const float4*>(Ap + j * LDA + 64);
#pragma unroll
      for (int r = 0; r < 4; r++) {
        if ((msk[r] >> j) & 1) {
          a[r][0]=fmaxf(a[r][0],ra.s[0]); a[r][1]=fmaxf(a[r][1],ra.s[1]);
          a[r][2]=fmaxf(a[r][2],ra.s[2]); a[r][3]=fmaxf(a[r][3],ra.s[3]);
          a[r][4]=fmaxf(a[r][4],rb.s[0]); a[r][5]=fmaxf(a[r][5],rb.s[1]);
          a[r][6]=fmaxf(a[r][6],rb.s[2]); a[r][7]=fmaxf(a[r][7],rb.s[3]);
        }
      }
    }
#pragma unroll
    for (int r = 0; r < 4; r++) {
      *reinterpret_cast<float4*>(s->B + (i0+r)*LDA + c0) =
          make_float4(a[r][0], a[r][1], a[r][2], a[r][3]);
      *reinterpret_cast<float4*>(s->B + (i0+r)*LDA + c0 + 64) =
          make_float4(a[r][4], a[r][5], a[r][6], a[r][7]);
    }
  }
  __syncthreads();

  // XQ = B @ lw^T + lb -> B (K-split dual group, round 7)
  {
    const int grp = tid >> 7, t = tid & 127;
    const int i0 = (t >> 4) * 8, c0 = (t & 15) * 8;
    u64 acc[8][4];
#pragma unroll
    for (int r = 0; r < 8; r++)
#pragma unroll
      for (int j = 0; j < 4; j++) acc[r][j] = 0ull;
    mm88(acc, s->B, lw_t, i0, c0, grp ? 64 : 0, 64);
    __syncthreads();
    if (grp == 1) storeT<8>(acc, s->B, i0, c0);
    __syncthreads();
    if (grp == 0) combineT<8, false>(acc, s->B, s->B, i0, c0, lb);
  }
  __syncthreads();

  // s1 = XQ.aw[:128] (B), s2 = X.aw[128:] (A)
  for (int d = w; d < 128; d += 8) {
    const float* row = (d < 64) ? (s->B + d * LDA) : (s->A + (d - 64) * LDA);
    const float* wv = (d < 64) ? aw : (aw + 128);
    float4 a = reinterpret_cast<const float4*>(row)[lane];
    float4 b = reinterpret_cast<const float4*>(wv)[lane];
    float dot = warp_red_sum(a.x*b.x + a.y*b.y + a.z*b.z + a.w*b.w);
    if (lane == 0) { if (d < 64) s->s1[d] = dot; else s->s2[d - 64] = dot; }
  }
  __syncthreads();

  // masked softmax -> S
  for (int i = w; i < 64; i += 8) {
    u64 mi = s->masks[i];
    float s1i = s->s1[i];
    bool vA = (mi >> lane) & 1, vB = (mi >> (lane + 32)) & 1;
    float e0 = s1i + s->s2[lane] + ab;       e0 = (e0 > 0.f) ? e0 : SLOPE * e0;
    float e1 = s1i + s->s2[lane + 32] + ab;  e1 = (e1 > 0.f) ? e1 : SLOPE * e1;
    float ev0 = vA ? e0 : -1e30f, ev1 = vB ? e1 : -1e30f;
    float mx = fmaxf(ev0, ev1);
#pragma unroll
    for (int o = 16; o; o >>= 1) mx = fmaxf(mx, __shfl_xor_sync(0xffffffffu, mx, o));
    float ex0 = vA ? __expf(ev0 - mx) : 0.f;
    float ex1 = vB ? __expf(ev1 - mx) : 0.f;
    float sum = warp_red_sum(ex0 + ex1);
    float inv = 1.f / sum;
    s->S[i * LDS_ + lane]      = ex0 * inv;
    s->S[i * LDS_ + lane + 32] = ex1 * inv;
  }
  __syncthreads();

  // XC = S @ X -> B : 4 rows x 8 cols, zero-skip
  {
    const int i0 = (tid >> 4) * 4, c0 = (tid & 15) * 4;
    u64 a[4][4];
#pragma unroll
    for (int r = 0; r < 4; r++)
#pragma unroll
      for (int j = 0; j < 4; j++) a[r][j] = 0ull;
    for (int k = 0; k < 64; k++) {
      float l0 = s->S[i0*LDS_ + k], l1 = s->S[(i0+1)*LDS_ + k];
      float l2 = s->S[(i0+2)*LDS_ + k], l3 = s->S[(i0+3)*LDS_ + k];
      if (l0 == 0.f && l1 == 0.f && l2 == 0.f && l3 == 0.f) continue;
      V4 ra, rb;
      ra.f = *reinterpret_cast<const float4*>(s->A + k * LDA + c0);
      rb.f = *reinterpret_cast<const float4*>(s->A + k * LDA + c0 + 64);
      float lv[4] = {l0, l1, l2, l3};
#pragma unroll
      for (int r = 0; r < 4; r++) {
        if (lv[r] != 0.f) {
          u64 lp = bcast2(lv[r]);
          a[r][0]=ffma2(lp,ra.p[0],a[r][0]); a[r][1]=ffma2(lp,ra.p[1],a[r][1]);
          a[r][2]=ffma2(lp,rb.p[0],a[r][2]); a[r][3]=ffma2(lp,rb.p[1],a[r][3]);
        }
      }
    }
#pragma unroll
    for (int r = 0; r < 4; r++) {
      V4 o;
      o.p[0]=a[r][0]; o.p[1]=a[r][1];
      *reinterpret_cast<float4*>(s->B + (i0+r)*LDA + c0) = o.f;
      o.p[0]=a[r][2]; o.p[1]=a[r][3];
      *reinterpret_cast<float4*>(s->B + (i0+r)*LDA + c0 + 64) = o.f;
    }
  }
  __syncthreads();

  // av/bv/cv dots
  for (int d = w; d < 192; d += 8) {
    int grp = d >> 6, i = d & 63;
    const float* wv = (grp == 0) ? l1w : (grp == 1) ? l2w : l3w;
    float4 a = reinterpret_cast<const float4*>(s->B + i * LDA)[lane];
    float4 b = reinterpret_cast<const float4*>(wv)[lane];
    float dot = warp_red_sum(a.x*b.x + a.y*b.y + a.z*b.z + a.w*b.w);
    if (lane == 0) {
      if (grp == 0)      s->av[i] = dot + l1b;
      else if (grp == 1) s->bv[i] = dot;
      else               s->cv[i] = dot + l3b;
    }
  }
  __syncthreads();

  if (tid < 64) {
    u64 mm = s->masks[tid];
    float a = 0.f;
    while (mm) {
      int j = __ffsll((long long)mm) - 1;
      mm &= mm - 1;
      a += s->av[j];
    }
    float f = a - s->bv[tid] * s->degw[tid] + s->cv[tid];
    s->fit[tid] = 1.f / (1.f + expf(-f));
  }
  __syncthreads();
  topk<16>(s, 64);
  __syncthreads();

  // XN = XC[perm]*vals -> A rows 0..15 ; T = S[perm]@adj1 -> A rows 16..31
  for (int idx = tid; idx < 16 * 128; idx += THREADS) {
    int t2 = idx >> 7, h = idx & 127;
    s->A[t2 * LDA + h] = s->B[s->perm[t2] * LDA + h] * s->vals[t2];
  }
  for (int idx = tid; idx < 16 * 64; idx += THREADS) {
    int t2 = idx >> 6, m = idx & 63;
    const float* srow = s->S + s->perm[t2] * LDS_;
    float a = 0.f;
    for (int n = 0; n < 64; n++) {
      float sv = srow[n];
      if (sv != 0.f && ((s->masks[n] >> m) & 1)) a += sv;
    }
    s->A[(16 + t2) * LDA + m] = a;
  }
  __syncthreads();

  // adjn = T @ S[perm]^T, zero diag -> adjP
  {
    int t2 = tid >> 4, l = tid & 15;
    const float* sl = s->S + s->perm[l] * LDS_;
    const float* tr = s->A + (16 + t2) * LDA;
    float a = 0.f;
    for (int m = 0; m < 64; m++) a += tr[m] * sl[m];
    s->adjP[t2 * LDP + l] = (t2 == l) ? 0.f : a;
  }
  __syncthreads();
}

// ---------------------------------------------------------------------------
// ASAP pool 2 (N=16 -> 4, float adjP) (round 7 verbatim)
// ---------------------------------------------------------------------------
__device__ void pool2(Smem* s, const float* __restrict__ lw_t,
    const float* __restrict__ lb, const float* __restrict__ aw, float ab,
    const float* __restrict__ l1w, float l1b,
    const float* __restrict__ l2w,
    const float* __restrict__ l3w, float l3b)
{
  const int tid = threadIdx.x;
  const int w = tid >> 5, lane = tid & 31;

  if (tid < 16) {
    float d = s->adjP[tid * LDP + tid];
    if (d == 0.f) s->adjP[tid * LDP + tid] = 1.f;
  }
  __syncthreads();
  if (tid < 16) {
    float sum = 0.f;
    for (int j = 0; j < 16; j++) sum += s->adjP[tid * LDP + j];
    s->degw[tid] = sum;
  }

  // masked max-agg -> B
  {
    int row = tid >> 4, c0 = (tid & 15) * 4;
    float a[8];
#pragma unroll
    for (int c = 0; c < 8; c++) a[c] = -1e30f;
    for (int j = 0; j < 16; j++) {
      if (s->adjP[row * LDP + j] != 0.f) {
        V4 ra, rb;
        ra.f = *reinterpret_cast<const float4*>(s->A + j * LDA + c0);
        rb.f = *reinterpret_cast<const float4*>(s->A + j * LDA + c0 + 64);
        a[0]=fmaxf(a[0],ra.s[0]); a[1]=fmaxf(a[1],ra.s[1]);
        a[2]=fmaxf(a[2],ra.s[2]); a[3]=fmaxf(a[3],ra.s[3]);
        a[4]=fmaxf(a[4],rb.s[0]); a[5]=fmaxf(a[5],rb.s[1]);
        a[6]=fmaxf(a[6],rb.s[2]); a[7]=fmaxf(a[7],rb.s[3]);
      }
    }
    *reinterpret_cast<float4*>(s->B + row*LDA + c0) = make_float4(a[0],a[1],a[2],a[3]);
    *reinterpret_cast<float4*>(s->B + row*LDA + c0 + 64) = make_float4(a[4],a[5],a[6],a[7]);
  }
  __syncthreads();

  // XQ = B @ lw^T + lb -> B (K-split, 16 rows, 4-row tiles, round 7)
  {
    const int grp = tid >> 7, t = tid & 127;
    const int i0 = (t >> 4) * 4, c0 = (t & 15) * 8;
    const bool act = i0 < 16;
    u64 acc[4][4];
#pragma unroll
    for (int r = 0; r < 4; r++)
#pragma unroll
      for (int j = 0; j < 4; j++) acc[r][j] = 0ull;
    if (act) mm48g(acc, s->B, lw_t, i0, c0, grp ? 64 : 0, 64);
    __syncthreads();
    if (grp == 1 && act) storeT<4>(acc, s->B, i0, c0);
    __syncthreads();
    if (grp == 0 && act) combineT<4, false>(acc, s->B, s->B, i0, c0, lb);
  }
  __syncthreads();

  // s1/s2
  for (int d = w; d < 32; d += 8) {
    const float* row = (d < 16) ? (s->B + d * LDA) : (s->A + (d - 16) * LDA);
    const float* wv = (d < 16) ? aw : (aw + 128);
    float4 a = reinterpret_cast<const float4*>(row)[lane];
    float4 b = reinterpret_cast<const float4*>(wv)[lane];
    float dot = warp_red_sum(a.x*b.x + a.y*b.y + a.z*b.z + a.w*b.w);
    if (lane == 0) { if (d < 16) s->s1[d] = dot; else s->s2[d - 16] = dot; }
  }
  __syncthreads();

  // attention (warp per row, rows 0..15)
  for (int i = w; i < 16; i += 8) {
    float adjv = (lane < 16) ? s->adjP[i * LDP + lane] : 0.f;
    float e = s->s1[i] + ((lane < 16) ? s->s2[lane] : 0.f) + ab;
    e = (e > 0.f) ? e : SLOPE * e;
    float ev = (adjv != 0.f) ? e : -1e30f;
    float mx = ev;
#pragma unroll
    for (int o = 16; o; o >>= 1) mx = fmaxf(mx, __shfl_xor_sync(0xffffffffu, mx, o));
    float ex = (adjv != 0.f) ? __expf(ev - mx) : 0.f;
    float sum = warp_red_sum(ex);
    if (lane < 16) s->S[i * LDS_ + lane] = ex / sum;
  }
  __syncthreads();

  // XC = S @ X -> B
  {
    int row = tid >> 4, c0 = (tid & 15) * 4;
    float a[8] = {0,0,0,0,0,0,0,0};
    for (int j = 0; j < 16; j++) {
      float sv = s->S[row * LDS_ + j];
      if (sv != 0.f) {
        V4 ra, rb;
        ra.f = *reinterpret_cast<const float4*>(s->A + j * LDA + c0);
        rb.f = *reinterpret_cast<const float4*>(s->A + j * LDA + c0 + 64);
        a[0]=fmaf(sv,ra.s[0],a[0]); a[1]=fmaf(sv,ra.s[1],a[1]);
        a[2]=fmaf(sv,ra.s[2],a[2]); a[3]=fmaf(sv,ra.s[3],a[3]);
        a[4]=fmaf(sv,rb.s[0],a[4]); a[5]=fmaf(sv,rb.s[1],a[5]);
        a[6]=fmaf(sv,rb.s[2],a[6]); a[7]=fmaf(sv,rb.s[3],a[7]);
      }
    }
    *reinterpret_cast<float4*>(s->B + row*LDA + c0) = make_float4(a[0],a[1],a[2],a[3]);
    *reinterpret_cast<float4*>(s->B + row*LDA + c0 + 64) = make_float4(a[4],a[5],a[6],a[7]);
  }
  __syncthreads();

  // av/bv/cv
  for (int d = w; d < 48; d += 8) {
    int grp = d >> 4, i = d & 15;
    const float* wv = (grp == 0) ? l1w : (grp == 1) ? l2w : l3w;
    float4 a = reinterpret_cast<const float4*>(s->B + i * LDA)[lane];
    float4 b = reinterpret_cast<const float4*>(wv)[lane];
    float dot = warp_red_sum(a.x*b.x + a.y*b.y + a.z*b.z + a.w*b.w);
    if (lane == 0) {
      if (grp == 0)      s->av[i] = dot + l1b;
      else if (grp == 1) s->bv[i] = dot;
      else               s->cv[i] = dot + l3b;
    }
  }
  __syncthreads();

  if (tid < 16) {
    float a = 0.f;
    for (int j = 0; j < 16; j++) a += s->adjP[tid * LDP + j] * s->av[j];
    float f = a - s->bv[tid] * s->degw[tid] + s->cv[tid];
    s->fit[tid] = 1.f / (1.f + expf(-f));
  }
  __syncthreads();
  topk<4>(s, 16);
  __syncthreads();

  // XN = XC[perm]*vals -> A rows 0..3
  for (int idx = tid; idx < 4 * 128; idx += THREADS) {
    int t2 = idx >> 7, h = idx & 127;
    s->A[t2 * LDA + h] = s->B[s->perm[t2] * LDA + h] * s->vals[t2];
  }
  // T = S[perm] @ adjP -> A rows 16..19
  if (tid < 64) {
    int t2 = tid >> 4, m = tid & 15;
    const float* srow = s->S + s->perm[t2] * LDS_;
    float a = 0.f;
    for (int n = 0; n < 16; n++) a += srow[n] * s->adjP[n * LDP + m];
    s->A[(16 + t2) * LDA + m] = a;
  }
  __syncthreads();
  if (tid < 16) {
    int t2 = tid >> 2, l = tid & 3;
    const float* sl = s->S + s->perm[l] * LDS_;
    const float* tr = s->A + (16 + t2) * LDA;
    float a = 0.f;
    for (int m = 0; m < 16; m++) a += tr[m] * sl[m];
    s->adjP[t2 * LDP + l] = (t2 == l) ? 0.f : a;
  }
  __syncthreads();
}

// ---------------------------------------------------------------------------
// main kernel
// ---------------------------------------------------------------------------
__global__ void __launch_bounds__(THREADS, 2) asap_kernel(
    const float* __restrict__ x,          const float* __restrict__ adj,
    const float* __restrict__ conv1_br,
    const float* __restrict__ convs_br,
    const float* __restrict__ pool_lin_b,
    const float* __restrict__ pool_att_w, const float* __restrict__ pool_att_b,
    const float* __restrict__ pool_le1_w, const float* __restrict__ pool_le1_b,
    const float* __restrict__ pool_le2_w,
    const float* __restrict__ pool_le3_w, const float* __restrict__ pool_le3_b,
    const float* __restrict__ lin1_w,     const float* __restrict__ lin1_b,
    const float* __restrict__ lin2_w,     const float* __restrict__ lin2_b,
    float* __restrict__ out)
{
  extern __shared__ unsigned char smraw[];
  Smem* s = reinterpret_cast<Smem*>(smraw);
  const int g = blockIdx.x, tid = threadIdx.x;
  const int w = tid >> 5, lane = tid & 31;

  // load features + binary adjacency -> masks
  {
    const float4* xs = reinterpret_cast<const float4*>(x + (size_t)g * 8192);
#pragma unroll
    for (int i = 0; i < 8; i++) {
      int idx = tid + i * 256;
      int row = idx >> 5, c = (idx & 31) * 4;
      *reinterpret_cast<float4*>(s->A + row * LDA + c) = xs[idx];
    }
    if (tid < 64) {
      const float4* ar = reinterpret_cast<const float4*>(adj + (size_t)g * 4096 + tid * 64);
      u64 m = 0;
#pragma unroll
      for (int c = 0; c < 16; c++) {
        float4 v = __ldg(ar + c);
        if (v.x != 0.f) m |= 1ull << (c * 4 + 0);
        if (v.y != 0.f) m |= 1ull << (c * 4 + 1);
        if (v.z != 0.f) m |= 1ull << (c * 4 + 2);
        if (v.w != 0.f) m |= 1ull << (c * 4 + 3);
      }
      s->masks[tid] = m;
    }
  }
  __syncthreads();

  const float* W = g_WT;
  conv64(s, W + 0*16384, W + 1*16384, conv1_br);
  mean_pool(s, 64, 0);

  conv64(s, W + 2*16384, W + 6*16384, convs_br);
  mean_pool(s, 64, 1);

  pool1(s, W + 10*16384, pool_lin_b, pool_att_w, pool_att_b[0],
        pool_le1_w, pool_le1_b[0], pool_le2_w, pool_le3_w, pool_le3_b[0]);

  conv_small<16>(s, W + 3*16384, W + 7*16384, convs_br + 128);
  mean_pool(s, 16, 2);

  conv_small<16>(s, W + 4*16384, W + 8*16384, convs_br + 256);
  mean_pool(s, 16, 3);

  pool2(s, W + 11*16384, pool_lin_b + 128, pool_att_w + 256, pool_att_b[1],
        pool_le1_w + 128, pool_le1_b[1], pool_le2_w + 128,
        pool_le3_w + 128, pool_le3_b[1]);

  conv_small<4>(s, W + 5*16384, W + 9*16384, convs_br + 384);
  mean_pool(s, 4, 4);
  __syncthreads();   // xsum complete before MLP head reads it

  // MLP head
  for (int d = w; d < 128; d += 8) {
    const float4* zr = reinterpret_cast<const float4*>(s->xsum);
    const float4* wr = reinterpret_cast<const float4*>(lin1_w + d * 640);
    float a = 0.f;
#pragma unroll
    for (int c = 0; c < 5; c++) {
      float4 zc = zr[lane + 32 * c];
      float4 wc = __ldg(wr + lane + 32 * c);
      a += zc.x*wc.x + zc.y*wc.y + zc.z*wc.z + zc.w*wc.w;
    }
    a = warp_red_sum(a);
    if (lane == 0) s->zz[d] = fmaxf(a + lin1_b[d], 0.f);
  }
  __syncthreads();
  for (int d = w; d < 10; d += 8) {
    float4 zc = reinterpret_cast<const float4*>(s->zz)[lane];
    float4 wc = __ldg(reinterpret_cast<const float4*>(lin2_w + d * 128) + lane);
    float a = warp_red_sum(zc.x*wc.x + zc.y*wc.y + zc.z*wc.z + zc.w*wc.w);
    if (lane == 0) s->yy[d] = a + lin2_b[d];
  }
  __syncthreads();
  if (tid == 0) {
    float mx = -1e30f;
    for (int c = 0; c < 10; c++) mx = fmaxf(mx, s->yy[c]);
    float sum = 0.f;
    for (int c = 0; c < 10; c++) sum += __expf(s->yy[c] - mx);
    s->lse = mx + __logf(sum);
  }
  __syncthreads();
  if (tid < 10) out[g * 10 + tid] = s->yy[tid] - s->lse;
}

// ---------------------------------------------------------------------------
// prologue: transpose the 12 [128x128] weight matrices into g_WT
// ---------------------------------------------------------------------------
__global__ void transpose_k(
    const float* __restrict__ conv1_wr, const float* __restrict__ conv1_wroot,
    const float* __restrict__ convs_wr, const float* __restrict__ convs_wroot,
    const float* __restrict__ pool_lin_w)
{
  __shared__ float t[32][33];
  int mat = blockIdx.y;
  int tile = blockIdx.x;
  int tx = tile & 3, ty = tile >> 2;
  const float* src =
      (mat == 0) ? conv1_wr :
      (mat == 1) ? conv1_wroot :
      (mat < 6)  ? convs_wr + (mat - 2) * 16384 :
      (mat < 10) ? convs_wroot + (mat - 6) * 16384 :
                   pool_lin_w + (mat - 10) * 16384;
#pragma unroll
  for (int r = threadIdx.y; r < 32; r += 8)
    t[r][threadIdx.x] = src[(ty * 32 + r) * 128 + tx * 32 + threadIdx.x];
  __syncthreads();
#pragma unroll
  for (int r = threadIdx.y; r < 32; r += 8)
    g_WT[mat * 16384 + (tx * 32 + r) * 128 + ty * 32 + threadIdx.x] = t[threadIdx.x][r];
}

// ---------------------------------------------------------------------------
// launch
// ---------------------------------------------------------------------------
extern "C" void kernel_launch(void* const* d_in, const int* in_sizes, int n_in,
                              void* d_out, int out_size)
{
  const float* x           = (const float*)d_in[0];
  const float* adj         = (const float*)d_in[1];
  const float* conv1_wr    = (const float*)d_in[2];
  const float* conv1_br    = (const float*)d_in[3];
  const float* conv1_wroot = (const float*)d_in[4];
  const float* convs_wr    = (const float*)d_in[5];
  const float* convs_br    = (const float*)d_in[6];
  const float* convs_wroot = (const float*)d_in[7];
  const float* pool_lin_w  = (const float*)d_in[8];
  const float* pool_lin_b  = (const float*)d_in[9];
  const float* pool_att_w  = (const float*)d_in[10];
  const float* pool_att_b  = (const float*)d_in[11];
  const float* pool_le1_w  = (const float*)d_in[12];
  const float* pool_le1_b  = (const float*)d_in[13];
  const float* pool_le2_w  = (const float*)d_in[14];
  const float* pool_le3_w  = (const float*)d_in[15];
  const float* pool_le3_b  = (const float*)d_in[16];
  const float* lin1_w      = (const float*)d_in[17];
  const float* lin1_b      = (const float*)d_in[18];
  const float* lin2_w      = (const float*)d_in[19];
  const float* lin2_b      = (const float*)d_in[20];
  float* out = (float*)d_out;

  transpose_k<<<dim3(16, 12), dim3(32, 8)>>>(
      conv1_wr, conv1_wroot, convs_wr, convs_wroot, pool_lin_w);

  cudaFuncSetAttribute(asap_kernel, cudaFuncAttributeMaxDynamicSharedMemorySize,
                       (int)sizeof(Smem));
  asap_kernel<<<G_TOT, THREADS, sizeof(Smem)>>>(
      x, adj, conv1_br, convs_br,
      pool_lin_b, pool_att_w, pool_att_b,
      pool_le1_w, pool_le1_b, pool_le2_w, pool_le3_w, pool_le3_b,
      lin1_w, lin1_b, lin2_w, lin2_b, out);
}